// round 8
// baseline (speedup 1.0000x reference)
#include <cuda_runtime.h>
#include <cuda_bf16.h>
#include <mma.h>
#include <cstdint>
#include <math.h>

using namespace nvcuda;

#define BB    128
#define SSQ   256
#define LLC   16
#define EMB   256
#define HID   512
#define NCLS  20
#define CEMB  64
#define CHID  128
#define NW    (BB*SSQ)        // 32768 words
#define DIM   384             // EMB + CHID
#define G3C   384             // 3*CHID
#define G3H   1536            // 3*HID
#define NBLK_W 128

// ---------------- scratch (__device__ globals, no allocation) ----------------
__device__ float g_cxw[(size_t)NW*LLC*G3C];       // char input projections
__device__ float g_charh[NW*CHID];                // char GRU final hidden (n = s*B+b)
__device__ float g_xw[(size_t)NW*G3H];            // word input projections
__device__ float g_hword[2*BB*HID];
__device__ float g_gruout[(size_t)NW*HID];
__device__ unsigned int g_barArrive;
__device__ unsigned int g_barPhase;
// split-bf16 weights (row-major [N][K])
__device__ __nv_bfloat16 g_BxwHi[G3H*DIM],  g_BxwLo[G3H*DIM];
__device__ __nv_bfloat16 g_BcxHi[G3C*CEMB], g_BcxLo[G3C*CEMB];
__device__ __nv_bfloat16 g_WhHi[G3C*CHID],  g_WhLo[G3C*CHID];   // char Wh
// split-bf16 gathered A matrices
__device__ __nv_bfloat16 g_AcH[(size_t)NW*LLC*CEMB], g_AcL[(size_t)NW*LLC*CEMB];
__device__ __nv_bfloat16 g_AxH[(size_t)NW*DIM],      g_AxL[(size_t)NW*DIM];

// ---------------- helpers ----------------
__device__ __forceinline__ void cvtf4(float4 v, uint2& hi, uint2& lo) {
    __nv_bfloat16 hx = __float2bfloat16(v.x), hy = __float2bfloat16(v.y);
    __nv_bfloat16 hz = __float2bfloat16(v.z), hw = __float2bfloat16(v.w);
    float lx = v.x - __bfloat162float(hx), ly = v.y - __bfloat162float(hy);
    float lz = v.z - __bfloat162float(hz), lw = v.w - __bfloat162float(hw);
    union { __nv_bfloat162 b; uint32_t u; } a0, a1, b0, b1;
    a0.b = __halves2bfloat162(hx, hy);  a1.b = __halves2bfloat162(hz, hw);
    b0.b = __halves2bfloat162(__float2bfloat16(lx), __float2bfloat16(ly));
    b1.b = __halves2bfloat162(__float2bfloat16(lz), __float2bfloat16(lw));
    hi = make_uint2(a0.u, a1.u);
    lo = make_uint2(b0.u, b1.u);
}

// ---------------- kernel P: weight prep ----------------
__global__ void k_prep(const float* __restrict__ cWh, const float* __restrict__ gWi,
                       const float* __restrict__ cWi) {
    int stride = gridDim.x * blockDim.x;
    int i0 = blockIdx.x * blockDim.x + threadIdx.x;
    for (int i = i0; i < G3C*CHID; i += stride) {
        float v = cWh[i];
        __nv_bfloat16 h = __float2bfloat16(v);
        g_WhHi[i] = h;
        g_WhLo[i] = __float2bfloat16(v - __bfloat162float(h));
    }
    for (int i = i0; i < G3H*DIM; i += stride) {
        float v = gWi[i];
        __nv_bfloat16 h = __float2bfloat16(v);
        g_BxwHi[i] = h;
        g_BxwLo[i] = __float2bfloat16(v - __bfloat162float(h));
    }
    for (int i = i0; i < G3C*CEMB; i += stride) {
        float v = cWi[i];
        __nv_bfloat16 h = __float2bfloat16(v);
        g_BcxHi[i] = h;
        g_BcxLo[i] = __float2bfloat16(v - __bfloat162float(h));
    }
}

// ---------------- gather A for char GEMM ----------------
__global__ __launch_bounds__(256)
void k_gatherA_c(const int* __restrict__ xc, const float* __restrict__ cembw) {
    const int r = blockIdx.x * 256 + threadIdx.x;
    const int c = xc[r];
    const float4* src = (const float4*)(cembw + (size_t)c * CEMB);
    uint2* dh = (uint2*)(g_AcH + (size_t)r * CEMB);
    uint2* dl = (uint2*)(g_AcL + (size_t)r * CEMB);
    #pragma unroll
    for (int i = 0; i < 16; i++) {
        uint2 hi, lo;
        cvtf4(src[i], hi, lo);
        dh[i] = hi; dl[i] = lo;
    }
}

// ---------------- gather A for word GEMM ----------------
__global__ __launch_bounds__(256)
void k_gatherA_x(const int* __restrict__ xtok, const float* __restrict__ embw) {
    const int warp = threadIdx.x >> 5, lane = threadIdx.x & 31;
    const int row = blockIdx.x * 8 + warp;
    const int tok = xtok[row];
    const int nidx = (row & 255) * 128 + (row >> 8);
    uint2* dh = (uint2*)(g_AxH + (size_t)row * DIM);
    uint2* dl = (uint2*)(g_AxL + (size_t)row * DIM);
    #pragma unroll
    for (int q = 0; q < 3; q++) {
        int k4 = q * 32 + lane;
        int k = k4 * 4;
        float4 v = (k < EMB)
            ? *(const float4*)(embw + (size_t)tok * EMB + k)
            : *(const float4*)(g_charh + (size_t)nidx * CHID + (k - EMB));
        uint2 hi, lo;
        cvtf4(v, hi, lo);
        dh[k4] = hi; dl[k4] = lo;
    }
}

// ---------------- wmma split-bf16 GEMM: C = A·B^T + bias ---------------------
#define GPAD 72
#define GSM_A  (128*GPAD)
#define GSM_B  (64*GPAD)
#define GEMM_SMEM ((2*GSM_A + 2*GSM_B) * 2)

__global__ __launch_bounds__(256)
void k_gemm(const __nv_bfloat16* __restrict__ Ah, const __nv_bfloat16* __restrict__ Al,
            const __nv_bfloat16* __restrict__ Bh, const __nv_bfloat16* __restrict__ Bl,
            const float* __restrict__ bias, float* __restrict__ C,
            int N, int K) {
    extern __shared__ char smraw[];
    __nv_bfloat16* sAh = (__nv_bfloat16*)smraw;
    __nv_bfloat16* sAl = sAh + GSM_A;
    __nv_bfloat16* sBh = sAl + GSM_A;
    __nv_bfloat16* sBl = sBh + GSM_B;
    float* sC = (float*)smraw;

    const int tid = threadIdx.x;
    const int warp = tid >> 5;
    const int wm = warp & 3, wn = warp >> 2;
    const int bm = blockIdx.y * 128, bn = blockIdx.x * 64;

    wmma::fragment<wmma::accumulator, 16, 16, 16, float> acc[2][2];
    #pragma unroll
    for (int i = 0; i < 2; i++)
        #pragma unroll
        for (int j = 0; j < 2; j++) wmma::fill_fragment(acc[i][j], 0.f);

    for (int k0 = 0; k0 < K; k0 += 64) {
        #pragma unroll
        for (int q = 0; q < 4; q++) {
            int j = tid * 4 + q;
            int r = j >> 3, c8 = j & 7;
            const uint4* sh = (const uint4*)(Ah + (size_t)(bm + r) * K + k0);
            const uint4* sl = (const uint4*)(Al + (size_t)(bm + r) * K + k0);
            *(uint4*)(sAh + r*GPAD + c8*8) = sh[c8];
            *(uint4*)(sAl + r*GPAD + c8*8) = sl[c8];
        }
        #pragma unroll
        for (int q = 0; q < 2; q++) {
            int j = tid * 2 + q;
            int r = j >> 3, c8 = j & 7;
            const uint4* sh = (const uint4*)(Bh + (size_t)(bn + r) * K + k0);
            const uint4* sl = (const uint4*)(Bl + (size_t)(bn + r) * K + k0);
            *(uint4*)(sBh + r*GPAD + c8*8) = sh[c8];
            *(uint4*)(sBl + r*GPAD + c8*8) = sl[c8];
        }
        __syncthreads();

        #pragma unroll
        for (int kk = 0; kk < 4; kk++) {
            wmma::fragment<wmma::matrix_a, 16, 16, 16, __nv_bfloat16, wmma::row_major> aH[2], aL[2];
            wmma::fragment<wmma::matrix_b, 16, 16, 16, __nv_bfloat16, wmma::col_major> bH[2], bL[2];
            #pragma unroll
            for (int mi = 0; mi < 2; mi++) {
                wmma::load_matrix_sync(aH[mi], sAh + (wm*32 + mi*16)*GPAD + kk*16, GPAD);
                wmma::load_matrix_sync(aL[mi], sAl + (wm*32 + mi*16)*GPAD + kk*16, GPAD);
            }
            #pragma unroll
            for (int ni = 0; ni < 2; ni++) {
                wmma::load_matrix_sync(bH[ni], sBh + (wn*32 + ni*16)*GPAD + kk*16, GPAD);
                wmma::load_matrix_sync(bL[ni], sBl + (wn*32 + ni*16)*GPAD + kk*16, GPAD);
            }
            #pragma unroll
            for (int mi = 0; mi < 2; mi++)
                #pragma unroll
                for (int ni = 0; ni < 2; ni++) {
                    wmma::mma_sync(acc[mi][ni], aH[mi], bH[ni], acc[mi][ni]);
                    wmma::mma_sync(acc[mi][ni], aH[mi], bL[ni], acc[mi][ni]);
                    wmma::mma_sync(acc[mi][ni], aL[mi], bH[ni], acc[mi][ni]);
                }
        }
        __syncthreads();
    }

    #pragma unroll
    for (int mi = 0; mi < 2; mi++)
        #pragma unroll
        for (int ni = 0; ni < 2; ni++)
            wmma::store_matrix_sync(sC + (wm*32 + mi*16)*68 + wn*32 + ni*16,
                                    acc[mi][ni], 68, wmma::mem_row_major);
    __syncthreads();
    #pragma unroll
    for (int q = 0; q < 8; q++) {
        int j = q * 256 + tid;
        int r = j >> 4, c4 = (j & 15) * 4;
        float4 v = *(float4*)(sC + r*68 + c4);
        float4 b = *(const float4*)(bias + bn + c4);
        v.x += b.x; v.y += b.y; v.z += b.z; v.w += b.w;
        *(float4*)(C + (size_t)(bm + r) * N + bn + c4) = v;
    }
}

// ---------------- kernel CR: char GRU recurrent (WMMA, resident operands) ----
// Block: M=32 words, 256 threads = 8 warps; warp wn owns n-range [wn*48, wn*48+48).
// Bh (Wh-hi) fragments hoisted to REGISTERS (t-invariant, 24 frags/warp).
// Bl (Wh-lo) staged in SMEM once. h hi/lo in smem. No global traffic in t-loop
// except streaming g_cxw reads in the gate update.
#define CR_M   32
#define CR_HS  136                      // h row stride (bf16)
#define CR_BLS 136                      // Bl row stride (bf16)
#define CR_PS  392                      // pre row stride (fp32)
#define CR_OFF_HLO  (CR_M*CR_HS*2)                  // 8704
#define CR_OFF_BL   (2*CR_M*CR_HS*2)                // 17408
#define CR_OFF_PRE  (CR_OFF_BL + G3C*CR_BLS*2)      // 121856
#define CR_OFF_BH   (CR_OFF_PRE + CR_M*CR_PS*4)     // 172032
#define CR_SMEM     (CR_OFF_BH + G3C*4)             // 173568

__global__ __launch_bounds__(256, 1)
void k_charrec(const float* __restrict__ cbh) {
    extern __shared__ char smraw[];
    __nv_bfloat16* hHi = (__nv_bfloat16*)smraw;
    __nv_bfloat16* hLo = (__nv_bfloat16*)(smraw + CR_OFF_HLO);
    __nv_bfloat16* sBl = (__nv_bfloat16*)(smraw + CR_OFF_BL);
    float* pre = (float*)(smraw + CR_OFF_PRE);
    float* sbh = (float*)(smraw + CR_OFF_BH);
    const int tid = threadIdx.x;
    const int wn = tid >> 5;
    const int n0 = wn * 48;
    const int w0 = blockIdx.x * CR_M;

    // stage: h=0, Bl->smem (padded stride), bias
    {
        uint32_t* hz = (uint32_t*)hHi;
        for (int i = tid; i < 2*CR_M*CR_HS/2; i += 256) hz[i] = 0u;
        for (int i = tid; i < G3C*16; i += 256) {
            int r = i >> 4, c = i & 15;
            *(uint4*)(sBl + r*CR_BLS + c*8) = *(const uint4*)(g_WhLo + (size_t)r*CHID + c*8);
        }
        if (tid < 128) {
            sbh[tid] = cbh[tid];
            sbh[128 + tid] = cbh[128 + tid];
            sbh[256 + tid] = cbh[256 + tid];
        }
    }

    // hoist Bh fragments (t-invariant)
    wmma::fragment<wmma::matrix_b, 16, 16, 16, __nv_bfloat16, wmma::col_major> bH[3][8];
    #pragma unroll
    for (int ni = 0; ni < 3; ni++)
        #pragma unroll
        for (int kk = 0; kk < 8; kk++)
            wmma::load_matrix_sync(bH[ni][kk],
                g_WhHi + (size_t)(n0 + ni*16)*CHID + kk*16, CHID);
    __syncthreads();

    const int ju = tid & 127;
    const int mb = tid >> 7;        // 0..1

    for (int t = 0; t < LLC; t++) {
        wmma::fragment<wmma::accumulator, 16, 16, 16, float> acc[2][3];
        #pragma unroll
        for (int mi = 0; mi < 2; mi++)
            #pragma unroll
            for (int ni = 0; ni < 3; ni++) wmma::fill_fragment(acc[mi][ni], 0.f);

        #pragma unroll
        for (int kk = 0; kk < 8; kk++) {
            wmma::fragment<wmma::matrix_a, 16, 16, 16, __nv_bfloat16, wmma::row_major> aH[2], aL[2];
            #pragma unroll
            for (int mi = 0; mi < 2; mi++) {
                wmma::load_matrix_sync(aH[mi], hHi + (mi*16)*CR_HS + kk*16, CR_HS);
                wmma::load_matrix_sync(aL[mi], hLo + (mi*16)*CR_HS + kk*16, CR_HS);
            }
            #pragma unroll
            for (int ni = 0; ni < 3; ni++) {
                wmma::fragment<wmma::matrix_b, 16, 16, 16, __nv_bfloat16, wmma::col_major> bL;
                wmma::load_matrix_sync(bL, sBl + (n0 + ni*16)*CR_BLS + kk*16, CR_BLS);
                #pragma unroll
                for (int mi = 0; mi < 2; mi++) {
                    wmma::mma_sync(acc[mi][ni], aH[mi], bH[ni][kk], acc[mi][ni]);
                    wmma::mma_sync(acc[mi][ni], aL[mi], bH[ni][kk], acc[mi][ni]);
                    wmma::mma_sync(acc[mi][ni], aH[mi], bL, acc[mi][ni]);
                }
            }
        }
        #pragma unroll
        for (int mi = 0; mi < 2; mi++)
            #pragma unroll
            for (int ni = 0; ni < 3; ni++)
                wmma::store_matrix_sync(pre + (mi*16)*CR_PS + n0 + ni*16,
                                        acc[mi][ni], CR_PS, wmma::mem_row_major);
        __syncthreads();

        // gate update: 256 threads over 32x128 (m, j) pairs
        #pragma unroll
        for (int q = 0; q < 16; q++) {
            int m = mb + q*2;
            float pR = pre[m*CR_PS + ju] + sbh[ju];
            float pZ = pre[m*CR_PS + CHID + ju] + sbh[CHID + ju];
            float pN = pre[m*CR_PS + 2*CHID + ju] + sbh[2*CHID + ju];
            size_t rr = ((size_t)(w0 + m)*LLC + t)*G3C;
            float xr = g_cxw[rr + ju];
            float xz = g_cxw[rr + CHID + ju];
            float xn = g_cxw[rr + 2*CHID + ju];
            float r  = 1.f / (1.f + expf(-(xr + pR)));
            float z  = 1.f / (1.f + expf(-(xz + pZ)));
            float nn = tanhf(xn + r*pN);
            float hp = __bfloat162float(hHi[m*CR_HS + ju]) + __bfloat162float(hLo[m*CR_HS + ju]);
            float hn = nn + z*(hp - nn);
            __nv_bfloat16 hh = __float2bfloat16(hn);
            hHi[m*CR_HS + ju] = hh;
            hLo[m*CR_HS + ju] = __float2bfloat16(hn - __bfloat162float(hh));
        }
        __syncthreads();
    }

    #pragma unroll
    for (int q = 0; q < 16; q++) {
        int m = mb + q*2;
        g_charh[(size_t)(w0 + m)*CHID + ju] =
            __bfloat162float(hHi[m*CR_HS + ju]) + __bfloat162float(hLo[m*CR_HS + ju]);
    }
}

// ---------------- persistent word GRU ----------------
__device__ __forceinline__ void grid_barrier() {
    __threadfence();
    __syncthreads();
    if (threadIdx.x == 0) {
        volatile unsigned int* vph = &g_barPhase;
        unsigned int ph = *vph;
        unsigned int a = atomicAdd(&g_barArrive, 1u);
        if (a == NBLK_W - 1u) {
            g_barArrive = 0u;
            __threadfence();
            *vph = ph + 1u;
        } else {
            while (*vph == ph) { __nanosleep(20); }
        }
        __threadfence();
    }
    __syncthreads();
}

__device__ __forceinline__ float dot4(float4 a, float4 b, float c) {
    c = fmaf(a.x, b.x, c); c = fmaf(a.y, b.y, c);
    c = fmaf(a.z, b.z, c); c = fmaf(a.w, b.w, c);
    return c;
}

#define WBB 32
#define WJB 16
#define WST 516

__global__ __launch_bounds__(128, 1)
void k_wordgru(const float* __restrict__ gWh, const float* __restrict__ gbh) {
    extern __shared__ float sm[];
    float* sW = sm;
    float* sH = sm + 48*WST;
    const int tid = threadIdx.x;
    const int bid = blockIdx.x;
    const int jc = bid & 31, bc = bid >> 5;
    const int j0 = jc * WJB, b0 = bc * WBB;
    const int jl = tid & 15;
    const int bq = tid >> 4;
    const int bl0 = bq * 4;

    for (int i = tid; i < 48*HID; i += 128) {
        int gl = i >> 9, k = i & 511;
        int gate = gl >> 4, jj = gl & 15;
        int g = gate*HID + j0 + jj;
        sW[gl*WST + k] = gWh[(size_t)g*HID + k];
    }
    const float bhR = gbh[j0 + jl];
    const float bhZ = gbh[HID + j0 + jl];
    const float bhN = gbh[2*HID + j0 + jl];
    {
        float4 z4 = make_float4(0.f,0.f,0.f,0.f);
        float4* h4 = (float4*)sH;
        for (int i = tid; i < WBB*HID/4; i += 128) h4[i] = z4;
    }
    __syncthreads();

    const float4* wR = (const float4*)(sW + (0*16 + jl)*WST);
    const float4* wZ = (const float4*)(sW + (16  + jl)*WST);
    const float4* wN = (const float4*)(sW + (32  + jl)*WST);
    const int j = j0 + jl;

    for (int s = 0; s < SSQ; s++) {
        float xr[4], xz[4], xn[4];
        #pragma unroll
        for (int q = 0; q < 4; q++) {
            size_t base = ((size_t)(b0 + bl0 + q)*SSQ + s) * G3H;
            xr[q] = g_xw[base + j];
            xz[q] = g_xw[base + HID + j];
            xn[q] = g_xw[base + 2*HID + j];
        }

        float aR[4], aZ[4], aNh[4];
        #pragma unroll
        for (int q = 0; q < 4; q++) { aR[q]=bhR; aZ[q]=bhZ; aNh[q]=bhN; }

        const float4* h0p = (const float4*)(sH + (bl0+0)*HID);
        const float4* h1p = (const float4*)(sH + (bl0+1)*HID);
        const float4* h2p = (const float4*)(sH + (bl0+2)*HID);
        const float4* h3p = (const float4*)(sH + (bl0+3)*HID);
        #pragma unroll 4
        for (int k4 = 0; k4 < HID/4; k4++) {
            float4 r4 = wR[k4], z4 = wZ[k4], n4 = wN[k4];
            float4 h0 = h0p[k4], h1 = h1p[k4], h2 = h2p[k4], h3 = h3p[k4];
            aR[0]=dot4(h0,r4,aR[0]); aZ[0]=dot4(h0,z4,aZ[0]); aNh[0]=dot4(h0,n4,aNh[0]);
            aR[1]=dot4(h1,r4,aR[1]); aZ[1]=dot4(h1,z4,aZ[1]); aNh[1]=dot4(h1,n4,aNh[1]);
            aR[2]=dot4(h2,r4,aR[2]); aZ[2]=dot4(h2,z4,aZ[2]); aNh[2]=dot4(h2,n4,aNh[2]);
            aR[3]=dot4(h3,r4,aR[3]); aZ[3]=dot4(h3,z4,aZ[3]); aNh[3]=dot4(h3,n4,aNh[3]);
        }

        float* hOut = g_hword + ((s + 1) & 1) * (BB*HID);
        #pragma unroll
        for (int q = 0; q < 4; q++) {
            int b = b0 + bl0 + q;
            float r  = 1.f / (1.f + expf(-(xr[q] + aR[q])));
            float z  = 1.f / (1.f + expf(-(xz[q] + aZ[q])));
            float nn = tanhf(xn[q] + r*aNh[q]);
            float hp = sH[(bl0+q)*HID + j];
            float hn = nn + z*(hp - nn);
            hOut[b*HID + j] = hn;
            g_gruout[((size_t)b*SSQ + s)*HID + j] = hn;
        }
        if (s == SSQ - 1) break;
        grid_barrier();
        const float4* hIn4 = (const float4*)(g_hword + ((s + 1) & 1) * (BB*HID) + b0*HID);
        float4* sH4 = (float4*)sH;
        for (int i = tid; i < WBB*HID/4; i += 128) sH4[i] = hIn4[i];
        __syncthreads();
    }
}

// ---------------- classifier ----------------
__global__ __launch_bounds__(256)
void k_cls(const float* __restrict__ clsW, const float* __restrict__ clsb,
           float* __restrict__ out) {
    const int warp = threadIdx.x >> 5, lane = threadIdx.x & 31;
    const int gw = blockIdx.x * 8 + warp;
    for (int row = gw; row < NW; row += gridDim.x * 8) {
        const float* hrow = g_gruout + (size_t)row * HID;
        float acc[NCLS];
        #pragma unroll
        for (int c = 0; c < NCLS; c++) acc[c] = 0.f;
        for (int k = lane; k < HID; k += 32) {
            float hv = hrow[k];
            #pragma unroll
            for (int c = 0; c < NCLS; c++)
                acc[c] = fmaf(hv, clsW[c*HID + k], acc[c]);
        }
        #pragma unroll
        for (int off = 16; off > 0; off >>= 1) {
            #pragma unroll
            for (int c = 0; c < NCLS; c++)
                acc[c] += __shfl_down_sync(0xffffffffu, acc[c], off);
        }
        if (lane == 0) {
            #pragma unroll
            for (int c = 0; c < NCLS; c++)
                out[(size_t)row*NCLS + c] = acc[c] + clsb[c];
        }
    }
}

// ---------------- launch ----------------
extern "C" void kernel_launch(void* const* d_in, const int* in_sizes, int n_in,
                              void* d_out, int out_size) {
    const int*   x     = (const int*)  d_in[0];
    const int*   xch   = (const int*)  d_in[1];
    const float* embw  = (const float*)d_in[2];
    const float* cembw = (const float*)d_in[3];
    const float* cWi   = (const float*)d_in[4];
    const float* cWh   = (const float*)d_in[5];
    const float* cbi   = (const float*)d_in[6];
    const float* cbh   = (const float*)d_in[7];
    const float* gWi   = (const float*)d_in[8];
    const float* gWh   = (const float*)d_in[9];
    const float* gbi   = (const float*)d_in[10];
    const float* gbh   = (const float*)d_in[11];
    const float* clsW  = (const float*)d_in[12];
    const float* clsb  = (const float*)d_in[13];
    float* out = (float*)d_out;

    void *aCh, *aCl, *aXh, *aXl, *bCh, *bCl, *bXh, *bXl;
    cudaGetSymbolAddress(&aCh, g_AcH);  cudaGetSymbolAddress(&aCl, g_AcL);
    cudaGetSymbolAddress(&aXh, g_AxH);  cudaGetSymbolAddress(&aXl, g_AxL);
    cudaGetSymbolAddress(&bCh, g_BcxHi); cudaGetSymbolAddress(&bCl, g_BcxLo);
    cudaGetSymbolAddress(&bXh, g_BxwHi); cudaGetSymbolAddress(&bXl, g_BxwLo);
    void *pcxw, *pxw;
    cudaGetSymbolAddress(&pcxw, g_cxw);
    cudaGetSymbolAddress(&pxw, g_xw);

    const int wsmem  = (48*WST + WBB*HID) * 4;
    cudaFuncSetAttribute(k_charrec, cudaFuncAttributeMaxDynamicSharedMemorySize, CR_SMEM);
    cudaFuncSetAttribute(k_wordgru, cudaFuncAttributeMaxDynamicSharedMemorySize, wsmem);
    cudaFuncSetAttribute(k_gemm,    cudaFuncAttributeMaxDynamicSharedMemorySize, GEMM_SMEM);

    k_prep<<<512, 256>>>(cWh, gWi, cWi);
    k_gatherA_c<<<NW*LLC/256, 256>>>(xch, cembw);
    dim3 gc(G3C/64, NW*LLC/128);   // (6, 4096)
    k_gemm<<<gc, 256, GEMM_SMEM>>>((const __nv_bfloat16*)aCh, (const __nv_bfloat16*)aCl,
                                   (const __nv_bfloat16*)bCh, (const __nv_bfloat16*)bCl,
                                   cbi, (float*)pcxw, G3C, CEMB);
    k_charrec<<<NW/CR_M, 256, CR_SMEM>>>(cbh);
    k_gatherA_x<<<NW/8, 256>>>(x, embw);
    dim3 gx(G3H/64, NW/128);       // (24, 256)
    k_gemm<<<gx, 256, GEMM_SMEM>>>((const __nv_bfloat16*)aXh, (const __nv_bfloat16*)aXl,
                                   (const __nv_bfloat16*)bXh, (const __nv_bfloat16*)bXl,
                                   gbi, (float*)pxw, G3H, DIM);
    k_wordgru<<<NBLK_W, 128, wsmem>>>(gWh, gbh);
    k_cls<<<512, 256>>>(clsW, clsb, out);
}

// round 9
// speedup vs baseline: 1.3385x; 1.3385x over previous
#include <cuda_runtime.h>
#include <cuda_bf16.h>
#include <mma.h>
#include <cstdint>
#include <math.h>

using namespace nvcuda;

#define BB    128
#define SSQ   256
#define LLC   16
#define EMB   256
#define HID   512
#define NCLS  20
#define CEMB  64
#define CHID  128
#define NW    (BB*SSQ)        // 32768 words
#define DIM   384             // EMB + CHID
#define G3C   384             // 3*CHID
#define G3H   1536            // 3*HID
#define NBLK_W 128

// ---------------- scratch (__device__ globals, no allocation) ----------------
__device__ float g_cxw[(size_t)NW*LLC*G3C];       // char input projections
__device__ float g_charh[NW*CHID];                // char GRU final hidden (n = s*B+b)
__device__ float g_xw[(size_t)NW*G3H];            // word input projections
__device__ float g_hword[2*BB*HID];
__device__ float g_gruout[(size_t)NW*HID];
__device__ unsigned int g_barArrive;
__device__ unsigned int g_barPhase;
// split-bf16 weights (row-major [N][K])
__device__ __nv_bfloat16 g_BxwHi[G3H*DIM],  g_BxwLo[G3H*DIM];
__device__ __nv_bfloat16 g_BcxHi[G3C*CEMB], g_BcxLo[G3C*CEMB];
__device__ __nv_bfloat16 g_WhHi[G3C*CHID],  g_WhLo[G3C*CHID];   // char Wh [384][128]
// split-bf16 gathered A matrices
__device__ __nv_bfloat16 g_AcH[(size_t)NW*LLC*CEMB], g_AcL[(size_t)NW*LLC*CEMB];
__device__ __nv_bfloat16 g_AxH[(size_t)NW*DIM],      g_AxL[(size_t)NW*DIM];

// ---------------- helpers ----------------
__device__ __forceinline__ void cvtf4(float4 v, uint2& hi, uint2& lo) {
    __nv_bfloat16 hx = __float2bfloat16(v.x), hy = __float2bfloat16(v.y);
    __nv_bfloat16 hz = __float2bfloat16(v.z), hw = __float2bfloat16(v.w);
    float lx = v.x - __bfloat162float(hx), ly = v.y - __bfloat162float(hy);
    float lz = v.z - __bfloat162float(hz), lw = v.w - __bfloat162float(hw);
    union { __nv_bfloat162 b; uint32_t u; } a0, a1, b0, b1;
    a0.b = __halves2bfloat162(hx, hy);  a1.b = __halves2bfloat162(hz, hw);
    b0.b = __halves2bfloat162(__float2bfloat16(lx), __float2bfloat16(ly));
    b1.b = __halves2bfloat162(__float2bfloat16(lz), __float2bfloat16(lw));
    hi = make_uint2(a0.u, a1.u);
    lo = make_uint2(b0.u, b1.u);
}

// ---------------- kernel P: weight prep ----------------
__global__ void k_prep(const float* __restrict__ cWh, const float* __restrict__ gWi,
                       const float* __restrict__ cWi) {
    int stride = gridDim.x * blockDim.x;
    int i0 = blockIdx.x * blockDim.x + threadIdx.x;
    for (int i = i0; i < G3C*CHID; i += stride) {
        float v = cWh[i];
        __nv_bfloat16 h = __float2bfloat16(v);
        g_WhHi[i] = h;
        g_WhLo[i] = __float2bfloat16(v - __bfloat162float(h));
    }
    for (int i = i0; i < G3H*DIM; i += stride) {
        float v = gWi[i];
        __nv_bfloat16 h = __float2bfloat16(v);
        g_BxwHi[i] = h;
        g_BxwLo[i] = __float2bfloat16(v - __bfloat162float(h));
    }
    for (int i = i0; i < G3C*CEMB; i += stride) {
        float v = cWi[i];
        __nv_bfloat16 h = __float2bfloat16(v);
        g_BcxHi[i] = h;
        g_BcxLo[i] = __float2bfloat16(v - __bfloat162float(h));
    }
}

// ---------------- gather A for char GEMM ----------------
__global__ __launch_bounds__(256)
void k_gatherA_c(const int* __restrict__ xc, const float* __restrict__ cembw) {
    const int r = blockIdx.x * 256 + threadIdx.x;
    const int c = xc[r];
    const float4* src = (const float4*)(cembw + (size_t)c * CEMB);
    uint2* dh = (uint2*)(g_AcH + (size_t)r * CEMB);
    uint2* dl = (uint2*)(g_AcL + (size_t)r * CEMB);
    #pragma unroll
    for (int i = 0; i < 16; i++) {
        uint2 hi, lo;
        cvtf4(src[i], hi, lo);
        dh[i] = hi; dl[i] = lo;
    }
}

// ---------------- gather A for word GEMM ----------------
__global__ __launch_bounds__(256)
void k_gatherA_x(const int* __restrict__ xtok, const float* __restrict__ embw) {
    const int warp = threadIdx.x >> 5, lane = threadIdx.x & 31;
    const int row = blockIdx.x * 8 + warp;
    const int tok = xtok[row];
    const int nidx = (row & 255) * 128 + (row >> 8);
    uint2* dh = (uint2*)(g_AxH + (size_t)row * DIM);
    uint2* dl = (uint2*)(g_AxL + (size_t)row * DIM);
    #pragma unroll
    for (int q = 0; q < 3; q++) {
        int k4 = q * 32 + lane;
        int k = k4 * 4;
        float4 v = (k < EMB)
            ? *(const float4*)(embw + (size_t)tok * EMB + k)
            : *(const float4*)(g_charh + (size_t)nidx * CHID + (k - EMB));
        uint2 hi, lo;
        cvtf4(v, hi, lo);
        dh[k4] = hi; dl[k4] = lo;
    }
}

// ---------------- wmma split-bf16 GEMM: C = A·B^T + bias ---------------------
#define GPAD 72
#define GSM_A  (128*GPAD)
#define GSM_B  (64*GPAD)
#define GEMM_SMEM ((2*GSM_A + 2*GSM_B) * 2)

__global__ __launch_bounds__(256)
void k_gemm(const __nv_bfloat16* __restrict__ Ah, const __nv_bfloat16* __restrict__ Al,
            const __nv_bfloat16* __restrict__ Bh, const __nv_bfloat16* __restrict__ Bl,
            const float* __restrict__ bias, float* __restrict__ C,
            int N, int K) {
    extern __shared__ char smraw[];
    __nv_bfloat16* sAh = (__nv_bfloat16*)smraw;
    __nv_bfloat16* sAl = sAh + GSM_A;
    __nv_bfloat16* sBh = sAl + GSM_A;
    __nv_bfloat16* sBl = sBh + GSM_B;
    float* sC = (float*)smraw;

    const int tid = threadIdx.x;
    const int warp = tid >> 5;
    const int wm = warp & 3, wn = warp >> 2;
    const int bm = blockIdx.y * 128, bn = blockIdx.x * 64;

    wmma::fragment<wmma::accumulator, 16, 16, 16, float> acc[2][2];
    #pragma unroll
    for (int i = 0; i < 2; i++)
        #pragma unroll
        for (int j = 0; j < 2; j++) wmma::fill_fragment(acc[i][j], 0.f);

    for (int k0 = 0; k0 < K; k0 += 64) {
        #pragma unroll
        for (int q = 0; q < 4; q++) {
            int j = tid * 4 + q;
            int r = j >> 3, c8 = j & 7;
            const uint4* sh = (const uint4*)(Ah + (size_t)(bm + r) * K + k0);
            const uint4* sl = (const uint4*)(Al + (size_t)(bm + r) * K + k0);
            *(uint4*)(sAh + r*GPAD + c8*8) = sh[c8];
            *(uint4*)(sAl + r*GPAD + c8*8) = sl[c8];
        }
        #pragma unroll
        for (int q = 0; q < 2; q++) {
            int j = tid * 2 + q;
            int r = j >> 3, c8 = j & 7;
            const uint4* sh = (const uint4*)(Bh + (size_t)(bn + r) * K + k0);
            const uint4* sl = (const uint4*)(Bl + (size_t)(bn + r) * K + k0);
            *(uint4*)(sBh + r*GPAD + c8*8) = sh[c8];
            *(uint4*)(sBl + r*GPAD + c8*8) = sl[c8];
        }
        __syncthreads();

        #pragma unroll
        for (int kk = 0; kk < 4; kk++) {
            wmma::fragment<wmma::matrix_a, 16, 16, 16, __nv_bfloat16, wmma::row_major> aH[2], aL[2];
            wmma::fragment<wmma::matrix_b, 16, 16, 16, __nv_bfloat16, wmma::col_major> bH[2], bL[2];
            #pragma unroll
            for (int mi = 0; mi < 2; mi++) {
                wmma::load_matrix_sync(aH[mi], sAh + (wm*32 + mi*16)*GPAD + kk*16, GPAD);
                wmma::load_matrix_sync(aL[mi], sAl + (wm*32 + mi*16)*GPAD + kk*16, GPAD);
            }
            #pragma unroll
            for (int ni = 0; ni < 2; ni++) {
                wmma::load_matrix_sync(bH[ni], sBh + (wn*32 + ni*16)*GPAD + kk*16, GPAD);
                wmma::load_matrix_sync(bL[ni], sBl + (wn*32 + ni*16)*GPAD + kk*16, GPAD);
            }
            #pragma unroll
            for (int mi = 0; mi < 2; mi++)
                #pragma unroll
                for (int ni = 0; ni < 2; ni++) {
                    wmma::mma_sync(acc[mi][ni], aH[mi], bH[ni], acc[mi][ni]);
                    wmma::mma_sync(acc[mi][ni], aH[mi], bL[ni], acc[mi][ni]);
                    wmma::mma_sync(acc[mi][ni], aL[mi], bH[ni], acc[mi][ni]);
                }
        }
        __syncthreads();
    }

    #pragma unroll
    for (int mi = 0; mi < 2; mi++)
        #pragma unroll
        for (int ni = 0; ni < 2; ni++)
            wmma::store_matrix_sync(sC + (wm*32 + mi*16)*68 + wn*32 + ni*16,
                                    acc[mi][ni], 68, wmma::mem_row_major);
    __syncthreads();
    #pragma unroll
    for (int q = 0; q < 8; q++) {
        int j = q * 256 + tid;
        int r = j >> 4, c4 = (j & 15) * 4;
        float4 v = *(float4*)(sC + r*68 + c4);
        float4 b = *(const float4*)(bias + bn + c4);
        v.x += b.x; v.y += b.y; v.z += b.z; v.w += b.w;
        *(float4*)(C + (size_t)(bm + r) * N + bn + c4) = v;
    }
}

// ---------------- kernel CR: char GRU recurrent (WMMA, smem-resident h) -----
// Block: 64 words, 256 threads = 8 warps (2m x 4n), warp tile 32x96.
// h hi/lo lives in SMEM for all 16 steps (words are block-independent).
// Wh hi/lo streamed from L2 via double-buffered smem k-chunks (same chunks
// every step -> L2-resident). acc in registers (12 frags). pre via smem.
#define CR_M    64
#define CR_HS   136                     // h row stride (bf16)
#define CR_BS   24                      // B chunk row stride (bf16)
#define CR_PS   392                     // pre row stride (fp32)
#define CR_OFF_AL   (CR_M*CR_HS*2)                     // 17408
#define CR_OFF_B    (2*CR_M*CR_HS*2)                   // 34816
#define CR_BBUF     (G3C*CR_BS*2)                      // 18432 per matrix
#define CR_OFF_PRE  (CR_OFF_B + 4*CR_BBUF)             // 108544
#define CR_OFF_BH   (CR_OFF_PRE + CR_M*CR_PS*4)        // 208896
#define CR_SMEM     (CR_OFF_BH + G3C*4)                // 210432

__global__ __launch_bounds__(256, 1)
void k_charrec(const float* __restrict__ cbh) {
    extern __shared__ char smraw[];
    __nv_bfloat16* sAh = (__nv_bfloat16*)smraw;                       // [64][136]
    __nv_bfloat16* sAl = (__nv_bfloat16*)(smraw + CR_OFF_AL);
    __nv_bfloat16* sB  = (__nv_bfloat16*)(smraw + CR_OFF_B);          // 2 bufs x (hi,lo)
    float* pre = (float*)(smraw + CR_OFF_PRE);                        // [64][392]
    float* sbh = (float*)(smraw + CR_OFF_BH);
    const int tid = threadIdx.x;
    const int warp = tid >> 5;
    const int wm = warp & 1, wn = warp >> 1;
    const int m0 = wm * 32, n0 = wn * 96;
    const int w0 = blockIdx.x * CR_M;

    // init: h = 0, bias
    {
        uint32_t* hz = (uint32_t*)sAh;
        for (int i = tid; i < 2*CR_M*CR_HS/2; i += 256) hz[i] = 0u;
        if (tid < 128) {
            sbh[tid] = cbh[tid];
            sbh[128 + tid] = cbh[128 + tid];
            sbh[256 + tid] = cbh[256 + tid];
        }
    }

    // B chunk staging lambda data: thread loads 3 uint4 per matrix per chunk
    const int jb0 = tid;              // j = jb0 + 256*q, q<3; row = j>>1, col8 = j&1
    __syncthreads();

    const int ju = tid & 127;
    const int mb = (tid >> 7) * 32;   // 0 or 32

    for (int t = 0; t < LLC; t++) {
        // preload chunk 0 into buffer 0
        {
            __nv_bfloat16* dbh = sB;                     // buf0 hi
            __nv_bfloat16* dbl = sB + CR_BBUF;           // buf0 lo
            #pragma unroll
            for (int q = 0; q < 3; q++) {
                int j = jb0 + 256*q;
                int r = j >> 1, c8 = (j & 1) * 8;
                *(uint4*)(dbh + r*CR_BS + c8) = *(const uint4*)(g_WhHi + (size_t)r*CHID + c8);
                *(uint4*)(dbl + r*CR_BS + c8) = *(const uint4*)(g_WhLo + (size_t)r*CHID + c8);
            }
        }
        __syncthreads();

        wmma::fragment<wmma::accumulator, 16, 16, 16, float> acc[2][6];
        #pragma unroll
        for (int mi = 0; mi < 2; mi++)
            #pragma unroll
            for (int ni = 0; ni < 6; ni++) wmma::fill_fragment(acc[mi][ni], 0.f);

        for (int kc = 0; kc < 8; kc++) {
            // prefetch next chunk (registers)
            uint4 pf[6];
            if (kc < 7) {
                int k0n = (kc + 1) * 16;
                #pragma unroll
                for (int q = 0; q < 3; q++) {
                    int j = jb0 + 256*q;
                    int r = j >> 1, c8 = (j & 1) * 8;
                    pf[q]   = *(const uint4*)(g_WhHi + (size_t)r*CHID + k0n + c8);
                    pf[q+3] = *(const uint4*)(g_WhLo + (size_t)r*CHID + k0n + c8);
                }
            }
            const __nv_bfloat16* bh = sB + (kc & 1) * 2 * CR_BBUF;
            const __nv_bfloat16* bl = bh + CR_BBUF;

            wmma::fragment<wmma::matrix_a, 16, 16, 16, __nv_bfloat16, wmma::row_major> aH[2], aL[2];
            #pragma unroll
            for (int mi = 0; mi < 2; mi++) {
                wmma::load_matrix_sync(aH[mi], sAh + (m0 + mi*16)*CR_HS + kc*16, CR_HS);
                wmma::load_matrix_sync(aL[mi], sAl + (m0 + mi*16)*CR_HS + kc*16, CR_HS);
            }
            #pragma unroll
            for (int ni = 0; ni < 6; ni++) {
                wmma::fragment<wmma::matrix_b, 16, 16, 16, __nv_bfloat16, wmma::col_major> bHf, bLf;
                wmma::load_matrix_sync(bHf, bh + (n0 + ni*16)*CR_BS, CR_BS);
                wmma::load_matrix_sync(bLf, bl + (n0 + ni*16)*CR_BS, CR_BS);
                #pragma unroll
                for (int mi = 0; mi < 2; mi++) {
                    wmma::mma_sync(acc[mi][ni], aH[mi], bHf, acc[mi][ni]);
                    wmma::mma_sync(acc[mi][ni], aL[mi], bHf, acc[mi][ni]);
                    wmma::mma_sync(acc[mi][ni], aH[mi], bLf, acc[mi][ni]);
                }
            }
            if (kc < 7) {
                __nv_bfloat16* dbh = sB + ((kc + 1) & 1) * 2 * CR_BBUF;
                __nv_bfloat16* dbl = dbh + CR_BBUF;
                #pragma unroll
                for (int q = 0; q < 3; q++) {
                    int j = jb0 + 256*q;
                    int r = j >> 1, c8 = (j & 1) * 8;
                    *(uint4*)(dbh + r*CR_BS + c8) = pf[q];
                    *(uint4*)(dbl + r*CR_BS + c8) = pf[q+3];
                }
            }
            __syncthreads();
        }

        #pragma unroll
        for (int mi = 0; mi < 2; mi++)
            #pragma unroll
            for (int ni = 0; ni < 6; ni++)
                wmma::store_matrix_sync(pre + (m0 + mi*16)*CR_PS + n0 + ni*16,
                                        acc[mi][ni], CR_PS, wmma::mem_row_major);
        __syncthreads();

        // gate update: thread (ju, mb) owns 32 m-rows at column ju
        #pragma unroll 4
        for (int q = 0; q < 32; q++) {
            int m = mb + q;
            float pR = pre[m*CR_PS + ju] + sbh[ju];
            float pZ = pre[m*CR_PS + CHID + ju] + sbh[CHID + ju];
            float pN = pre[m*CR_PS + 2*CHID + ju] + sbh[2*CHID + ju];
            size_t rr = ((size_t)(w0 + m)*LLC + t)*G3C;
            float xr = g_cxw[rr + ju];
            float xz = g_cxw[rr + CHID + ju];
            float xn = g_cxw[rr + 2*CHID + ju];
            float r  = 1.f / (1.f + expf(-(xr + pR)));
            float z  = 1.f / (1.f + expf(-(xz + pZ)));
            float nn = tanhf(xn + r*pN);
            float hp = __bfloat162float(sAh[m*CR_HS + ju]) + __bfloat162float(sAl[m*CR_HS + ju]);
            float hn = nn + z*(hp - nn);
            __nv_bfloat16 hh = __float2bfloat16(hn);
            sAh[m*CR_HS + ju] = hh;
            sAl[m*CR_HS + ju] = __float2bfloat16(hn - __bfloat162float(hh));
        }
        __syncthreads();
    }

    #pragma unroll 4
    for (int q = 0; q < 32; q++) {
        int m = mb + q;
        g_charh[(size_t)(w0 + m)*CHID + ju] =
            __bfloat162float(sAh[m*CR_HS + ju]) + __bfloat162float(sAl[m*CR_HS + ju]);
    }
}

// ---------------- persistent word GRU ----------------
__device__ __forceinline__ void grid_barrier() {
    __threadfence();
    __syncthreads();
    if (threadIdx.x == 0) {
        volatile unsigned int* vph = &g_barPhase;
        unsigned int ph = *vph;
        unsigned int a = atomicAdd(&g_barArrive, 1u);
        if (a == NBLK_W - 1u) {
            g_barArrive = 0u;
            __threadfence();
            *vph = ph + 1u;
        } else {
            while (*vph == ph) { __nanosleep(20); }
        }
        __threadfence();
    }
    __syncthreads();
}

__device__ __forceinline__ float dot4(float4 a, float4 b, float c) {
    c = fmaf(a.x, b.x, c); c = fmaf(a.y, b.y, c);
    c = fmaf(a.z, b.z, c); c = fmaf(a.w, b.w, c);
    return c;
}

#define WBB 32
#define WJB 16
#define WST 516

__global__ __launch_bounds__(128, 1)
void k_wordgru(const float* __restrict__ gWh, const float* __restrict__ gbh) {
    extern __shared__ float sm[];
    float* sW = sm;
    float* sH = sm + 48*WST;
    const int tid = threadIdx.x;
    const int bid = blockIdx.x;
    const int jc = bid & 31, bc = bid >> 5;
    const int j0 = jc * WJB, b0 = bc * WBB;
    const int jl = tid & 15;
    const int bq = tid >> 4;
    const int bl0 = bq * 4;

    for (int i = tid; i < 48*HID; i += 128) {
        int gl = i >> 9, k = i & 511;
        int gate = gl >> 4, jj = gl & 15;
        int g = gate*HID + j0 + jj;
        sW[gl*WST + k] = gWh[(size_t)g*HID + k];
    }
    const float bhR = gbh[j0 + jl];
    const float bhZ = gbh[HID + j0 + jl];
    const float bhN = gbh[2*HID + j0 + jl];
    {
        float4 z4 = make_float4(0.f,0.f,0.f,0.f);
        float4* h4 = (float4*)sH;
        for (int i = tid; i < WBB*HID/4; i += 128) h4[i] = z4;
    }
    __syncthreads();

    const float4* wR = (const float4*)(sW + (0*16 + jl)*WST);
    const float4* wZ = (const float4*)(sW + (16  + jl)*WST);
    const float4* wN = (const float4*)(sW + (32  + jl)*WST);
    const int j = j0 + jl;

    for (int s = 0; s < SSQ; s++) {
        float xr[4], xz[4], xn[4];
        #pragma unroll
        for (int q = 0; q < 4; q++) {
            size_t base = ((size_t)(b0 + bl0 + q)*SSQ + s) * G3H;
            xr[q] = g_xw[base + j];
            xz[q] = g_xw[base + HID + j];
            xn[q] = g_xw[base + 2*HID + j];
        }

        float aR[4], aZ[4], aNh[4];
        #pragma unroll
        for (int q = 0; q < 4; q++) { aR[q]=bhR; aZ[q]=bhZ; aNh[q]=bhN; }

        const float4* h0p = (const float4*)(sH + (bl0+0)*HID);
        const float4* h1p = (const float4*)(sH + (bl0+1)*HID);
        const float4* h2p = (const float4*)(sH + (bl0+2)*HID);
        const float4* h3p = (const float4*)(sH + (bl0+3)*HID);
        #pragma unroll 4
        for (int k4 = 0; k4 < HID/4; k4++) {
            float4 r4 = wR[k4], z4 = wZ[k4], n4 = wN[k4];
            float4 h0 = h0p[k4], h1 = h1p[k4], h2 = h2p[k4], h3 = h3p[k4];
            aR[0]=dot4(h0,r4,aR[0]); aZ[0]=dot4(h0,z4,aZ[0]); aNh[0]=dot4(h0,n4,aNh[0]);
            aR[1]=dot4(h1,r4,aR[1]); aZ[1]=dot4(h1,z4,aZ[1]); aNh[1]=dot4(h1,n4,aNh[1]);
            aR[2]=dot4(h2,r4,aR[2]); aZ[2]=dot4(h2,z4,aZ[2]); aNh[2]=dot4(h2,n4,aNh[2]);
            aR[3]=dot4(h3,r4,aR[3]); aZ[3]=dot4(h3,z4,aZ[3]); aNh[3]=dot4(h3,n4,aNh[3]);
        }

        float* hOut = g_hword + ((s + 1) & 1) * (BB*HID);
        #pragma unroll
        for (int q = 0; q < 4; q++) {
            int b = b0 + bl0 + q;
            float r  = 1.f / (1.f + expf(-(xr[q] + aR[q])));
            float z  = 1.f / (1.f + expf(-(xz[q] + aZ[q])));
            float nn = tanhf(xn[q] + r*aNh[q]);
            float hp = sH[(bl0+q)*HID + j];
            float hn = nn + z*(hp - nn);
            hOut[b*HID + j] = hn;
            g_gruout[((size_t)b*SSQ + s)*HID + j] = hn;
        }
        if (s == SSQ - 1) break;
        grid_barrier();
        const float4* hIn4 = (const float4*)(g_hword + ((s + 1) & 1) * (BB*HID) + b0*HID);
        float4* sH4 = (float4*)sH;
        for (int i = tid; i < WBB*HID/4; i += 128) sH4[i] = hIn4[i];
        __syncthreads();
    }
}

// ---------------- classifier ----------------
__global__ __launch_bounds__(256)
void k_cls(const float* __restrict__ clsW, const float* __restrict__ clsb,
           float* __restrict__ out) {
    const int warp = threadIdx.x >> 5, lane = threadIdx.x & 31;
    const int gw = blockIdx.x * 8 + warp;
    for (int row = gw; row < NW; row += gridDim.x * 8) {
        const float* hrow = g_gruout + (size_t)row * HID;
        float acc[NCLS];
        #pragma unroll
        for (int c = 0; c < NCLS; c++) acc[c] = 0.f;
        for (int k = lane; k < HID; k += 32) {
            float hv = hrow[k];
            #pragma unroll
            for (int c = 0; c < NCLS; c++)
                acc[c] = fmaf(hv, clsW[c*HID + k], acc[c]);
        }
        #pragma unroll
        for (int off = 16; off > 0; off >>= 1) {
            #pragma unroll
            for (int c = 0; c < NCLS; c++)
                acc[c] += __shfl_down_sync(0xffffffffu, acc[c], off);
        }
        if (lane == 0) {
            #pragma unroll
            for (int c = 0; c < NCLS; c++)
                out[(size_t)row*NCLS + c] = acc[c] + clsb[c];
        }
    }
}

// ---------------- launch ----------------
extern "C" void kernel_launch(void* const* d_in, const int* in_sizes, int n_in,
                              void* d_out, int out_size) {
    const int*   x     = (const int*)  d_in[0];
    const int*   xch   = (const int*)  d_in[1];
    const float* embw  = (const float*)d_in[2];
    const float* cembw = (const float*)d_in[3];
    const float* cWi   = (const float*)d_in[4];
    const float* cWh   = (const float*)d_in[5];
    const float* cbi   = (const float*)d_in[6];
    const float* cbh   = (const float*)d_in[7];
    const float* gWi   = (const float*)d_in[8];
    const float* gWh   = (const float*)d_in[9];
    const float* gbi   = (const float*)d_in[10];
    const float* gbh   = (const float*)d_in[11];
    const float* clsW  = (const float*)d_in[12];
    const float* clsb  = (const float*)d_in[13];
    float* out = (float*)d_out;

    void *aCh, *aCl, *aXh, *aXl, *bCh, *bCl, *bXh, *bXl;
    cudaGetSymbolAddress(&aCh, g_AcH);  cudaGetSymbolAddress(&aCl, g_AcL);
    cudaGetSymbolAddress(&aXh, g_AxH);  cudaGetSymbolAddress(&aXl, g_AxL);
    cudaGetSymbolAddress(&bCh, g_BcxHi); cudaGetSymbolAddress(&bCl, g_BcxLo);
    cudaGetSymbolAddress(&bXh, g_BxwHi); cudaGetSymbolAddress(&bXl, g_BxwLo);
    void *pcxw, *pxw;
    cudaGetSymbolAddress(&pcxw, g_cxw);
    cudaGetSymbolAddress(&pxw, g_xw);

    const int wsmem  = (48*WST + WBB*HID) * 4;
    cudaFuncSetAttribute(k_charrec, cudaFuncAttributeMaxDynamicSharedMemorySize, CR_SMEM);
    cudaFuncSetAttribute(k_wordgru, cudaFuncAttributeMaxDynamicSharedMemorySize, wsmem);
    cudaFuncSetAttribute(k_gemm,    cudaFuncAttributeMaxDynamicSharedMemorySize, GEMM_SMEM);

    k_prep<<<512, 256>>>(cWh, gWi, cWi);
    k_gatherA_c<<<NW*LLC/256, 256>>>(xch, cembw);
    dim3 gc(G3C/64, NW*LLC/128);   // (6, 4096)
    k_gemm<<<gc, 256, GEMM_SMEM>>>((const __nv_bfloat16*)aCh, (const __nv_bfloat16*)aCl,
                                   (const __nv_bfloat16*)bCh, (const __nv_bfloat16*)bCl,
                                   cbi, (float*)pcxw, G3C, CEMB);
    k_charrec<<<NW/CR_M, 256, CR_SMEM>>>(cbh);
    k_gatherA_x<<<NW/8, 256>>>(x, embw);
    dim3 gx(G3H/64, NW/128);       // (24, 256)
    k_gemm<<<gx, 256, GEMM_SMEM>>>((const __nv_bfloat16*)aXh, (const __nv_bfloat16*)aXl,
                                   (const __nv_bfloat16*)bXh, (const __nv_bfloat16*)bXl,
                                   gbi, (float*)pxw, G3H, DIM);
    k_wordgru<<<NBLK_W, 128, wsmem>>>(gWh, gbh);
    k_cls<<<512, 256>>>(clsW, clsb, out);
}

// round 10
// speedup vs baseline: 1.4632x; 1.0931x over previous
#include <cuda_runtime.h>
#include <cuda_bf16.h>
#include <mma.h>
#include <cstdint>
#include <math.h>

using namespace nvcuda;

#define BB    128
#define SSQ   256
#define LLC   16
#define EMB   256
#define HID   512
#define NCLS  20
#define CEMB  64
#define CHID  128
#define NW    (BB*SSQ)        // 32768 words
#define DIM   384             // EMB + CHID
#define G3C   384             // 3*CHID
#define G3H   1536            // 3*HID
#define NBLK_W 128

// ---------------- scratch (__device__ globals, no allocation) ----------------
__device__ float g_cxw[(size_t)NW*LLC*G3C];       // char input projections
__device__ float g_charh[NW*CHID];                // char GRU final hidden (n = s*B+b)
__device__ float g_xw[(size_t)NW*G3H];            // word input projections
__device__ float g_hword[2*BB*HID];
__device__ float g_gruout[(size_t)NW*HID];
__device__ unsigned int g_barA[4];
__device__ unsigned int g_barPh[4];
// split-bf16 weights (row-major [N][K])
__device__ __nv_bfloat16 g_BxwHi[G3H*DIM],  g_BxwLo[G3H*DIM];
__device__ __nv_bfloat16 g_BcxHi[G3C*CEMB], g_BcxLo[G3C*CEMB];
// char Wh packed for scalar recurrent: wrz[(i*128+j)*2] = (Wh[j][i], Wh[128+j][i])
__device__ float g_WrzP[CHID*CHID*2];
__device__ float g_WnP[CHID*CHID];
// split-bf16 gathered A matrices
__device__ __nv_bfloat16 g_AcH[(size_t)NW*LLC*CEMB], g_AcL[(size_t)NW*LLC*CEMB];
__device__ __nv_bfloat16 g_AxH[(size_t)NW*DIM],      g_AxL[(size_t)NW*DIM];

// ---------------- helpers ----------------
__device__ __forceinline__ void cvtf4(float4 v, uint2& hi, uint2& lo) {
    __nv_bfloat16 hx = __float2bfloat16(v.x), hy = __float2bfloat16(v.y);
    __nv_bfloat16 hz = __float2bfloat16(v.z), hw = __float2bfloat16(v.w);
    float lx = v.x - __bfloat162float(hx), ly = v.y - __bfloat162float(hy);
    float lz = v.z - __bfloat162float(hz), lw = v.w - __bfloat162float(hw);
    union { __nv_bfloat162 b; uint32_t u; } a0, a1, b0, b1;
    a0.b = __halves2bfloat162(hx, hy);  a1.b = __halves2bfloat162(hz, hw);
    b0.b = __halves2bfloat162(__float2bfloat16(lx), __float2bfloat16(ly));
    b1.b = __halves2bfloat162(__float2bfloat16(lz), __float2bfloat16(lw));
    hi = make_uint2(a0.u, a1.u);
    lo = make_uint2(b0.u, b1.u);
}

// ---------------- kernel P: weight prep ----------------
__global__ void k_prep(const float* __restrict__ cWh, const float* __restrict__ gWi,
                       const float* __restrict__ cWi) {
    int stride = gridDim.x * blockDim.x;
    int i0 = blockIdx.x * blockDim.x + threadIdx.x;
    for (int p = i0; p < CHID*CHID; p += stride) {
        int i = p >> 7, j = p & 127;
        g_WrzP[2*p]   = cWh[j*CHID + i];
        g_WrzP[2*p+1] = cWh[(CHID + j)*CHID + i];
        g_WnP[p]      = cWh[(2*CHID + j)*CHID + i];
    }
    for (int i = i0; i < G3H*DIM; i += stride) {
        float v = gWi[i];
        __nv_bfloat16 h = __float2bfloat16(v);
        g_BxwHi[i] = h;
        g_BxwLo[i] = __float2bfloat16(v - __bfloat162float(h));
    }
    for (int i = i0; i < G3C*CEMB; i += stride) {
        float v = cWi[i];
        __nv_bfloat16 h = __float2bfloat16(v);
        g_BcxHi[i] = h;
        g_BcxLo[i] = __float2bfloat16(v - __bfloat162float(h));
    }
}

// ---------------- gather A for char GEMM ----------------
__global__ __launch_bounds__(256)
void k_gatherA_c(const int* __restrict__ xc, const float* __restrict__ cembw) {
    const int r = blockIdx.x * 256 + threadIdx.x;
    const int c = xc[r];
    const float4* src = (const float4*)(cembw + (size_t)c * CEMB);
    uint2* dh = (uint2*)(g_AcH + (size_t)r * CEMB);
    uint2* dl = (uint2*)(g_AcL + (size_t)r * CEMB);
    #pragma unroll
    for (int i = 0; i < 16; i++) {
        uint2 hi, lo;
        cvtf4(src[i], hi, lo);
        dh[i] = hi; dl[i] = lo;
    }
}

// ---------------- gather A for word GEMM ----------------
__global__ __launch_bounds__(256)
void k_gatherA_x(const int* __restrict__ xtok, const float* __restrict__ embw) {
    const int warp = threadIdx.x >> 5, lane = threadIdx.x & 31;
    const int row = blockIdx.x * 8 + warp;
    const int tok = xtok[row];
    const int nidx = (row & 255) * 128 + (row >> 8);
    uint2* dh = (uint2*)(g_AxH + (size_t)row * DIM);
    uint2* dl = (uint2*)(g_AxL + (size_t)row * DIM);
    #pragma unroll
    for (int q = 0; q < 3; q++) {
        int k4 = q * 32 + lane;
        int k = k4 * 4;
        float4 v = (k < EMB)
            ? *(const float4*)(embw + (size_t)tok * EMB + k)
            : *(const float4*)(g_charh + (size_t)nidx * CHID + (k - EMB));
        uint2 hi, lo;
        cvtf4(v, hi, lo);
        dh[k4] = hi; dl[k4] = lo;
    }
}

// ---------------- wmma split-bf16 GEMM: C = A·B^T + bias ---------------------
#define GPAD 72
#define GSM_A  (128*GPAD)
#define GSM_B  (64*GPAD)
#define GEMM_SMEM ((2*GSM_A + 2*GSM_B) * 2)

__global__ __launch_bounds__(256)
void k_gemm(const __nv_bfloat16* __restrict__ Ah, const __nv_bfloat16* __restrict__ Al,
            const __nv_bfloat16* __restrict__ Bh, const __nv_bfloat16* __restrict__ Bl,
            const float* __restrict__ bias, float* __restrict__ C,
            int N, int K) {
    extern __shared__ char smraw[];
    __nv_bfloat16* sAh = (__nv_bfloat16*)smraw;
    __nv_bfloat16* sAl = sAh + GSM_A;
    __nv_bfloat16* sBh = sAl + GSM_A;
    __nv_bfloat16* sBl = sBh + GSM_B;
    float* sC = (float*)smraw;

    const int tid = threadIdx.x;
    const int warp = tid >> 5;
    const int wm = warp & 3, wn = warp >> 2;
    const int bm = blockIdx.y * 128, bn = blockIdx.x * 64;

    wmma::fragment<wmma::accumulator, 16, 16, 16, float> acc[2][2];
    #pragma unroll
    for (int i = 0; i < 2; i++)
        #pragma unroll
        for (int j = 0; j < 2; j++) wmma::fill_fragment(acc[i][j], 0.f);

    for (int k0 = 0; k0 < K; k0 += 64) {
        #pragma unroll
        for (int q = 0; q < 4; q++) {
            int j = tid * 4 + q;
            int r = j >> 3, c8 = j & 7;
            const uint4* sh = (const uint4*)(Ah + (size_t)(bm + r) * K + k0);
            const uint4* sl = (const uint4*)(Al + (size_t)(bm + r) * K + k0);
            *(uint4*)(sAh + r*GPAD + c8*8) = sh[c8];
            *(uint4*)(sAl + r*GPAD + c8*8) = sl[c8];
        }
        #pragma unroll
        for (int q = 0; q < 2; q++) {
            int j = tid * 2 + q;
            int r = j >> 3, c8 = j & 7;
            const uint4* sh = (const uint4*)(Bh + (size_t)(bn + r) * K + k0);
            const uint4* sl = (const uint4*)(Bl + (size_t)(bn + r) * K + k0);
            *(uint4*)(sBh + r*GPAD + c8*8) = sh[c8];
            *(uint4*)(sBl + r*GPAD + c8*8) = sl[c8];
        }
        __syncthreads();

        #pragma unroll
        for (int kk = 0; kk < 4; kk++) {
            wmma::fragment<wmma::matrix_a, 16, 16, 16, __nv_bfloat16, wmma::row_major> aH[2], aL[2];
            wmma::fragment<wmma::matrix_b, 16, 16, 16, __nv_bfloat16, wmma::col_major> bH[2], bL[2];
            #pragma unroll
            for (int mi = 0; mi < 2; mi++) {
                wmma::load_matrix_sync(aH[mi], sAh + (wm*32 + mi*16)*GPAD + kk*16, GPAD);
                wmma::load_matrix_sync(aL[mi], sAl + (wm*32 + mi*16)*GPAD + kk*16, GPAD);
            }
            #pragma unroll
            for (int ni = 0; ni < 2; ni++) {
                wmma::load_matrix_sync(bH[ni], sBh + (wn*32 + ni*16)*GPAD + kk*16, GPAD);
                wmma::load_matrix_sync(bL[ni], sBl + (wn*32 + ni*16)*GPAD + kk*16, GPAD);
            }
            #pragma unroll
            for (int mi = 0; mi < 2; mi++)
                #pragma unroll
                for (int ni = 0; ni < 2; ni++) {
                    wmma::mma_sync(acc[mi][ni], aH[mi], bH[ni], acc[mi][ni]);
                    wmma::mma_sync(acc[mi][ni], aH[mi], bL[ni], acc[mi][ni]);
                    wmma::mma_sync(acc[mi][ni], aL[mi], bH[ni], acc[mi][ni]);
                }
        }
        __syncthreads();
    }

    #pragma unroll
    for (int mi = 0; mi < 2; mi++)
        #pragma unroll
        for (int ni = 0; ni < 2; ni++)
            wmma::store_matrix_sync(sC + (wm*32 + mi*16)*68 + wn*32 + ni*16,
                                    acc[mi][ni], 68, wmma::mem_row_major);
    __syncthreads();
    #pragma unroll
    for (int q = 0; q < 8; q++) {
        int j = q * 256 + tid;
        int r = j >> 4, c4 = (j & 15) * 4;
        float4 v = *(float4*)(sC + r*68 + c4);
        float4 b = *(const float4*)(bias + bn + c4);
        v.x += b.x; v.y += b.y; v.z += b.z; v.w += b.w;
        *(float4*)(C + (size_t)(bm + r) * N + bn + c4) = v;
    }
}

// ---------------- kernel CR: char GRU recurrent (scalar v2) ------------------
// 512 threads, 32 words/block. j = tid&127 (hidden col), grp = tid>>7 (8 words).
// Weights packed (wr,wz)+wn: 2 LDS per i. h transposed [hidden][word] so the
// 8 h values per i are 2 broadcast LDS.128. xw prefetched before dot loop.
#define CR_WPB 32
#define CR_HTS 40                                  // sHT row stride (floats)
#define CR_OFF_WN   (CHID*CHID*2*4)                // 131072
#define CR_OFF_HT   (CR_OFF_WN + CHID*CHID*4)      // 196608
#define CR_OFF_BH   (CR_OFF_HT + CHID*CR_HTS*4)    // 217088
#define CR_SMEM     (CR_OFF_BH + G3C*4)            // 218624

__global__ __launch_bounds__(512, 1)
void k_charrec(const float* __restrict__ cbh) {
    extern __shared__ char smraw[];
    float* sWrz = (float*)smraw;                   // [128][128][2]
    float* sWn  = (float*)(smraw + CR_OFF_WN);     // [128][128]
    float* sHT  = (float*)(smraw + CR_OFF_HT);     // [128][40]  h[w][i] at sHT[i*40+w]
    float* sbh  = (float*)(smraw + CR_OFF_BH);     // [384]
    const int tid = threadIdx.x;
    const int j = tid & 127;
    const int grp = tid >> 7;                      // 0..3
    const int w0 = blockIdx.x * CR_WPB;

    {
        float4* d = (float4*)sWrz;
        const float4* s = (const float4*)g_WrzP;
        for (int i = tid; i < CHID*CHID*2/4; i += 512) d[i] = s[i];
        float4* d2 = (float4*)sWn;
        const float4* s2 = (const float4*)g_WnP;
        for (int i = tid; i < CHID*CHID/4; i += 512) d2[i] = s2[i];
        for (int i = tid; i < CHID*CR_HTS; i += 512) sHT[i] = 0.f;
        if (tid < G3C) sbh[tid] = cbh[tid];
    }
    __syncthreads();
    const float bR = sbh[j], bZ = sbh[CHID + j], bN = sbh[2*CHID + j];

    for (int t = 0; t < LLC; t++) {
        // prefetch xw for this step (independent of h)
        float xr[8], xz[8], xn[8];
        #pragma unroll
        for (int q = 0; q < 8; q++) {
            size_t rr = ((size_t)(w0 + grp*8 + q)*LLC + t)*G3C;
            xr[q] = g_cxw[rr + j];
            xz[q] = g_cxw[rr + CHID + j];
            xn[q] = g_cxw[rr + 2*CHID + j];
        }

        float aR[8], aZ[8], aN[8];
        #pragma unroll
        for (int q = 0; q < 8; q++) { aR[q]=bR; aZ[q]=bZ; aN[q]=bN; }

        #pragma unroll 4
        for (int i = 0; i < CHID; i++) {
            const float2 wrz = *(const float2*)(sWrz + (i*CHID + j)*2);
            const float wn = sWn[i*CHID + j];
            const float4 h0 = *(const float4*)(sHT + i*CR_HTS + grp*8);
            const float4 h1 = *(const float4*)(sHT + i*CR_HTS + grp*8 + 4);
            const float hv[8] = {h0.x,h0.y,h0.z,h0.w,h1.x,h1.y,h1.z,h1.w};
            #pragma unroll
            for (int q = 0; q < 8; q++) {
                aR[q] = fmaf(hv[q], wrz.x, aR[q]);
                aZ[q] = fmaf(hv[q], wrz.y, aZ[q]);
                aN[q] = fmaf(hv[q], wn,    aN[q]);
            }
        }
        __syncthreads();
        #pragma unroll
        for (int q = 0; q < 8; q++) {
            int w = grp*8 + q;
            float r  = 1.f / (1.f + expf(-(xr[q] + aR[q])));
            float z  = 1.f / (1.f + expf(-(xz[q] + aZ[q])));
            float nn = tanhf(xn[q] + r*aN[q]);
            float hp = sHT[j*CR_HTS + w];
            sHT[j*CR_HTS + w] = nn + z*(hp - nn);
        }
        __syncthreads();
    }

    #pragma unroll
    for (int q = 0; q < 8; q++) {
        int w = grp*8 + q;
        g_charh[(size_t)(w0 + w)*CHID + j] = sHT[j*CR_HTS + w];
    }
}

// ---------------- persistent word GRU (per-group barriers) -------------------
__device__ __forceinline__ void group_barrier(int g) {
    __threadfence();
    __syncthreads();
    if (threadIdx.x == 0) {
        volatile unsigned int* vph = &g_barPh[g];
        unsigned int ph = *vph;
        unsigned int a = atomicAdd(&g_barA[g], 1u);
        if (a == 31u) {
            g_barA[g] = 0u;
            __threadfence();
            *vph = ph + 1u;
        } else {
            while (*vph == ph) { __nanosleep(20); }
        }
        __threadfence();
    }
    __syncthreads();
}

__device__ __forceinline__ float dot4(float4 a, float4 b, float c) {
    c = fmaf(a.x, b.x, c); c = fmaf(a.y, b.y, c);
    c = fmaf(a.z, b.z, c); c = fmaf(a.w, b.w, c);
    return c;
}

#define WBB 32
#define WJB 16
#define WST 516

__global__ __launch_bounds__(128, 1)
void k_wordgru(const float* __restrict__ gWh, const float* __restrict__ gbh) {
    extern __shared__ float sm[];
    float* sW = sm;
    float* sH = sm + 48*WST;
    const int tid = threadIdx.x;
    const int bid = blockIdx.x;
    const int jc = bid & 31, bc = bid >> 5;     // bc = dependency group
    const int j0 = jc * WJB, b0 = bc * WBB;
    const int jl = tid & 15;
    const int bq = tid >> 4;
    const int bl0 = bq * 4;

    for (int i = tid; i < 48*HID; i += 128) {
        int gl = i >> 9, k = i & 511;
        int gate = gl >> 4, jj = gl & 15;
        int g = gate*HID + j0 + jj;
        sW[gl*WST + k] = gWh[(size_t)g*HID + k];
    }
    const float bhR = gbh[j0 + jl];
    const float bhZ = gbh[HID + j0 + jl];
    const float bhN = gbh[2*HID + j0 + jl];
    {
        float4 z4 = make_float4(0.f,0.f,0.f,0.f);
        float4* h4 = (float4*)sH;
        for (int i = tid; i < WBB*HID/4; i += 128) h4[i] = z4;
    }
    __syncthreads();

    const float4* wR = (const float4*)(sW + (0*16 + jl)*WST);
    const float4* wZ = (const float4*)(sW + (16  + jl)*WST);
    const float4* wN = (const float4*)(sW + (32  + jl)*WST);
    const int j = j0 + jl;

    for (int s = 0; s < SSQ; s++) {
        float xr[4], xz[4], xn[4];
        #pragma unroll
        for (int q = 0; q < 4; q++) {
            size_t base = ((size_t)(b0 + bl0 + q)*SSQ + s) * G3H;
            xr[q] = g_xw[base + j];
            xz[q] = g_xw[base + HID + j];
            xn[q] = g_xw[base + 2*HID + j];
        }

        float aR[4], aZ[4], aNh[4];
        #pragma unroll
        for (int q = 0; q < 4; q++) { aR[q]=bhR; aZ[q]=bhZ; aNh[q]=bhN; }

        const float4* h0p = (const float4*)(sH + (bl0+0)*HID);
        const float4* h1p = (const float4*)(sH + (bl0+1)*HID);
        const float4* h2p = (const float4*)(sH + (bl0+2)*HID);
        const float4* h3p = (const float4*)(sH + (bl0+3)*HID);
        #pragma unroll 4
        for (int k4 = 0; k4 < HID/4; k4++) {
            float4 r4 = wR[k4], z4 = wZ[k4], n4 = wN[k4];
            float4 h0 = h0p[k4], h1 = h1p[k4], h2 = h2p[k4], h3 = h3p[k4];
            aR[0]=dot4(h0,r4,aR[0]); aZ[0]=dot4(h0,z4,aZ[0]); aNh[0]=dot4(h0,n4,aNh[0]);
            aR[1]=dot4(h1,r4,aR[1]); aZ[1]=dot4(h1,z4,aZ[1]); aNh[1]=dot4(h1,n4,aNh[1]);
            aR[2]=dot4(h2,r4,aR[2]); aZ[2]=dot4(h2,z4,aZ[2]); aNh[2]=dot4(h2,n4,aNh[2]);
            aR[3]=dot4(h3,r4,aR[3]); aZ[3]=dot4(h3,z4,aZ[3]); aNh[3]=dot4(h3,n4,aNh[3]);
        }

        float* hOut = g_hword + ((s + 1) & 1) * (BB*HID);
        #pragma unroll
        for (int q = 0; q < 4; q++) {
            int b = b0 + bl0 + q;
            float r  = 1.f / (1.f + expf(-(xr[q] + aR[q])));
            float z  = 1.f / (1.f + expf(-(xz[q] + aZ[q])));
            float nn = tanhf(xn[q] + r*aNh[q]);
            float hp = sH[(bl0+q)*HID + j];
            float hn = nn + z*(hp - nn);
            hOut[b*HID + j] = hn;
            g_gruout[((size_t)b*SSQ + s)*HID + j] = hn;
        }
        if (s == SSQ - 1) break;
        group_barrier(bc);
        const float4* hIn4 = (const float4*)(g_hword + ((s + 1) & 1) * (BB*HID) + b0*HID);
        float4* sH4 = (float4*)sH;
        for (int i = tid; i < WBB*HID/4; i += 128) sH4[i] = hIn4[i];
        __syncthreads();
    }
}

// ---------------- classifier ----------------
__global__ __launch_bounds__(256)
void k_cls(const float* __restrict__ clsW, const float* __restrict__ clsb,
           float* __restrict__ out) {
    const int warp = threadIdx.x >> 5, lane = threadIdx.x & 31;
    const int gw = blockIdx.x * 8 + warp;
    for (int row = gw; row < NW; row += gridDim.x * 8) {
        const float* hrow = g_gruout + (size_t)row * HID;
        float acc[NCLS];
        #pragma unroll
        for (int c = 0; c < NCLS; c++) acc[c] = 0.f;
        for (int k = lane; k < HID; k += 32) {
            float hv = hrow[k];
            #pragma unroll
            for (int c = 0; c < NCLS; c++)
                acc[c] = fmaf(hv, clsW[c*HID + k], acc[c]);
        }
        #pragma unroll
        for (int off = 16; off > 0; off >>= 1) {
            #pragma unroll
            for (int c = 0; c < NCLS; c++)
                acc[c] += __shfl_down_sync(0xffffffffu, acc[c], off);
        }
        if (lane == 0) {
            #pragma unroll
            for (int c = 0; c < NCLS; c++)
                out[(size_t)row*NCLS + c] = acc[c] + clsb[c];
        }
    }
}

// ---------------- launch ----------------
extern "C" void kernel_launch(void* const* d_in, const int* in_sizes, int n_in,
                              void* d_out, int out_size) {
    const int*   x     = (const int*)  d_in[0];
    const int*   xch   = (const int*)  d_in[1];
    const float* embw  = (const float*)d_in[2];
    const float* cembw = (const float*)d_in[3];
    const float* cWi   = (const float*)d_in[4];
    const float* cWh   = (const float*)d_in[5];
    const float* cbi   = (const float*)d_in[6];
    const float* cbh   = (const float*)d_in[7];
    const float* gWi   = (const float*)d_in[8];
    const float* gWh   = (const float*)d_in[9];
    const float* gbi   = (const float*)d_in[10];
    const float* gbh   = (const float*)d_in[11];
    const float* clsW  = (const float*)d_in[12];
    const float* clsb  = (const float*)d_in[13];
    float* out = (float*)d_out;

    void *aCh, *aCl, *aXh, *aXl, *bCh, *bCl, *bXh, *bXl;
    cudaGetSymbolAddress(&aCh, g_AcH);  cudaGetSymbolAddress(&aCl, g_AcL);
    cudaGetSymbolAddress(&aXh, g_AxH);  cudaGetSymbolAddress(&aXl, g_AxL);
    cudaGetSymbolAddress(&bCh, g_BcxHi); cudaGetSymbolAddress(&bCl, g_BcxLo);
    cudaGetSymbolAddress(&bXh, g_BxwHi); cudaGetSymbolAddress(&bXl, g_BxwLo);
    void *pcxw, *pxw;
    cudaGetSymbolAddress(&pcxw, g_cxw);
    cudaGetSymbolAddress(&pxw, g_xw);

    const int wsmem  = (48*WST + WBB*HID) * 4;
    cudaFuncSetAttribute(k_charrec, cudaFuncAttributeMaxDynamicSharedMemorySize, CR_SMEM);
    cudaFuncSetAttribute(k_wordgru, cudaFuncAttributeMaxDynamicSharedMemorySize, wsmem);
    cudaFuncSetAttribute(k_gemm,    cudaFuncAttributeMaxDynamicSharedMemorySize, GEMM_SMEM);

    k_prep<<<512, 256>>>(cWh, gWi, cWi);
    k_gatherA_c<<<NW*LLC/256, 256>>>(xch, cembw);
    dim3 gc(G3C/64, NW*LLC/128);   // (6, 4096)
    k_gemm<<<gc, 256, GEMM_SMEM>>>((const __nv_bfloat16*)aCh, (const __nv_bfloat16*)aCl,
                                   (const __nv_bfloat16*)bCh, (const __nv_bfloat16*)bCl,
                                   cbi, (float*)pcxw, G3C, CEMB);
    k_charrec<<<NW/CR_WPB, 512, CR_SMEM>>>(cbh);
    k_gatherA_x<<<NW/8, 256>>>(x, embw);
    dim3 gx(G3H/64, NW/128);       // (24, 256)
    k_gemm<<<gx, 256, GEMM_SMEM>>>((const __nv_bfloat16*)aXh, (const __nv_bfloat16*)aXl,
                                   (const __nv_bfloat16*)bXh, (const __nv_bfloat16*)bXl,
                                   gbi, (float*)pxw, G3H, DIM);
    k_wordgru<<<NBLK_W, 128, wsmem>>>(gWh, gbh);
    k_cls<<<512, 256>>>(clsW, clsb, out);
}

// round 11
// speedup vs baseline: 1.6602x; 1.1346x over previous
#include <cuda_runtime.h>
#include <cuda_bf16.h>
#include <cuda_fp16.h>
#include <mma.h>
#include <cstdint>
#include <math.h>

using namespace nvcuda;

#define BB    128
#define SSQ   256
#define LLC   16
#define EMB   256
#define HID   512
#define NCLS  20
#define CEMB  64
#define CHID  128
#define NW    (BB*SSQ)        // 32768 words
#define DIM   384             // EMB + CHID
#define G3C   384             // 3*CHID
#define G3H   1536            // 3*HID
#define NBLK_W 128

// ---------------- scratch (__device__ globals, no allocation) ----------------
__device__ float g_cxw[(size_t)NW*LLC*G3C];       // char input projections
__device__ float g_charh[NW*CHID];                // char GRU final hidden (n = s*B+b)
__device__ float g_xw[(size_t)NW*G3H];            // word input projections
__device__ float g_hword[2*BB*HID];
__device__ float g_gruout[(size_t)NW*HID];
__device__ unsigned int g_barA[4];
__device__ unsigned int g_barPh[4];
// split-bf16 weights (row-major [N][K])
__device__ __nv_bfloat16 g_BxwHi[G3H*DIM],  g_BxwLo[G3H*DIM];
__device__ __nv_bfloat16 g_BcxHi[G3C*CEMB], g_BcxLo[G3C*CEMB];
// char Wh in fp16, padded [384][136] (k contiguous; pad cols zero)
#define WHS 136
__device__ __half g_Wh16[G3C*WHS];
// split-bf16 gathered A matrices
__device__ __nv_bfloat16 g_AcH[(size_t)NW*LLC*CEMB], g_AcL[(size_t)NW*LLC*CEMB];
__device__ __nv_bfloat16 g_AxH[(size_t)NW*DIM],      g_AxL[(size_t)NW*DIM];

// ---------------- helpers ----------------
__device__ __forceinline__ void cvtf4(float4 v, uint2& hi, uint2& lo) {
    __nv_bfloat16 hx = __float2bfloat16(v.x), hy = __float2bfloat16(v.y);
    __nv_bfloat16 hz = __float2bfloat16(v.z), hw = __float2bfloat16(v.w);
    float lx = v.x - __bfloat162float(hx), ly = v.y - __bfloat162float(hy);
    float lz = v.z - __bfloat162float(hz), lw = v.w - __bfloat162float(hw);
    union { __nv_bfloat162 b; uint32_t u; } a0, a1, b0, b1;
    a0.b = __halves2bfloat162(hx, hy);  a1.b = __halves2bfloat162(hz, hw);
    b0.b = __halves2bfloat162(__float2bfloat16(lx), __float2bfloat16(ly));
    b1.b = __halves2bfloat162(__float2bfloat16(lz), __float2bfloat16(lw));
    hi = make_uint2(a0.u, a1.u);
    lo = make_uint2(b0.u, b1.u);
}

// ---------------- kernel P: weight prep ----------------
__global__ void k_prep(const float* __restrict__ cWh, const float* __restrict__ gWi,
                       const float* __restrict__ cWi) {
    int stride = gridDim.x * blockDim.x;
    int i0 = blockIdx.x * blockDim.x + threadIdx.x;
    for (int i = i0; i < G3C*WHS; i += stride) {
        int n = i / WHS, k = i % WHS;
        g_Wh16[i] = (k < CHID) ? __float2half(cWh[n*CHID + k]) : __float2half(0.f);
    }
    for (int i = i0; i < G3H*DIM; i += stride) {
        float v = gWi[i];
        __nv_bfloat16 h = __float2bfloat16(v);
        g_BxwHi[i] = h;
        g_BxwLo[i] = __float2bfloat16(v - __bfloat162float(h));
    }
    for (int i = i0; i < G3C*CEMB; i += stride) {
        float v = cWi[i];
        __nv_bfloat16 h = __float2bfloat16(v);
        g_BcxHi[i] = h;
        g_BcxLo[i] = __float2bfloat16(v - __bfloat162float(h));
    }
}

// ---------------- gather A for char GEMM ----------------
__global__ __launch_bounds__(256)
void k_gatherA_c(const int* __restrict__ xc, const float* __restrict__ cembw) {
    const int r = blockIdx.x * 256 + threadIdx.x;
    const int c = xc[r];
    const float4* src = (const float4*)(cembw + (size_t)c * CEMB);
    uint2* dh = (uint2*)(g_AcH + (size_t)r * CEMB);
    uint2* dl = (uint2*)(g_AcL + (size_t)r * CEMB);
    #pragma unroll
    for (int i = 0; i < 16; i++) {
        uint2 hi, lo;
        cvtf4(src[i], hi, lo);
        dh[i] = hi; dl[i] = lo;
    }
}

// ---------------- gather A for word GEMM ----------------
__global__ __launch_bounds__(256)
void k_gatherA_x(const int* __restrict__ xtok, const float* __restrict__ embw) {
    const int warp = threadIdx.x >> 5, lane = threadIdx.x & 31;
    const int row = blockIdx.x * 8 + warp;
    const int tok = xtok[row];
    const int nidx = (row & 255) * 128 + (row >> 8);
    uint2* dh = (uint2*)(g_AxH + (size_t)row * DIM);
    uint2* dl = (uint2*)(g_AxL + (size_t)row * DIM);
    #pragma unroll
    for (int q = 0; q < 3; q++) {
        int k4 = q * 32 + lane;
        int k = k4 * 4;
        float4 v = (k < EMB)
            ? *(const float4*)(embw + (size_t)tok * EMB + k)
            : *(const float4*)(g_charh + (size_t)nidx * CHID + (k - EMB));
        uint2 hi, lo;
        cvtf4(v, hi, lo);
        dh[k4] = hi; dl[k4] = lo;
    }
}

// ---------------- wmma split-bf16 GEMM: C = A·B^T + bias ---------------------
#define GPAD 72
#define GSM_A  (128*GPAD)
#define GSM_B  (64*GPAD)
#define GEMM_SMEM ((2*GSM_A + 2*GSM_B) * 2)

__global__ __launch_bounds__(256)
void k_gemm(const __nv_bfloat16* __restrict__ Ah, const __nv_bfloat16* __restrict__ Al,
            const __nv_bfloat16* __restrict__ Bh, const __nv_bfloat16* __restrict__ Bl,
            const float* __restrict__ bias, float* __restrict__ C,
            int N, int K) {
    extern __shared__ char smraw[];
    __nv_bfloat16* sAh = (__nv_bfloat16*)smraw;
    __nv_bfloat16* sAl = sAh + GSM_A;
    __nv_bfloat16* sBh = sAl + GSM_A;
    __nv_bfloat16* sBl = sBh + GSM_B;
    float* sC = (float*)smraw;

    const int tid = threadIdx.x;
    const int warp = tid >> 5;
    const int wm = warp & 3, wn = warp >> 2;
    const int bm = blockIdx.y * 128, bn = blockIdx.x * 64;

    wmma::fragment<wmma::accumulator, 16, 16, 16, float> acc[2][2];
    #pragma unroll
    for (int i = 0; i < 2; i++)
        #pragma unroll
        for (int j = 0; j < 2; j++) wmma::fill_fragment(acc[i][j], 0.f);

    for (int k0 = 0; k0 < K; k0 += 64) {
        #pragma unroll
        for (int q = 0; q < 4; q++) {
            int j = tid * 4 + q;
            int r = j >> 3, c8 = j & 7;
            const uint4* sh = (const uint4*)(Ah + (size_t)(bm + r) * K + k0);
            const uint4* sl = (const uint4*)(Al + (size_t)(bm + r) * K + k0);
            *(uint4*)(sAh + r*GPAD + c8*8) = sh[c8];
            *(uint4*)(sAl + r*GPAD + c8*8) = sl[c8];
        }
        #pragma unroll
        for (int q = 0; q < 2; q++) {
            int j = tid * 2 + q;
            int r = j >> 3, c8 = j & 7;
            const uint4* sh = (const uint4*)(Bh + (size_t)(bn + r) * K + k0);
            const uint4* sl = (const uint4*)(Bl + (size_t)(bn + r) * K + k0);
            *(uint4*)(sBh + r*GPAD + c8*8) = sh[c8];
            *(uint4*)(sBl + r*GPAD + c8*8) = sl[c8];
        }
        __syncthreads();

        #pragma unroll
        for (int kk = 0; kk < 4; kk++) {
            wmma::fragment<wmma::matrix_a, 16, 16, 16, __nv_bfloat16, wmma::row_major> aH[2], aL[2];
            wmma::fragment<wmma::matrix_b, 16, 16, 16, __nv_bfloat16, wmma::col_major> bH[2], bL[2];
            #pragma unroll
            for (int mi = 0; mi < 2; mi++) {
                wmma::load_matrix_sync(aH[mi], sAh + (wm*32 + mi*16)*GPAD + kk*16, GPAD);
                wmma::load_matrix_sync(aL[mi], sAl + (wm*32 + mi*16)*GPAD + kk*16, GPAD);
            }
            #pragma unroll
            for (int ni = 0; ni < 2; ni++) {
                wmma::load_matrix_sync(bH[ni], sBh + (wn*32 + ni*16)*GPAD + kk*16, GPAD);
                wmma::load_matrix_sync(bL[ni], sBl + (wn*32 + ni*16)*GPAD + kk*16, GPAD);
            }
            #pragma unroll
            for (int mi = 0; mi < 2; mi++)
                #pragma unroll
                for (int ni = 0; ni < 2; ni++) {
                    wmma::mma_sync(acc[mi][ni], aH[mi], bH[ni], acc[mi][ni]);
                    wmma::mma_sync(acc[mi][ni], aH[mi], bL[ni], acc[mi][ni]);
                    wmma::mma_sync(acc[mi][ni], aL[mi], bH[ni], acc[mi][ni]);
                }
        }
        __syncthreads();
    }

    #pragma unroll
    for (int mi = 0; mi < 2; mi++)
        #pragma unroll
        for (int ni = 0; ni < 2; ni++)
            wmma::store_matrix_sync(sC + (wm*32 + mi*16)*68 + wn*32 + ni*16,
                                    acc[mi][ni], 68, wmma::mem_row_major);
    __syncthreads();
    #pragma unroll
    for (int q = 0; q < 8; q++) {
        int j = q * 256 + tid;
        int r = j >> 4, c4 = (j & 15) * 4;
        float4 v = *(float4*)(sC + r*68 + c4);
        float4 b = *(const float4*)(bias + bn + c4);
        v.x += b.x; v.y += b.y; v.z += b.z; v.w += b.w;
        *(float4*)(C + (size_t)(bm + r) * N + bn + c4) = v;
    }
}

// ---------------- kernel CR: char GRU recurrent (WMMA fp16 Wh, split-fp16 h) -
// 64 words/block, 512 threads = 16 warps: wm = warp&1 (m half), wj = warp>>1
// (16-col j group). Wh fp16 resident in SMEM (104KB). h hi/lo fp16 in SMEM.
// All MMA operands in smem; 2 block syncs per timestep; acc[2][3] = 48 regs.
#define CR_M   64
#define CR_HS  136                                  // h row stride (fp16)
#define CR_SC  52                                   // scratch row stride (fp32)
#define CR_OFF_HHI  (G3C*WHS*2)                     // 104448
#define CR_OFF_HLO  (CR_OFF_HHI + CR_M*CR_HS*2)     // +17408
#define CR_OFF_SCR  (CR_OFF_HLO + CR_M*CR_HS*2)     // +17408
#define CR_OFF_BH   (CR_OFF_SCR + 16*16*CR_SC*4)    // +53248
#define CR_SMEM     (CR_OFF_BH + G3C*4)             // 194048

__global__ __launch_bounds__(512, 1)
void k_charrec(const float* __restrict__ cbh) {
    extern __shared__ char smraw[];
    __half* sWh = (__half*)smraw;                       // [384][136]
    __half* hHi = (__half*)(smraw + CR_OFF_HHI);        // [64][136]
    __half* hLo = (__half*)(smraw + CR_OFF_HLO);
    float*  scr = (float*)(smraw + CR_OFF_SCR);         // [16 warps][16][52]
    float*  sbh = (float*)(smraw + CR_OFF_BH);
    const int tid = threadIdx.x;
    const int warp = tid >> 5, lane = tid & 31;
    const int wm = warp & 1, wj = warp >> 1;
    const int w0 = blockIdx.x * CR_M;
    float* myscr = scr + warp * 16 * CR_SC;

    // init: Wh copy, h = 0, bias
    {
        const uint4* s = (const uint4*)g_Wh16;
        uint4* d = (uint4*)sWh;
        for (int i = tid; i < G3C*WHS*2/16; i += 512) d[i] = s[i];
        uint32_t* hz = (uint32_t*)hHi;
        for (int i = tid; i < 2*CR_M*CR_HS/2; i += 512) hz[i] = 0u;
        if (tid < G3C) sbh[tid] = cbh[tid];
    }
    __syncthreads();

    for (int t = 0; t < LLC; t++) {
        wmma::fragment<wmma::accumulator, 16, 16, 16, float> acc[2][3];
        #pragma unroll
        for (int mi = 0; mi < 2; mi++)
            #pragma unroll
            for (int g = 0; g < 3; g++) wmma::fill_fragment(acc[mi][g], 0.f);

        #pragma unroll
        for (int kk = 0; kk < 8; kk++) {
            wmma::fragment<wmma::matrix_a, 16, 16, 16, __half, wmma::row_major> aH[2], aL[2];
            #pragma unroll
            for (int mi = 0; mi < 2; mi++) {
                wmma::load_matrix_sync(aH[mi], hHi + (wm*32 + mi*16)*CR_HS + kk*16, CR_HS);
                wmma::load_matrix_sync(aL[mi], hLo + (wm*32 + mi*16)*CR_HS + kk*16, CR_HS);
            }
            #pragma unroll
            for (int g = 0; g < 3; g++) {
                wmma::fragment<wmma::matrix_b, 16, 16, 16, __half, wmma::col_major> b;
                wmma::load_matrix_sync(b, sWh + (g*CHID + wj*16)*WHS + kk*16, WHS);
                #pragma unroll
                for (int mi = 0; mi < 2; mi++) {
                    wmma::mma_sync(acc[mi][g], aH[mi], b, acc[mi][g]);
                    wmma::mma_sync(acc[mi][g], aL[mi], b, acc[mi][g]);
                }
            }
        }
        __syncthreads();   // all h reads complete before updates

        #pragma unroll
        for (int mi = 0; mi < 2; mi++) {
            #pragma unroll
            for (int g = 0; g < 3; g++)
                wmma::store_matrix_sync(myscr + g*16, acc[mi][g], CR_SC, wmma::mem_row_major);
            __syncwarp();
            #pragma unroll
            for (int q = 0; q < 8; q++) {
                int e = lane + 32*q;
                int row = e >> 4, jj = e & 15;
                int m = wm*32 + mi*16 + row;
                int j = wj*16 + jj;
                float pR = myscr[row*CR_SC + jj]      + sbh[j];
                float pZ = myscr[row*CR_SC + 16 + jj] + sbh[CHID + j];
                float pN = myscr[row*CR_SC + 32 + jj] + sbh[2*CHID + j];
                size_t rr = ((size_t)(w0 + m)*LLC + t)*G3C;
                float xr = g_cxw[rr + j];
                float xz = g_cxw[rr + CHID + j];
                float xn = g_cxw[rr + 2*CHID + j];
                float r  = 1.f / (1.f + expf(-(xr + pR)));
                float z  = 1.f / (1.f + expf(-(xz + pZ)));
                float nn = tanhf(xn + r*pN);
                float hp = __half2float(hHi[m*CR_HS + j]) + __half2float(hLo[m*CR_HS + j]);
                float hn = nn + z*(hp - nn);
                __half hh = __float2half(hn);
                hHi[m*CR_HS + j] = hh;
                hLo[m*CR_HS + j] = __float2half(hn - __half2float(hh));
            }
            __syncwarp();
        }
        __syncthreads();   // all h writes complete before next step's reads
    }

    #pragma unroll
    for (int mi = 0; mi < 2; mi++)
        #pragma unroll
        for (int q = 0; q < 8; q++) {
            int e = lane + 32*q;
            int row = e >> 4, jj = e & 15;
            int m = wm*32 + mi*16 + row;
            int j = wj*16 + jj;
            g_charh[(size_t)(w0 + m)*CHID + j] =
                __half2float(hHi[m*CR_HS + j]) + __half2float(hLo[m*CR_HS + j]);
        }
}

// ---------------- persistent word GRU (per-group barriers) -------------------
__device__ __forceinline__ void group_barrier(int g) {
    __threadfence();
    __syncthreads();
    if (threadIdx.x == 0) {
        volatile unsigned int* vph = &g_barPh[g];
        unsigned int ph = *vph;
        unsigned int a = atomicAdd(&g_barA[g], 1u);
        if (a == 31u) {
            g_barA[g] = 0u;
            __threadfence();
            *vph = ph + 1u;
        } else {
            while (*vph == ph) { __nanosleep(20); }
        }
        __threadfence();
    }
    __syncthreads();
}

__device__ __forceinline__ float dot4(float4 a, float4 b, float c) {
    c = fmaf(a.x, b.x, c); c = fmaf(a.y, b.y, c);
    c = fmaf(a.z, b.z, c); c = fmaf(a.w, b.w, c);
    return c;
}

#define WBB 32
#define WJB 16
#define WST 516

__global__ __launch_bounds__(128, 1)
void k_wordgru(const float* __restrict__ gWh, const float* __restrict__ gbh) {
    extern __shared__ float sm[];
    float* sW = sm;
    float* sH = sm + 48*WST;
    const int tid = threadIdx.x;
    const int bid = blockIdx.x;
    const int jc = bid & 31, bc = bid >> 5;
    const int j0 = jc * WJB, b0 = bc * WBB;
    const int jl = tid & 15;
    const int bq = tid >> 4;
    const int bl0 = bq * 4;

    for (int i = tid; i < 48*HID; i += 128) {
        int gl = i >> 9, k = i & 511;
        int gate = gl >> 4, jj = gl & 15;
        int g = gate*HID + j0 + jj;
        sW[gl*WST + k] = gWh[(size_t)g*HID + k];
    }
    const float bhR = gbh[j0 + jl];
    const float bhZ = gbh[HID + j0 + jl];
    const float bhN = gbh[2*HID + j0 + jl];
    {
        float4 z4 = make_float4(0.f,0.f,0.f,0.f);
        float4* h4 = (float4*)sH;
        for (int i = tid; i < WBB*HID/4; i += 128) h4[i] = z4;
    }
    __syncthreads();

    const float4* wR = (const float4*)(sW + (0*16 + jl)*WST);
    const float4* wZ = (const float4*)(sW + (16  + jl)*WST);
    const float4* wN = (const float4*)(sW + (32  + jl)*WST);
    const int j = j0 + jl;

    for (int s = 0; s < SSQ; s++) {
        float xr[4], xz[4], xn[4];
        #pragma unroll
        for (int q = 0; q < 4; q++) {
            size_t base = ((size_t)(b0 + bl0 + q)*SSQ + s) * G3H;
            xr[q] = g_xw[base + j];
            xz[q] = g_xw[base + HID + j];
            xn[q] = g_xw[base + 2*HID + j];
        }

        float aR[4], aZ[4], aNh[4];
        #pragma unroll
        for (int q = 0; q < 4; q++) { aR[q]=bhR; aZ[q]=bhZ; aNh[q]=bhN; }

        const float4* h0p = (const float4*)(sH + (bl0+0)*HID);
        const float4* h1p = (const float4*)(sH + (bl0+1)*HID);
        const float4* h2p = (const float4*)(sH + (bl0+2)*HID);
        const float4* h3p = (const float4*)(sH + (bl0+3)*HID);
        #pragma unroll 4
        for (int k4 = 0; k4 < HID/4; k4++) {
            float4 r4 = wR[k4], z4 = wZ[k4], n4 = wN[k4];
            float4 h0 = h0p[k4], h1 = h1p[k4], h2 = h2p[k4], h3 = h3p[k4];
            aR[0]=dot4(h0,r4,aR[0]); aZ[0]=dot4(h0,z4,aZ[0]); aNh[0]=dot4(h0,n4,aNh[0]);
            aR[1]=dot4(h1,r4,aR[1]); aZ[1]=dot4(h1,z4,aZ[1]); aNh[1]=dot4(h1,n4,aNh[1]);
            aR[2]=dot4(h2,r4,aR[2]); aZ[2]=dot4(h2,z4,aZ[2]); aNh[2]=dot4(h2,n4,aNh[2]);
            aR[3]=dot4(h3,r4,aR[3]); aZ[3]=dot4(h3,z4,aZ[3]); aNh[3]=dot4(h3,n4,aNh[3]);
        }

        float* hOut = g_hword + ((s + 1) & 1) * (BB*HID);
        #pragma unroll
        for (int q = 0; q < 4; q++) {
            int b = b0 + bl0 + q;
            float r  = 1.f / (1.f + expf(-(xr[q] + aR[q])));
            float z  = 1.f / (1.f + expf(-(xz[q] + aZ[q])));
            float nn = tanhf(xn[q] + r*aNh[q]);
            float hp = sH[(bl0+q)*HID + j];
            float hn = nn + z*(hp - nn);
            hOut[b*HID + j] = hn;
            g_gruout[((size_t)b*SSQ + s)*HID + j] = hn;
        }
        if (s == SSQ - 1) break;
        group_barrier(bc);
        const float4* hIn4 = (const float4*)(g_hword + ((s + 1) & 1) * (BB*HID) + b0*HID);
        float4* sH4 = (float4*)sH;
        for (int i = tid; i < WBB*HID/4; i += 128) sH4[i] = hIn4[i];
        __syncthreads();
    }
}

// ---------------- classifier ----------------
__global__ __launch_bounds__(256)
void k_cls(const float* __restrict__ clsW, const float* __restrict__ clsb,
           float* __restrict__ out) {
    const int warp = threadIdx.x >> 5, lane = threadIdx.x & 31;
    const int gw = blockIdx.x * 8 + warp;
    for (int row = gw; row < NW; row += gridDim.x * 8) {
        const float* hrow = g_gruout + (size_t)row * HID;
        float acc[NCLS];
        #pragma unroll
        for (int c = 0; c < NCLS; c++) acc[c] = 0.f;
        for (int k = lane; k < HID; k += 32) {
            float hv = hrow[k];
            #pragma unroll
            for (int c = 0; c < NCLS; c++)
                acc[c] = fmaf(hv, clsW[c*HID + k], acc[c]);
        }
        #pragma unroll
        for (int off = 16; off > 0; off >>= 1) {
            #pragma unroll
            for (int c = 0; c < NCLS; c++)
                acc[c] += __shfl_down_sync(0xffffffffu, acc[c], off);
        }
        if (lane == 0) {
            #pragma unroll
            for (int c = 0; c < NCLS; c++)
                out[(size_t)row*NCLS + c] = acc[c] + clsb[c];
        }
    }
}

// ---------------- launch ----------------
extern "C" void kernel_launch(void* const* d_in, const int* in_sizes, int n_in,
                              void* d_out, int out_size) {
    const int*   x     = (const int*)  d_in[0];
    const int*   xch   = (const int*)  d_in[1];
    const float* embw  = (const float*)d_in[2];
    const float* cembw = (const float*)d_in[3];
    const float* cWi   = (const float*)d_in[4];
    const float* cWh   = (const float*)d_in[5];
    const float* cbi   = (const float*)d_in[6];
    const float* cbh   = (const float*)d_in[7];
    const float* gWi   = (const float*)d_in[8];
    const float* gWh   = (const float*)d_in[9];
    const float* gbi   = (const float*)d_in[10];
    const float* gbh   = (const float*)d_in[11];
    const float* clsW  = (const float*)d_in[12];
    const float* clsb  = (const float*)d_in[13];
    float* out = (float*)d_out;

    void *aCh, *aCl, *aXh, *aXl, *bCh, *bCl, *bXh, *bXl;
    cudaGetSymbolAddress(&aCh, g_AcH);  cudaGetSymbolAddress(&aCl, g_AcL);
    cudaGetSymbolAddress(&aXh, g_AxH);  cudaGetSymbolAddress(&aXl, g_AxL);
    cudaGetSymbolAddress(&bCh, g_BcxHi); cudaGetSymbolAddress(&bCl, g_BcxLo);
    cudaGetSymbolAddress(&bXh, g_BxwHi); cudaGetSymbolAddress(&bXl, g_BxwLo);
    void *pcxw, *pxw;
    cudaGetSymbolAddress(&pcxw, g_cxw);
    cudaGetSymbolAddress(&pxw, g_xw);

    const int wsmem  = (48*WST + WBB*HID) * 4;
    cudaFuncSetAttribute(k_charrec, cudaFuncAttributeMaxDynamicSharedMemorySize, CR_SMEM);
    cudaFuncSetAttribute(k_wordgru, cudaFuncAttributeMaxDynamicSharedMemorySize, wsmem);
    cudaFuncSetAttribute(k_gemm,    cudaFuncAttributeMaxDynamicSharedMemorySize, GEMM_SMEM);

    k_prep<<<512, 256>>>(cWh, gWi, cWi);
    k_gatherA_c<<<NW*LLC/256, 256>>>(xch, cembw);
    dim3 gc(G3C/64, NW*LLC/128);   // (6, 4096)
    k_gemm<<<gc, 256, GEMM_SMEM>>>((const __nv_bfloat16*)aCh, (const __nv_bfloat16*)aCl,
                                   (const __nv_bfloat16*)bCh, (const __nv_bfloat16*)bCl,
                                   cbi, (float*)pcxw, G3C, CEMB);
    k_charrec<<<NW/CR_M, 512, CR_SMEM>>>(cbh);
    k_gatherA_x<<<NW/8, 256>>>(x, embw);
    dim3 gx(G3H/64, NW/128);       // (24, 256)
    k_gemm<<<gx, 256, GEMM_SMEM>>>((const __nv_bfloat16*)aXh, (const __nv_bfloat16*)aXl,
                                   (const __nv_bfloat16*)bXh, (const __nv_bfloat16*)bXl,
                                   gbi, (float*)pxw, G3H, DIM);
    k_wordgru<<<NBLK_W, 128, wsmem>>>(gWh, gbh);
    k_cls<<<512, 256>>>(clsW, clsb, out);
}

// round 12
// speedup vs baseline: 2.0778x; 1.2516x over previous
#include <cuda_runtime.h>
#include <cuda_bf16.h>
#include <cuda_fp16.h>
#include <mma.h>
#include <cstdint>
#include <math.h>

using namespace nvcuda;

#define BB    128
#define SSQ   256
#define LLC   16
#define EMB   256
#define HID   512
#define NCLS  20
#define CEMB  64
#define CHID  128
#define NW    (BB*SSQ)        // 32768 words
#define DIM   384             // EMB + CHID
#define G3C   384             // 3*CHID
#define G3H   1536            // 3*HID
#define NBLK_W 128

// ---------------- scratch (__device__ globals, no allocation) ----------------
__device__ float g_cxw[(size_t)NW*LLC*G3C];       // char input projections
__device__ float g_charh[NW*CHID];                // char GRU final hidden (n = s*B+b)
__device__ float g_xw[(size_t)NW*G3H];            // word input projections
__device__ float g_gruout[(size_t)NW*HID];
__device__ unsigned int g_barA[4];
__device__ unsigned int g_barPh[4];
// split-bf16 weights (row-major [N][K])
__device__ __nv_bfloat16 g_BxwHi[G3H*DIM],  g_BxwLo[G3H*DIM];
__device__ __nv_bfloat16 g_BcxHi[G3C*CEMB], g_BcxLo[G3C*CEMB];
// char Wh in fp16, padded [384][136]
#define WHS 136
__device__ __half g_Wh16[G3C*WHS];
// word Wh split-fp16 images [1536][512]
__device__ __half g_gWhH16[G3H*HID], g_gWhL16[G3H*HID];
// word GRU hidden state, split-fp16, double buffered
__device__ __half g_h16H[2*BB*HID], g_h16L[2*BB*HID];
// split-bf16 gathered A matrices
__device__ __nv_bfloat16 g_AcH[(size_t)NW*LLC*CEMB], g_AcL[(size_t)NW*LLC*CEMB];
__device__ __nv_bfloat16 g_AxH[(size_t)NW*DIM],      g_AxL[(size_t)NW*DIM];

// ---------------- helpers ----------------
__device__ __forceinline__ void cvtf4(float4 v, uint2& hi, uint2& lo) {
    __nv_bfloat16 hx = __float2bfloat16(v.x), hy = __float2bfloat16(v.y);
    __nv_bfloat16 hz = __float2bfloat16(v.z), hw = __float2bfloat16(v.w);
    float lx = v.x - __bfloat162float(hx), ly = v.y - __bfloat162float(hy);
    float lz = v.z - __bfloat162float(hz), lw = v.w - __bfloat162float(hw);
    union { __nv_bfloat162 b; uint32_t u; } a0, a1, b0, b1;
    a0.b = __halves2bfloat162(hx, hy);  a1.b = __halves2bfloat162(hz, hw);
    b0.b = __halves2bfloat162(__float2bfloat16(lx), __float2bfloat16(ly));
    b1.b = __halves2bfloat162(__float2bfloat16(lz), __float2bfloat16(lw));
    hi = make_uint2(a0.u, a1.u);
    lo = make_uint2(b0.u, b1.u);
}

// ---------------- kernel P: weight prep ----------------
__global__ void k_prep(const float* __restrict__ cWh, const float* __restrict__ gWi,
                       const float* __restrict__ cWi, const float* __restrict__ gWh) {
    int stride = gridDim.x * blockDim.x;
    int i0 = blockIdx.x * blockDim.x + threadIdx.x;
    for (int i = i0; i < G3C*WHS; i += stride) {
        int n = i / WHS, k = i % WHS;
        g_Wh16[i] = (k < CHID) ? __float2half(cWh[n*CHID + k]) : __float2half(0.f);
    }
    for (int i = i0; i < G3H*HID; i += stride) {
        float v = gWh[i];
        __half h = __float2half(v);
        g_gWhH16[i] = h;
        g_gWhL16[i] = __float2half(v - __half2float(h));
    }
    for (int i = i0; i < G3H*DIM; i += stride) {
        float v = gWi[i];
        __nv_bfloat16 h = __float2bfloat16(v);
        g_BxwHi[i] = h;
        g_BxwLo[i] = __float2bfloat16(v - __bfloat162float(h));
    }
    for (int i = i0; i < G3C*CEMB; i += stride) {
        float v = cWi[i];
        __nv_bfloat16 h = __float2bfloat16(v);
        g_BcxHi[i] = h;
        g_BcxLo[i] = __float2bfloat16(v - __bfloat162float(h));
    }
}

// ---------------- gather A for char GEMM ----------------
__global__ __launch_bounds__(256)
void k_gatherA_c(const int* __restrict__ xc, const float* __restrict__ cembw) {
    const int r = blockIdx.x * 256 + threadIdx.x;
    const int c = xc[r];
    const float4* src = (const float4*)(cembw + (size_t)c * CEMB);
    uint2* dh = (uint2*)(g_AcH + (size_t)r * CEMB);
    uint2* dl = (uint2*)(g_AcL + (size_t)r * CEMB);
    #pragma unroll
    for (int i = 0; i < 16; i++) {
        uint2 hi, lo;
        cvtf4(src[i], hi, lo);
        dh[i] = hi; dl[i] = lo;
    }
}

// ---------------- gather A for word GEMM ----------------
__global__ __launch_bounds__(256)
void k_gatherA_x(const int* __restrict__ xtok, const float* __restrict__ embw) {
    const int warp = threadIdx.x >> 5, lane = threadIdx.x & 31;
    const int row = blockIdx.x * 8 + warp;
    const int tok = xtok[row];
    const int nidx = (row & 255) * 128 + (row >> 8);
    uint2* dh = (uint2*)(g_AxH + (size_t)row * DIM);
    uint2* dl = (uint2*)(g_AxL + (size_t)row * DIM);
    #pragma unroll
    for (int q = 0; q < 3; q++) {
        int k4 = q * 32 + lane;
        int k = k4 * 4;
        float4 v = (k < EMB)
            ? *(const float4*)(embw + (size_t)tok * EMB + k)
            : *(const float4*)(g_charh + (size_t)nidx * CHID + (k - EMB));
        uint2 hi, lo;
        cvtf4(v, hi, lo);
        dh[k4] = hi; dl[k4] = lo;
    }
}

// ---------------- wmma split-bf16 GEMM: C = A·B^T + bias ---------------------
#define GPAD 72
#define GSM_A  (128*GPAD)
#define GSM_B  (64*GPAD)
#define GEMM_SMEM ((2*GSM_A + 2*GSM_B) * 2)

__global__ __launch_bounds__(256)
void k_gemm(const __nv_bfloat16* __restrict__ Ah, const __nv_bfloat16* __restrict__ Al,
            const __nv_bfloat16* __restrict__ Bh, const __nv_bfloat16* __restrict__ Bl,
            const float* __restrict__ bias, float* __restrict__ C,
            int N, int K) {
    extern __shared__ char smraw[];
    __nv_bfloat16* sAh = (__nv_bfloat16*)smraw;
    __nv_bfloat16* sAl = sAh + GSM_A;
    __nv_bfloat16* sBh = sAl + GSM_A;
    __nv_bfloat16* sBl = sBh + GSM_B;
    float* sC = (float*)smraw;

    const int tid = threadIdx.x;
    const int warp = tid >> 5;
    const int wm = warp & 3, wn = warp >> 2;
    const int bm = blockIdx.y * 128, bn = blockIdx.x * 64;

    wmma::fragment<wmma::accumulator, 16, 16, 16, float> acc[2][2];
    #pragma unroll
    for (int i = 0; i < 2; i++)
        #pragma unroll
        for (int j = 0; j < 2; j++) wmma::fill_fragment(acc[i][j], 0.f);

    for (int k0 = 0; k0 < K; k0 += 64) {
        #pragma unroll
        for (int q = 0; q < 4; q++) {
            int j = tid * 4 + q;
            int r = j >> 3, c8 = j & 7;
            const uint4* sh = (const uint4*)(Ah + (size_t)(bm + r) * K + k0);
            const uint4* sl = (const uint4*)(Al + (size_t)(bm + r) * K + k0);
            *(uint4*)(sAh + r*GPAD + c8*8) = sh[c8];
            *(uint4*)(sAl + r*GPAD + c8*8) = sl[c8];
        }
        #pragma unroll
        for (int q = 0; q < 2; q++) {
            int j = tid * 2 + q;
            int r = j >> 3, c8 = j & 7;
            const uint4* sh = (const uint4*)(Bh + (size_t)(bn + r) * K + k0);
            const uint4* sl = (const uint4*)(Bl + (size_t)(bn + r) * K + k0);
            *(uint4*)(sBh + r*GPAD + c8*8) = sh[c8];
            *(uint4*)(sBl + r*GPAD + c8*8) = sl[c8];
        }
        __syncthreads();

        #pragma unroll
        for (int kk = 0; kk < 4; kk++) {
            wmma::fragment<wmma::matrix_a, 16, 16, 16, __nv_bfloat16, wmma::row_major> aH[2], aL[2];
            wmma::fragment<wmma::matrix_b, 16, 16, 16, __nv_bfloat16, wmma::col_major> bH[2], bL[2];
            #pragma unroll
            for (int mi = 0; mi < 2; mi++) {
                wmma::load_matrix_sync(aH[mi], sAh + (wm*32 + mi*16)*GPAD + kk*16, GPAD);
                wmma::load_matrix_sync(aL[mi], sAl + (wm*32 + mi*16)*GPAD + kk*16, GPAD);
            }
            #pragma unroll
            for (int ni = 0; ni < 2; ni++) {
                wmma::load_matrix_sync(bH[ni], sBh + (wn*32 + ni*16)*GPAD + kk*16, GPAD);
                wmma::load_matrix_sync(bL[ni], sBl + (wn*32 + ni*16)*GPAD + kk*16, GPAD);
            }
            #pragma unroll
            for (int mi = 0; mi < 2; mi++)
                #pragma unroll
                for (int ni = 0; ni < 2; ni++) {
                    wmma::mma_sync(acc[mi][ni], aH[mi], bH[ni], acc[mi][ni]);
                    wmma::mma_sync(acc[mi][ni], aH[mi], bL[ni], acc[mi][ni]);
                    wmma::mma_sync(acc[mi][ni], aL[mi], bH[ni], acc[mi][ni]);
                }
        }
        __syncthreads();
    }

    #pragma unroll
    for (int mi = 0; mi < 2; mi++)
        #pragma unroll
        for (int ni = 0; ni < 2; ni++)
            wmma::store_matrix_sync(sC + (wm*32 + mi*16)*68 + wn*32 + ni*16,
                                    acc[mi][ni], 68, wmma::mem_row_major);
    __syncthreads();
    #pragma unroll
    for (int q = 0; q < 8; q++) {
        int j = q * 256 + tid;
        int r = j >> 4, c4 = (j & 15) * 4;
        float4 v = *(float4*)(sC + r*68 + c4);
        float4 b = *(const float4*)(bias + bn + c4);
        v.x += b.x; v.y += b.y; v.z += b.z; v.w += b.w;
        *(float4*)(C + (size_t)(bm + r) * N + bn + c4) = v;
    }
}

// ---------------- kernel CR: char GRU recurrent (WMMA fp16 Wh, split-fp16 h) -
#define CR_M   64
#define CR_HS  136
#define CR_SC  52
#define CR_OFF_HHI  (G3C*WHS*2)
#define CR_OFF_HLO  (CR_OFF_HHI + CR_M*CR_HS*2)
#define CR_OFF_SCR  (CR_OFF_HLO + CR_M*CR_HS*2)
#define CR_OFF_BH   (CR_OFF_SCR + 16*16*CR_SC*4)
#define CR_SMEM     (CR_OFF_BH + G3C*4)

__global__ __launch_bounds__(512, 1)
void k_charrec(const float* __restrict__ cbh) {
    extern __shared__ char smraw[];
    __half* sWh = (__half*)smraw;
    __half* hHi = (__half*)(smraw + CR_OFF_HHI);
    __half* hLo = (__half*)(smraw + CR_OFF_HLO);
    float*  scr = (float*)(smraw + CR_OFF_SCR);
    float*  sbh = (float*)(smraw + CR_OFF_BH);
    const int tid = threadIdx.x;
    const int warp = tid >> 5, lane = tid & 31;
    const int wm = warp & 1, wj = warp >> 1;
    const int w0 = blockIdx.x * CR_M;
    float* myscr = scr + warp * 16 * CR_SC;

    {
        const uint4* s = (const uint4*)g_Wh16;
        uint4* d = (uint4*)sWh;
        for (int i = tid; i < G3C*WHS*2/16; i += 512) d[i] = s[i];
        uint32_t* hz = (uint32_t*)hHi;
        for (int i = tid; i < 2*CR_M*CR_HS/2; i += 512) hz[i] = 0u;
        if (tid < G3C) sbh[tid] = cbh[tid];
    }
    __syncthreads();

    for (int t = 0; t < LLC; t++) {
        wmma::fragment<wmma::accumulator, 16, 16, 16, float> acc[2][3];
        #pragma unroll
        for (int mi = 0; mi < 2; mi++)
            #pragma unroll
            for (int g = 0; g < 3; g++) wmma::fill_fragment(acc[mi][g], 0.f);

        #pragma unroll
        for (int kk = 0; kk < 8; kk++) {
            wmma::fragment<wmma::matrix_a, 16, 16, 16, __half, wmma::row_major> aH[2], aL[2];
            #pragma unroll
            for (int mi = 0; mi < 2; mi++) {
                wmma::load_matrix_sync(aH[mi], hHi + (wm*32 + mi*16)*CR_HS + kk*16, CR_HS);
                wmma::load_matrix_sync(aL[mi], hLo + (wm*32 + mi*16)*CR_HS + kk*16, CR_HS);
            }
            #pragma unroll
            for (int g = 0; g < 3; g++) {
                wmma::fragment<wmma::matrix_b, 16, 16, 16, __half, wmma::col_major> b;
                wmma::load_matrix_sync(b, sWh + (g*CHID + wj*16)*WHS + kk*16, WHS);
                #pragma unroll
                for (int mi = 0; mi < 2; mi++) {
                    wmma::mma_sync(acc[mi][g], aH[mi], b, acc[mi][g]);
                    wmma::mma_sync(acc[mi][g], aL[mi], b, acc[mi][g]);
                }
            }
        }
        __syncthreads();

        #pragma unroll
        for (int mi = 0; mi < 2; mi++) {
            #pragma unroll
            for (int g = 0; g < 3; g++)
                wmma::store_matrix_sync(myscr + g*16, acc[mi][g], CR_SC, wmma::mem_row_major);
            __syncwarp();
            #pragma unroll
            for (int q = 0; q < 8; q++) {
                int e = lane + 32*q;
                int row = e >> 4, jj = e & 15;
                int m = wm*32 + mi*16 + row;
                int j = wj*16 + jj;
                float pR = myscr[row*CR_SC + jj]      + sbh[j];
                float pZ = myscr[row*CR_SC + 16 + jj] + sbh[CHID + j];
                float pN = myscr[row*CR_SC + 32 + jj] + sbh[2*CHID + j];
                size_t rr = ((size_t)(w0 + m)*LLC + t)*G3C;
                float xr = g_cxw[rr + j];
                float xz = g_cxw[rr + CHID + j];
                float xn = g_cxw[rr + 2*CHID + j];
                float r  = 1.f / (1.f + expf(-(xr + pR)));
                float z  = 1.f / (1.f + expf(-(xz + pZ)));
                float nn = tanhf(xn + r*pN);
                float hp = __half2float(hHi[m*CR_HS + j]) + __half2float(hLo[m*CR_HS + j]);
                float hn = nn + z*(hp - nn);
                __half hh = __float2half(hn);
                hHi[m*CR_HS + j] = hh;
                hLo[m*CR_HS + j] = __float2half(hn - __half2float(hh));
            }
            __syncwarp();
        }
        __syncthreads();
    }

    #pragma unroll
    for (int mi = 0; mi < 2; mi++)
        #pragma unroll
        for (int q = 0; q < 8; q++) {
            int e = lane + 32*q;
            int row = e >> 4, jj = e & 15;
            int m = wm*32 + mi*16 + row;
            int j = wj*16 + jj;
            g_charh[(size_t)(w0 + m)*CHID + j] =
                __half2float(hHi[m*CR_HS + j]) + __half2float(hLo[m*CR_HS + j]);
        }
}

// ---------------- group barrier ----------------
__device__ __forceinline__ void group_barrier(int g) {
    __threadfence();
    __syncthreads();
    if (threadIdx.x == 0) {
        volatile unsigned int* vph = &g_barPh[g];
        unsigned int ph = *vph;
        unsigned int a = atomicAdd(&g_barA[g], 1u);
        if (a == 31u) {
            g_barA[g] = 0u;
            __threadfence();
            *vph = ph + 1u;
        } else {
            while (*vph == ph) { __nanosleep(20); }
        }
        __threadfence();
    }
    __syncthreads();
}

// ---------------- persistent word GRU (WMMA split-fp16) ----------------------
// 128 blocks = 4 m-groups x 32 j-blocks. Block: 32 batch rows x 16 hidden units
// (3 gate cols per unit -> N=48). 256 threads; warps 0-5 own one 16x16 tile
// (2m x 3n). Wh slice split-fp16 resident in smem; h staged from global
// split-fp16 double buffer each step.
#define WG_LDW 520
#define WG_LDH 520
#define WG_SC  52
#define WG_OFF_WHL  (48*WG_LDW*2)                   // 49920
#define WG_OFF_HH   (2*48*WG_LDW*2)                 // 99840
#define WG_OFF_HL   (WG_OFF_HH + 32*WG_LDH*2)      // 133120
#define WG_OFF_PRE  (WG_OFF_HL + 32*WG_LDH*2)      // 166400
#define WG_OFF_BH   (WG_OFF_PRE + 32*WG_SC*4)      // 173056
#define WG_SMEM     (WG_OFF_BH + 48*4)             // 173248

__global__ __launch_bounds__(256, 1)
void k_wordgru(const float* __restrict__ gbh) {
    extern __shared__ char smraw[];
    __half* sWhH = (__half*)smraw;                     // [48][520]
    __half* sWhL = (__half*)(smraw + WG_OFF_WHL);
    __half* sHh  = (__half*)(smraw + WG_OFF_HH);       // [32][520]
    __half* sHl  = (__half*)(smraw + WG_OFF_HL);
    float*  pre  = (float*)(smraw + WG_OFF_PRE);       // [32][52]
    float*  sbh  = (float*)(smraw + WG_OFF_BH);        // [48]
    const int tid = threadIdx.x;
    const int warp = tid >> 5, lane = tid & 31;
    const int bid = blockIdx.x;
    const int mb = bid >> 5, jb = bid & 31;
    const int b0 = mb * 32, j0 = jb * 16;

    // stage Wh slices (once), bias, init h buf0 slice to zero
    for (int i = tid; i < 48*64; i += 256) {
        int r = i >> 6, c8 = (i & 63) * 8;
        int gate = r >> 4, jj = r & 15;
        size_t src = (size_t)(gate*HID + j0 + jj) * HID + c8;
        *(uint4*)(sWhH + r*WG_LDW + c8) = *(const uint4*)(g_gWhH16 + src);
        *(uint4*)(sWhL + r*WG_LDW + c8) = *(const uint4*)(g_gWhL16 + src);
    }
    if (tid < 48) {
        int gate = tid >> 4, jj = tid & 15;
        sbh[tid] = gbh[gate*HID + j0 + jj];
    }
    {
        // zero own h slice in buffer 0 (ownership: rows b0..b0+32, cols j0..j0+16)
        for (int e = tid; e < 32*16; e += 256) {
            int m = e >> 4, jj = e & 15;
            int idx = (b0 + m)*HID + j0 + jj;
            g_h16H[idx] = __float2half(0.f);
            g_h16L[idx] = __float2half(0.f);
        }
    }
    __syncthreads();
    group_barrier(mb);

    const int wmi = warp & 1, wni = warp >> 1;   // warps 0-5: tile (wmi, wni)

    for (int s = 0; s < SSQ; s++) {
        // stage h (hi/lo) for this m-group from buffer s&1
        {
            const __half* srcH = g_h16H + (s & 1) * (BB*HID);
            const __half* srcL = g_h16L + (s & 1) * (BB*HID);
            for (int i = tid; i < 32*64; i += 256) {
                int r = i >> 6, c8 = (i & 63) * 8;
                size_t src = (size_t)(b0 + r) * HID + c8;
                *(uint4*)(sHh + r*WG_LDH + c8) = *(const uint4*)(srcH + src);
                *(uint4*)(sHl + r*WG_LDH + c8) = *(const uint4*)(srcL + src);
            }
        }
        __syncthreads();

        if (warp < 6) {
            wmma::fragment<wmma::accumulator, 16, 16, 16, float> acc;
            wmma::fill_fragment(acc, 0.f);
            #pragma unroll 4
            for (int kk = 0; kk < 32; kk++) {
                wmma::fragment<wmma::matrix_a, 16, 16, 16, __half, wmma::row_major> aH, aL;
                wmma::fragment<wmma::matrix_b, 16, 16, 16, __half, wmma::col_major> bH, bL;
                wmma::load_matrix_sync(aH, sHh + (wmi*16)*WG_LDH + kk*16, WG_LDH);
                wmma::load_matrix_sync(aL, sHl + (wmi*16)*WG_LDH + kk*16, WG_LDH);
                wmma::load_matrix_sync(bH, sWhH + (wni*16)*WG_LDW + kk*16, WG_LDW);
                wmma::load_matrix_sync(bL, sWhL + (wni*16)*WG_LDW + kk*16, WG_LDW);
                wmma::mma_sync(acc, aH, bH, acc);
                wmma::mma_sync(acc, aL, bH, acc);
                wmma::mma_sync(acc, aH, bL, acc);
            }
            wmma::store_matrix_sync(pre + (wmi*16)*WG_SC + wni*16, acc, WG_SC,
                                    wmma::mem_row_major);
        }
        __syncthreads();

        // gate update: 512 (m, jj) elements over 256 threads
        const int ob = (s + 1) & 1;
        #pragma unroll
        for (int e = tid; e < 512; e += 256) {
            int m = e >> 4, jj = e & 15;
            int b = b0 + m, j = j0 + jj;
            float pR = pre[m*WG_SC + jj]      + sbh[jj];
            float pZ = pre[m*WG_SC + 16 + jj] + sbh[16 + jj];
            float pN = pre[m*WG_SC + 32 + jj] + sbh[32 + jj];
            size_t base = ((size_t)b*SSQ + s) * G3H;
            float xr = g_xw[base + j];
            float xz = g_xw[base + HID + j];
            float xn = g_xw[base + 2*HID + j];
            float r  = 1.f / (1.f + expf(-(xr + pR)));
            float z  = 1.f / (1.f + expf(-(xz + pZ)));
            float nn = tanhf(xn + r*pN);
            float hp = __half2float(sHh[m*WG_LDH + j]) + __half2float(sHl[m*WG_LDH + j]);
            float hn = nn + z*(hp - nn);
            g_gruout[((size_t)b*SSQ + s)*HID + j] = hn;
            __half hh = __float2half(hn);
            int idx = ob*(BB*HID) + b*HID + j;
            g_h16H[idx] = hh;
            g_h16L[idx] = __float2half(hn - __half2float(hh));
        }
        if (s == SSQ - 1) break;
        group_barrier(mb);
    }
}

// ---------------- classifier ----------------
__global__ __launch_bounds__(256)
void k_cls(const float* __restrict__ clsW, const float* __restrict__ clsb,
           float* __restrict__ out) {
    const int warp = threadIdx.x >> 5, lane = threadIdx.x & 31;
    const int gw = blockIdx.x * 8 + warp;
    for (int row = gw; row < NW; row += gridDim.x * 8) {
        const float* hrow = g_gruout + (size_t)row * HID;
        float acc[NCLS];
        #pragma unroll
        for (int c = 0; c < NCLS; c++) acc[c] = 0.f;
        for (int k = lane; k < HID; k += 32) {
            float hv = hrow[k];
            #pragma unroll
            for (int c = 0; c < NCLS; c++)
                acc[c] = fmaf(hv, clsW[c*HID + k], acc[c]);
        }
        #pragma unroll
        for (int off = 16; off > 0; off >>= 1) {
            #pragma unroll
            for (int c = 0; c < NCLS; c++)
                acc[c] += __shfl_down_sync(0xffffffffu, acc[c], off);
        }
        if (lane == 0) {
            #pragma unroll
            for (int c = 0; c < NCLS; c++)
                out[(size_t)row*NCLS + c] = acc[c] + clsb[c];
        }
    }
}

// ---------------- launch ----------------
extern "C" void kernel_launch(void* const* d_in, const int* in_sizes, int n_in,
                              void* d_out, int out_size) {
    const int*   x     = (const int*)  d_in[0];
    const int*   xch   = (const int*)  d_in[1];
    const float* embw  = (const float*)d_in[2];
    const float* cembw = (const float*)d_in[3];
    const float* cWi   = (const float*)d_in[4];
    const float* cWh   = (const float*)d_in[5];
    const float* cbi   = (const float*)d_in[6];
    const float* cbh   = (const float*)d_in[7];
    const float* gWi   = (const float*)d_in[8];
    const float* gWh   = (const float*)d_in[9];
    const float* gbi   = (const float*)d_in[10];
    const float* gbh   = (const float*)d_in[11];
    const float* clsW  = (const float*)d_in[12];
    const float* clsb  = (const float*)d_in[13];
    float* out = (float*)d_out;

    void *aCh, *aCl, *aXh, *aXl, *bCh, *bCl, *bXh, *bXl;
    cudaGetSymbolAddress(&aCh, g_AcH);  cudaGetSymbolAddress(&aCl, g_AcL);
    cudaGetSymbolAddress(&aXh, g_AxH);  cudaGetSymbolAddress(&aXl, g_AxL);
    cudaGetSymbolAddress(&bCh, g_BcxHi); cudaGetSymbolAddress(&bCl, g_BcxLo);
    cudaGetSymbolAddress(&bXh, g_BxwHi); cudaGetSymbolAddress(&bXl, g_BxwLo);
    void *pcxw, *pxw;
    cudaGetSymbolAddress(&pcxw, g_cxw);
    cudaGetSymbolAddress(&pxw, g_xw);

    cudaFuncSetAttribute(k_charrec, cudaFuncAttributeMaxDynamicSharedMemorySize, CR_SMEM);
    cudaFuncSetAttribute(k_wordgru, cudaFuncAttributeMaxDynamicSharedMemorySize, WG_SMEM);
    cudaFuncSetAttribute(k_gemm,    cudaFuncAttributeMaxDynamicSharedMemorySize, GEMM_SMEM);

    k_prep<<<512, 256>>>(cWh, gWi, cWi, gWh);
    k_gatherA_c<<<NW*LLC/256, 256>>>(xch, cembw);
    dim3 gc(G3C/64, NW*LLC/128);   // (6, 4096)
    k_gemm<<<gc, 256, GEMM_SMEM>>>((const __nv_bfloat16*)aCh, (const __nv_bfloat16*)aCl,
                                   (const __nv_bfloat16*)bCh, (const __nv_bfloat16*)bCl,
                                   cbi, (float*)pcxw, G3C, CEMB);
    k_charrec<<<NW/CR_M, 512, CR_SMEM>>>(cbh);
    k_gatherA_x<<<NW/8, 256>>>(x, embw);
    dim3 gx(G3H/64, NW/128);       // (24, 256)
    k_gemm<<<gx, 256, GEMM_SMEM>>>((const __nv_bfloat16*)aXh, (const __nv_bfloat16*)aXl,
                                   (const __nv_bfloat16*)bXh, (const __nv_bfloat16*)bXl,
                                   gbi, (float*)pxw, G3H, DIM);
    k_wordgru<<<NBLK_W, 256, WG_SMEM>>>(gbh);
    k_cls<<<512, 256>>>(clsW, clsb, out);
}

// round 13
// speedup vs baseline: 2.2306x; 1.0735x over previous
#include <cuda_runtime.h>
#include <cuda_bf16.h>
#include <cuda_fp16.h>
#include <mma.h>
#include <cstdint>
#include <math.h>

using namespace nvcuda;

#define BB    128
#define SSQ   256
#define LLC   16
#define EMB   256
#define HID   512
#define NCLS  20
#define CEMB  64
#define CHID  128
#define NW    (BB*SSQ)        // 32768 words
#define DIM   384             // EMB + CHID
#define G3C   384             // 3*CHID
#define G3H   1536            // 3*HID
#define NBLK_W 128

// ---------------- scratch (__device__ globals, no allocation) ----------------
__device__ float g_cxw[(size_t)NW*LLC*G3C];       // char input projections
__device__ float g_charh[NW*CHID];                // char GRU final hidden (n = s*B+b)
__device__ float g_xw[(size_t)NW*G3H];            // word input projections
__device__ float g_gruout[(size_t)NW*HID];
__device__ unsigned int g_barA[4];
__device__ unsigned int g_barPh[4];
// split-bf16 weights (row-major [N][K])
__device__ __nv_bfloat16 g_BxwHi[G3H*DIM],  g_BxwLo[G3H*DIM];
__device__ __nv_bfloat16 g_BcxHi[G3C*CEMB], g_BcxLo[G3C*CEMB];
// char Wh in fp16, padded [384][136]
#define WHS 136
__device__ __half g_Wh16[G3C*WHS];
// word Wh split-fp16 images [1536][512]
__device__ __half g_gWhH16[G3H*HID], g_gWhL16[G3H*HID];
// word GRU hidden state, split-fp16, double buffered
__device__ __half g_h16H[2*BB*HID], g_h16L[2*BB*HID];
// split-bf16 gathered A matrices
__device__ __nv_bfloat16 g_AcH[(size_t)NW*LLC*CEMB], g_AcL[(size_t)NW*LLC*CEMB];
__device__ __nv_bfloat16 g_AxH[(size_t)NW*DIM],      g_AxL[(size_t)NW*DIM];

// ---------------- helpers ----------------
__device__ __forceinline__ void cvtf4(float4 v, uint2& hi, uint2& lo) {
    __nv_bfloat16 hx = __float2bfloat16(v.x), hy = __float2bfloat16(v.y);
    __nv_bfloat16 hz = __float2bfloat16(v.z), hw = __float2bfloat16(v.w);
    float lx = v.x - __bfloat162float(hx), ly = v.y - __bfloat162float(hy);
    float lz = v.z - __bfloat162float(hz), lw = v.w - __bfloat162float(hw);
    union { __nv_bfloat162 b; uint32_t u; } a0, a1, b0, b1;
    a0.b = __halves2bfloat162(hx, hy);  a1.b = __halves2bfloat162(hz, hw);
    b0.b = __halves2bfloat162(__float2bfloat16(lx), __float2bfloat16(ly));
    b1.b = __halves2bfloat162(__float2bfloat16(lz), __float2bfloat16(lw));
    hi = make_uint2(a0.u, a1.u);
    lo = make_uint2(b0.u, b1.u);
}

// ---------------- kernel P: weight prep ----------------
__global__ void k_prep(const float* __restrict__ cWh, const float* __restrict__ gWi,
                       const float* __restrict__ cWi, const float* __restrict__ gWh) {
    int stride = gridDim.x * blockDim.x;
    int i0 = blockIdx.x * blockDim.x + threadIdx.x;
    for (int i = i0; i < G3C*WHS; i += stride) {
        int n = i / WHS, k = i % WHS;
        g_Wh16[i] = (k < CHID) ? __float2half(cWh[n*CHID + k]) : __float2half(0.f);
    }
    for (int i = i0; i < G3H*HID; i += stride) {
        float v = gWh[i];
        __half h = __float2half(v);
        g_gWhH16[i] = h;
        g_gWhL16[i] = __float2half(v - __half2float(h));
    }
    for (int i = i0; i < G3H*DIM; i += stride) {
        float v = gWi[i];
        __nv_bfloat16 h = __float2bfloat16(v);
        g_BxwHi[i] = h;
        g_BxwLo[i] = __float2bfloat16(v - __bfloat162float(h));
    }
    for (int i = i0; i < G3C*CEMB; i += stride) {
        float v = cWi[i];
        __nv_bfloat16 h = __float2bfloat16(v);
        g_BcxHi[i] = h;
        g_BcxLo[i] = __float2bfloat16(v - __bfloat162float(h));
    }
}

// ---------------- gather A for char GEMM ----------------
__global__ __launch_bounds__(256)
void k_gatherA_c(const int* __restrict__ xc, const float* __restrict__ cembw) {
    const int r = blockIdx.x * 256 + threadIdx.x;
    const int c = xc[r];
    const float4* src = (const float4*)(cembw + (size_t)c * CEMB);
    uint2* dh = (uint2*)(g_AcH + (size_t)r * CEMB);
    uint2* dl = (uint2*)(g_AcL + (size_t)r * CEMB);
    #pragma unroll
    for (int i = 0; i < 16; i++) {
        uint2 hi, lo;
        cvtf4(src[i], hi, lo);
        dh[i] = hi; dl[i] = lo;
    }
}

// ---------------- gather A for word GEMM ----------------
__global__ __launch_bounds__(256)
void k_gatherA_x(const int* __restrict__ xtok, const float* __restrict__ embw) {
    const int warp = threadIdx.x >> 5, lane = threadIdx.x & 31;
    const int row = blockIdx.x * 8 + warp;
    const int tok = xtok[row];
    const int nidx = (row & 255) * 128 + (row >> 8);
    uint2* dh = (uint2*)(g_AxH + (size_t)row * DIM);
    uint2* dl = (uint2*)(g_AxL + (size_t)row * DIM);
    #pragma unroll
    for (int q = 0; q < 3; q++) {
        int k4 = q * 32 + lane;
        int k = k4 * 4;
        float4 v = (k < EMB)
            ? *(const float4*)(embw + (size_t)tok * EMB + k)
            : *(const float4*)(g_charh + (size_t)nidx * CHID + (k - EMB));
        uint2 hi, lo;
        cvtf4(v, hi, lo);
        dh[k4] = hi; dl[k4] = lo;
    }
}

// ---------------- wmma split-bf16 GEMM: C = A·B^T + bias ---------------------
#define GPAD 72
#define GSM_A  (128*GPAD)
#define GSM_B  (64*GPAD)
#define GEMM_SMEM ((2*GSM_A + 2*GSM_B) * 2)

__global__ __launch_bounds__(256)
void k_gemm(const __nv_bfloat16* __restrict__ Ah, const __nv_bfloat16* __restrict__ Al,
            const __nv_bfloat16* __restrict__ Bh, const __nv_bfloat16* __restrict__ Bl,
            const float* __restrict__ bias, float* __restrict__ C,
            int N, int K) {
    extern __shared__ char smraw[];
    __nv_bfloat16* sAh = (__nv_bfloat16*)smraw;
    __nv_bfloat16* sAl = sAh + GSM_A;
    __nv_bfloat16* sBh = sAl + GSM_A;
    __nv_bfloat16* sBl = sBh + GSM_B;
    float* sC = (float*)smraw;

    const int tid = threadIdx.x;
    const int warp = tid >> 5;
    const int wm = warp & 3, wn = warp >> 2;
    const int bm = blockIdx.y * 128, bn = blockIdx.x * 64;

    wmma::fragment<wmma::accumulator, 16, 16, 16, float> acc[2][2];
    #pragma unroll
    for (int i = 0; i < 2; i++)
        #pragma unroll
        for (int j = 0; j < 2; j++) wmma::fill_fragment(acc[i][j], 0.f);

    for (int k0 = 0; k0 < K; k0 += 64) {
        #pragma unroll
        for (int q = 0; q < 4; q++) {
            int j = tid * 4 + q;
            int r = j >> 3, c8 = j & 7;
            const uint4* sh = (const uint4*)(Ah + (size_t)(bm + r) * K + k0);
            const uint4* sl = (const uint4*)(Al + (size_t)(bm + r) * K + k0);
            *(uint4*)(sAh + r*GPAD + c8*8) = sh[c8];
            *(uint4*)(sAl + r*GPAD + c8*8) = sl[c8];
        }
        #pragma unroll
        for (int q = 0; q < 2; q++) {
            int j = tid * 2 + q;
            int r = j >> 3, c8 = j & 7;
            const uint4* sh = (const uint4*)(Bh + (size_t)(bn + r) * K + k0);
            const uint4* sl = (const uint4*)(Bl + (size_t)(bn + r) * K + k0);
            *(uint4*)(sBh + r*GPAD + c8*8) = sh[c8];
            *(uint4*)(sBl + r*GPAD + c8*8) = sl[c8];
        }
        __syncthreads();

        #pragma unroll
        for (int kk = 0; kk < 4; kk++) {
            wmma::fragment<wmma::matrix_a, 16, 16, 16, __nv_bfloat16, wmma::row_major> aH[2], aL[2];
            wmma::fragment<wmma::matrix_b, 16, 16, 16, __nv_bfloat16, wmma::col_major> bH[2], bL[2];
            #pragma unroll
            for (int mi = 0; mi < 2; mi++) {
                wmma::load_matrix_sync(aH[mi], sAh + (wm*32 + mi*16)*GPAD + kk*16, GPAD);
                wmma::load_matrix_sync(aL[mi], sAl + (wm*32 + mi*16)*GPAD + kk*16, GPAD);
            }
            #pragma unroll
            for (int ni = 0; ni < 2; ni++) {
                wmma::load_matrix_sync(bH[ni], sBh + (wn*32 + ni*16)*GPAD + kk*16, GPAD);
                wmma::load_matrix_sync(bL[ni], sBl + (wn*32 + ni*16)*GPAD + kk*16, GPAD);
            }
            #pragma unroll
            for (int mi = 0; mi < 2; mi++)
                #pragma unroll
                for (int ni = 0; ni < 2; ni++) {
                    wmma::mma_sync(acc[mi][ni], aH[mi], bH[ni], acc[mi][ni]);
                    wmma::mma_sync(acc[mi][ni], aH[mi], bL[ni], acc[mi][ni]);
                    wmma::mma_sync(acc[mi][ni], aL[mi], bH[ni], acc[mi][ni]);
                }
        }
        __syncthreads();
    }

    #pragma unroll
    for (int mi = 0; mi < 2; mi++)
        #pragma unroll
        for (int ni = 0; ni < 2; ni++)
            wmma::store_matrix_sync(sC + (wm*32 + mi*16)*68 + wn*32 + ni*16,
                                    acc[mi][ni], 68, wmma::mem_row_major);
    __syncthreads();
    #pragma unroll
    for (int q = 0; q < 8; q++) {
        int j = q * 256 + tid;
        int r = j >> 4, c4 = (j & 15) * 4;
        float4 v = *(float4*)(sC + r*68 + c4);
        float4 b = *(const float4*)(bias + bn + c4);
        v.x += b.x; v.y += b.y; v.z += b.z; v.w += b.w;
        *(float4*)(C + (size_t)(bm + r) * N + bn + c4) = v;
    }
}

// ---------------- kernel CR: char GRU recurrent (WMMA fp16 Wh, split-fp16 h) -
#define CR_M   64
#define CR_HS  136
#define CR_SC  52
#define CR_OFF_HHI  (G3C*WHS*2)
#define CR_OFF_HLO  (CR_OFF_HHI + CR_M*CR_HS*2)
#define CR_OFF_SCR  (CR_OFF_HLO + CR_M*CR_HS*2)
#define CR_OFF_BH   (CR_OFF_SCR + 16*16*CR_SC*4)
#define CR_SMEM     (CR_OFF_BH + G3C*4)

__global__ __launch_bounds__(512, 1)
void k_charrec(const float* __restrict__ cbh) {
    extern __shared__ char smraw[];
    __half* sWh = (__half*)smraw;
    __half* hHi = (__half*)(smraw + CR_OFF_HHI);
    __half* hLo = (__half*)(smraw + CR_OFF_HLO);
    float*  scr = (float*)(smraw + CR_OFF_SCR);
    float*  sbh = (float*)(smraw + CR_OFF_BH);
    const int tid = threadIdx.x;
    const int warp = tid >> 5, lane = tid & 31;
    const int wm = warp & 1, wj = warp >> 1;
    const int w0 = blockIdx.x * CR_M;
    float* myscr = scr + warp * 16 * CR_SC;

    {
        const uint4* s = (const uint4*)g_Wh16;
        uint4* d = (uint4*)sWh;
        for (int i = tid; i < G3C*WHS*2/16; i += 512) d[i] = s[i];
        uint32_t* hz = (uint32_t*)hHi;
        for (int i = tid; i < 2*CR_M*CR_HS/2; i += 512) hz[i] = 0u;
        if (tid < G3C) sbh[tid] = cbh[tid];
    }
    __syncthreads();

    for (int t = 0; t < LLC; t++) {
        wmma::fragment<wmma::accumulator, 16, 16, 16, float> acc[2][3];
        #pragma unroll
        for (int mi = 0; mi < 2; mi++)
            #pragma unroll
            for (int g = 0; g < 3; g++) wmma::fill_fragment(acc[mi][g], 0.f);

        #pragma unroll
        for (int kk = 0; kk < 8; kk++) {
            wmma::fragment<wmma::matrix_a, 16, 16, 16, __half, wmma::row_major> aH[2], aL[2];
            #pragma unroll
            for (int mi = 0; mi < 2; mi++) {
                wmma::load_matrix_sync(aH[mi], hHi + (wm*32 + mi*16)*CR_HS + kk*16, CR_HS);
                wmma::load_matrix_sync(aL[mi], hLo + (wm*32 + mi*16)*CR_HS + kk*16, CR_HS);
            }
            #pragma unroll
            for (int g = 0; g < 3; g++) {
                wmma::fragment<wmma::matrix_b, 16, 16, 16, __half, wmma::col_major> b;
                wmma::load_matrix_sync(b, sWh + (g*CHID + wj*16)*WHS + kk*16, WHS);
                #pragma unroll
                for (int mi = 0; mi < 2; mi++) {
                    wmma::mma_sync(acc[mi][g], aH[mi], b, acc[mi][g]);
                    wmma::mma_sync(acc[mi][g], aL[mi], b, acc[mi][g]);
                }
            }
        }
        __syncthreads();

        #pragma unroll
        for (int mi = 0; mi < 2; mi++) {
            #pragma unroll
            for (int g = 0; g < 3; g++)
                wmma::store_matrix_sync(myscr + g*16, acc[mi][g], CR_SC, wmma::mem_row_major);
            __syncwarp();
            #pragma unroll
            for (int q = 0; q < 8; q++) {
                int e = lane + 32*q;
                int row = e >> 4, jj = e & 15;
                int m = wm*32 + mi*16 + row;
                int j = wj*16 + jj;
                float pR = myscr[row*CR_SC + jj]      + sbh[j];
                float pZ = myscr[row*CR_SC + 16 + jj] + sbh[CHID + j];
                float pN = myscr[row*CR_SC + 32 + jj] + sbh[2*CHID + j];
                size_t rr = ((size_t)(w0 + m)*LLC + t)*G3C;
                float xr = g_cxw[rr + j];
                float xz = g_cxw[rr + CHID + j];
                float xn = g_cxw[rr + 2*CHID + j];
                float r  = 1.f / (1.f + expf(-(xr + pR)));
                float z  = 1.f / (1.f + expf(-(xz + pZ)));
                float nn = tanhf(xn + r*pN);
                float hp = __half2float(hHi[m*CR_HS + j]) + __half2float(hLo[m*CR_HS + j]);
                float hn = nn + z*(hp - nn);
                __half hh = __float2half(hn);
                hHi[m*CR_HS + j] = hh;
                hLo[m*CR_HS + j] = __float2half(hn - __half2float(hh));
            }
            __syncwarp();
        }
        __syncthreads();
    }

    #pragma unroll
    for (int mi = 0; mi < 2; mi++)
        #pragma unroll
        for (int q = 0; q < 8; q++) {
            int e = lane + 32*q;
            int row = e >> 4, jj = e & 15;
            int m = wm*32 + mi*16 + row;
            int j = wj*16 + jj;
            g_charh[(size_t)(w0 + m)*CHID + j] =
                __half2float(hHi[m*CR_HS + j]) + __half2float(hLo[m*CR_HS + j]);
        }
}

// ---------------- group barrier ----------------
__device__ __forceinline__ void group_barrier(int g) {
    __threadfence();
    __syncthreads();
    if (threadIdx.x == 0) {
        volatile unsigned int* vph = &g_barPh[g];
        unsigned int ph = *vph;
        unsigned int a = atomicAdd(&g_barA[g], 1u);
        if (a == 31u) {
            g_barA[g] = 0u;
            __threadfence();
            *vph = ph + 1u;
        } else {
            while (*vph == ph) { __nanosleep(20); }
        }
        __threadfence();
    }
    __syncthreads();
}

// ---------------- persistent word GRU (WMMA split-fp16, 4-way K-split) -------
#define WG_LDW 520
#define WG_LDH 520
#define WG_SC  52
#define WG_OFF_WHL  (48*WG_LDW*2)
#define WG_OFF_HH   (2*48*WG_LDW*2)
#define WG_OFF_HL   (WG_OFF_HH + 32*WG_LDH*2)
#define WG_OFF_PRE  (WG_OFF_HL + 32*WG_LDH*2)
#define WG_OFF_BH   (WG_OFF_PRE + 32*WG_SC*4)
#define WG_SMEM     (WG_OFF_BH + 48*4)

__global__ __launch_bounds__(256, 1)
void k_wordgru(const float* __restrict__ gbh) {
    extern __shared__ char smraw[];
    __half* sWhH = (__half*)smraw;                     // [48][520]
    __half* sWhL = (__half*)(smraw + WG_OFF_WHL);
    __half* sHh  = (__half*)(smraw + WG_OFF_HH);       // [32][520]
    __half* sHl  = (__half*)(smraw + WG_OFF_HL);
    float*  pre  = (float*)(smraw + WG_OFF_PRE);       // [32][52]
    float*  sbh  = (float*)(smraw + WG_OFF_BH);        // [48]
    const int tid = threadIdx.x;
    const int warp = tid >> 5;
    const int bid = blockIdx.x;
    const int mb = bid >> 5, jb = bid & 31;
    const int b0 = mb * 32, j0 = jb * 16;

    for (int i = tid; i < 48*64; i += 256) {
        int r = i >> 6, c8 = (i & 63) * 8;
        int gate = r >> 4, jj = r & 15;
        size_t src = (size_t)(gate*HID + j0 + jj) * HID + c8;
        *(uint4*)(sWhH + r*WG_LDW + c8) = *(const uint4*)(g_gWhH16 + src);
        *(uint4*)(sWhL + r*WG_LDW + c8) = *(const uint4*)(g_gWhL16 + src);
    }
    if (tid < 48) {
        int gate = tid >> 4, jj = tid & 15;
        sbh[tid] = gbh[gate*HID + j0 + jj];
    }
    for (int e = tid; e < 32*16; e += 256) {
        int m = e >> 4, jj = e & 15;
        int idx = (b0 + m)*HID + j0 + jj;
        g_h16H[idx] = __float2half(0.f);
        g_h16L[idx] = __float2half(0.f);
    }
    __syncthreads();
    group_barrier(mb);

    const int wmi = warp & 1, wni = warp >> 1;

    for (int s = 0; s < SSQ; s++) {
        // stage h (hi/lo) for this m-group from buffer s&1
        {
            const __half* srcH = g_h16H + (s & 1) * (BB*HID);
            const __half* srcL = g_h16L + (s & 1) * (BB*HID);
            for (int i = tid; i < 32*64; i += 256) {
                int r = i >> 6, c8 = (i & 63) * 8;
                size_t src = (size_t)(b0 + r) * HID + c8;
                *(uint4*)(sHh + r*WG_LDH + c8) = *(const uint4*)(srcH + src);
                *(uint4*)(sHl + r*WG_LDH + c8) = *(const uint4*)(srcL + src);
            }
        }
        __syncthreads();

        // prefetch this step's xw into registers (hides DRAM latency under MMA)
        float xr[2], xz[2], xn[2];
        #pragma unroll
        for (int q = 0; q < 2; q++) {
            int e = tid + 256*q;
            int m = e >> 4, jj = e & 15;
            size_t base = ((size_t)(b0 + m)*SSQ + s) * G3H;
            xr[q] = g_xw[base + j0 + jj];
            xz[q] = g_xw[base + HID + j0 + jj];
            xn[q] = g_xw[base + 2*HID + j0 + jj];
        }

        if (warp < 6) {
            // 4 independent accumulators (K split), k-index strided so the
            // instruction stream interleaves the 4 chains
            wmma::fragment<wmma::accumulator, 16, 16, 16, float> acc[4];
            #pragma unroll
            for (int q = 0; q < 4; q++) wmma::fill_fragment(acc[q], 0.f);
            #pragma unroll
            for (int kk = 0; kk < 8; kk++) {
                #pragma unroll
                for (int kq = 0; kq < 4; kq++) {
                    int k = kq*8 + kk;
                    wmma::fragment<wmma::matrix_a, 16, 16, 16, __half, wmma::row_major> aH, aL;
                    wmma::fragment<wmma::matrix_b, 16, 16, 16, __half, wmma::col_major> bH, bL;
                    wmma::load_matrix_sync(aH, sHh + (wmi*16)*WG_LDH + k*16, WG_LDH);
                    wmma::load_matrix_sync(aL, sHl + (wmi*16)*WG_LDH + k*16, WG_LDH);
                    wmma::load_matrix_sync(bH, sWhH + (wni*16)*WG_LDW + k*16, WG_LDW);
                    wmma::load_matrix_sync(bL, sWhL + (wni*16)*WG_LDW + k*16, WG_LDW);
                    wmma::mma_sync(acc[kq], aH, bH, acc[kq]);
                    wmma::mma_sync(acc[kq], aL, bH, acc[kq]);
                    wmma::mma_sync(acc[kq], aH, bL, acc[kq]);
                }
            }
            #pragma unroll
            for (int i = 0; i < acc[0].num_elements; i++)
                acc[0].x[i] += acc[1].x[i] + acc[2].x[i] + acc[3].x[i];
            wmma::store_matrix_sync(pre + (wmi*16)*WG_SC + wni*16, acc[0], WG_SC,
                                    wmma::mem_row_major);
        }
        __syncthreads();

        // gate update: 512 (m, jj) elements over 256 threads
        const int ob = (s + 1) & 1;
        #pragma unroll
        for (int q = 0; q < 2; q++) {
            int e = tid + 256*q;
            int m = e >> 4, jj = e & 15;
            int b = b0 + m, j = j0 + jj;
            float pR = pre[m*WG_SC + jj]      + sbh[jj];
            float pZ = pre[m*WG_SC + 16 + jj] + sbh[16 + jj];
            float pN = pre[m*WG_SC + 32 + jj] + sbh[32 + jj];
            float r  = 1.f / (1.f + expf(-(xr[q] + pR)));
            float z  = 1.f / (1.f + expf(-(xz[q] + pZ)));
            float nn = tanhf(xn[q] + r*pN);
            float hp = __half2float(sHh[m*WG_LDH + j]) + __half2float(sHl[m*WG_LDH + j]);
            float hn = nn + z*(hp - nn);
            g_gruout[((size_t)b*SSQ + s)*HID + j] = hn;
            __half hh = __float2half(hn);
            int idx = ob*(BB*HID) + b*HID + j;
            g_h16H[idx] = hh;
            g_h16L[idx] = __float2half(hn - __half2float(hh));
        }
        if (s == SSQ - 1) break;
        group_barrier(mb);
    }
}

// ---------------- classifier ----------------
__global__ __launch_bounds__(256)
void k_cls(const float* __restrict__ clsW, const float* __restrict__ clsb,
           float* __restrict__ out) {
    const int warp = threadIdx.x >> 5, lane = threadIdx.x & 31;
    const int gw = blockIdx.x * 8 + warp;
    for (int row = gw; row < NW; row += gridDim.x * 8) {
        const float* hrow = g_gruout + (size_t)row * HID;
        float acc[NCLS];
        #pragma unroll
        for (int c = 0; c < NCLS; c++) acc[c] = 0.f;
        for (int k = lane; k < HID; k += 32) {
            float hv = hrow[k];
            #pragma unroll
            for (int c = 0; c < NCLS; c++)
                acc[c] = fmaf(hv, clsW[c*HID + k], acc[c]);
        }
        #pragma unroll
        for (int off = 16; off > 0; off >>= 1) {
            #pragma unroll
            for (int c = 0; c < NCLS; c++)
                acc[c] += __shfl_down_sync(0xffffffffu, acc[c], off);
        }
        if (lane == 0) {
            #pragma unroll
            for (int c = 0; c < NCLS; c++)
                out[(size_t)row*NCLS + c] = acc[c] + clsb[c];
        }
    }
}

// ---------------- launch ----------------
extern "C" void kernel_launch(void* const* d_in, const int* in_sizes, int n_in,
                              void* d_out, int out_size) {
    const int*   x     = (const int*)  d_in[0];
    const int*   xch   = (const int*)  d_in[1];
    const float* embw  = (const float*)d_in[2];
    const float* cembw = (const float*)d_in[3];
    const float* cWi   = (const float*)d_in[4];
    const float* cWh   = (const float*)d_in[5];
    const float* cbi   = (const float*)d_in[6];
    const float* cbh   = (const float*)d_in[7];
    const float* gWi   = (const float*)d_in[8];
    const float* gWh   = (const float*)d_in[9];
    const float* gbi   = (const float*)d_in[10];
    const float* gbh   = (const float*)d_in[11];
    const float* clsW  = (const float*)d_in[12];
    const float* clsb  = (const float*)d_in[13];
    float* out = (float*)d_out;

    void *aCh, *aCl, *aXh, *aXl, *bCh, *bCl, *bXh, *bXl;
    cudaGetSymbolAddress(&aCh, g_AcH);  cudaGetSymbolAddress(&aCl, g_AcL);
    cudaGetSymbolAddress(&aXh, g_AxH);  cudaGetSymbolAddress(&aXl, g_AxL);
    cudaGetSymbolAddress(&bCh, g_BcxHi); cudaGetSymbolAddress(&bCl, g_BcxLo);
    cudaGetSymbolAddress(&bXh, g_BxwHi); cudaGetSymbolAddress(&bXl, g_BxwLo);
    void *pcxw, *pxw;
    cudaGetSymbolAddress(&pcxw, g_cxw);
    cudaGetSymbolAddress(&pxw, g_xw);

    cudaFuncSetAttribute(k_charrec, cudaFuncAttributeMaxDynamicSharedMemorySize, CR_SMEM);
    cudaFuncSetAttribute(k_wordgru, cudaFuncAttributeMaxDynamicSharedMemorySize, WG_SMEM);
    cudaFuncSetAttribute(k_gemm,    cudaFuncAttributeMaxDynamicSharedMemorySize, GEMM_SMEM);

    k_prep<<<512, 256>>>(cWh, gWi, cWi, gWh);
    k_gatherA_c<<<NW*LLC/256, 256>>>(xch, cembw);
    dim3 gc(G3C/64, NW*LLC/128);   // (6, 4096)
    k_gemm<<<gc, 256, GEMM_SMEM>>>((const __nv_bfloat16*)aCh, (const __nv_bfloat16*)aCl,
                                   (const __nv_bfloat16*)bCh, (const __nv_bfloat16*)bCl,
                                   cbi, (float*)pcxw, G3C, CEMB);
    k_charrec<<<NW/CR_M, 512, CR_SMEM>>>(cbh);
    k_gatherA_x<<<NW/8, 256>>>(x, embw);
    dim3 gx(G3H/64, NW/128);       // (24, 256)
    k_gemm<<<gx, 256, GEMM_SMEM>>>((const __nv_bfloat16*)aXh, (const __nv_bfloat16*)aXl,
                                   (const __nv_bfloat16*)bXh, (const __nv_bfloat16*)bXl,
                                   gbi, (float*)pxw, G3H, DIM);
    k_wordgru<<<NBLK_W, 256, WG_SMEM>>>(gbh);
    k_cls<<<512, 256>>>(clsW, clsb, out);
}

// round 14
// speedup vs baseline: 2.9938x; 1.3422x over previous
#include <cuda_runtime.h>
#include <cuda_bf16.h>
#include <cuda_fp16.h>
#include <mma.h>
#include <cstdint>
#include <math.h>

using namespace nvcuda;

#define BB    128
#define SSQ   256
#define LLC   16
#define EMB   256
#define HID   512
#define NCLS  20
#define CEMB  64
#define CHID  128
#define NW    (BB*SSQ)        // 32768 words
#define DIM   384             // EMB + CHID
#define G3C   384             // 3*CHID
#define G3H   1536            // 3*HID
#define NBLK_W 128

// ---------------- scratch (__device__ globals, no allocation) ----------------
__device__ float g_cxw[(size_t)NW*LLC*G3C];       // char input projections
__device__ float g_charh[NW*CHID];                // char GRU final hidden (n = s*B+b)
__device__ float g_xw[(size_t)NW*G3H];            // word input projections
__device__ float g_gruout[(size_t)NW*HID];
__device__ unsigned int g_barA[4];
__device__ unsigned int g_barPh[4];
// fp16 feed-forward weights (row-major [N][K])
__device__ __half g_Bxw16[G3H*DIM];
__device__ __half g_Bcx16[G3C*CEMB];
// char Wh in fp16, padded [384][136]
#define WHS 136
__device__ __half g_Wh16[G3C*WHS];
// word Wh split-fp16 images [1536][512]
__device__ __half g_gWhH16[G3H*HID], g_gWhL16[G3H*HID];
// word GRU hidden state, split-fp16, double buffered
__device__ __half g_h16H[2*BB*HID], g_h16L[2*BB*HID];
// fp16 gathered A matrices
__device__ __half g_Ac16[(size_t)NW*LLC*CEMB];
__device__ __half g_Ax16[(size_t)NW*DIM];

// ---------------- helpers ----------------
__device__ __forceinline__ uint2 cvt4h(float4 v) {
    union { __half2 h; uint32_t u; } a, b;
    a.h = __floats2half2_rn(v.x, v.y);
    b.h = __floats2half2_rn(v.z, v.w);
    return make_uint2(a.u, b.u);
}
__device__ __forceinline__ float fsig(float x) {
    return __fdividef(1.f, 1.f + __expf(-x));
}

// ---------------- kernel P: weight prep ----------------
__global__ void k_prep(const float* __restrict__ cWh, const float* __restrict__ gWi,
                       const float* __restrict__ cWi, const float* __restrict__ gWh) {
    int stride = gridDim.x * blockDim.x;
    int i0 = blockIdx.x * blockDim.x + threadIdx.x;
    for (int i = i0; i < G3C*WHS; i += stride) {
        int n = i / WHS, k = i % WHS;
        g_Wh16[i] = (k < CHID) ? __float2half(cWh[n*CHID + k]) : __float2half(0.f);
    }
    for (int i = i0; i < G3H*HID; i += stride) {
        float v = gWh[i];
        __half h = __float2half(v);
        g_gWhH16[i] = h;
        g_gWhL16[i] = __float2half(v - __half2float(h));
    }
    for (int i = i0; i < G3H*DIM; i += stride)
        g_Bxw16[i] = __float2half(gWi[i]);
    for (int i = i0; i < G3C*CEMB; i += stride)
        g_Bcx16[i] = __float2half(cWi[i]);
}

// ---------------- gather A for char GEMM (fp16) ----------------
__global__ __launch_bounds__(256)
void k_gatherA_c(const int* __restrict__ xc, const float* __restrict__ cembw) {
    const int r = blockIdx.x * 256 + threadIdx.x;
    const int c = xc[r];
    const float4* src = (const float4*)(cembw + (size_t)c * CEMB);
    uint2* dst = (uint2*)(g_Ac16 + (size_t)r * CEMB);
    #pragma unroll
    for (int i = 0; i < 16; i++) dst[i] = cvt4h(src[i]);
}

// ---------------- gather A for word GEMM (fp16) ----------------
__global__ __launch_bounds__(256)
void k_gatherA_x(const int* __restrict__ xtok, const float* __restrict__ embw) {
    const int warp = threadIdx.x >> 5, lane = threadIdx.x & 31;
    const int row = blockIdx.x * 8 + warp;
    const int tok = xtok[row];
    const int nidx = (row & 255) * 128 + (row >> 8);
    uint2* dst = (uint2*)(g_Ax16 + (size_t)row * DIM);
    #pragma unroll
    for (int q = 0; q < 3; q++) {
        int k4 = q * 32 + lane;
        int k = k4 * 4;
        float4 v = (k < EMB)
            ? *(const float4*)(embw + (size_t)tok * EMB + k)
            : *(const float4*)(g_charh + (size_t)nidx * CHID + (k - EMB));
        dst[k4] = cvt4h(v);
    }
}

// ---------------- wmma fp16 GEMM: C = A·B^T + bias ---------------------------
#define GPAD 72
#define GSM_A  (128*GPAD)                 // halves
#define GSM_B  (64*GPAD)
#define GEMM_SMEM (128*68*4)              // epilogue fp32 dominates: 34816 B

__global__ __launch_bounds__(256)
void k_gemm(const __half* __restrict__ A, const __half* __restrict__ B,
            const float* __restrict__ bias, float* __restrict__ C,
            int N, int K) {
    extern __shared__ char smraw[];
    __half* sA = (__half*)smraw;
    __half* sB = sA + GSM_A;
    float* sC = (float*)smraw;            // reused in epilogue

    const int tid = threadIdx.x;
    const int warp = tid >> 5;
    const int wm = warp & 3, wn = warp >> 2;
    const int bm = blockIdx.y * 128, bn = blockIdx.x * 64;

    wmma::fragment<wmma::accumulator, 16, 16, 16, float> acc[2][2];
    #pragma unroll
    for (int i = 0; i < 2; i++)
        #pragma unroll
        for (int j = 0; j < 2; j++) wmma::fill_fragment(acc[i][j], 0.f);

    for (int k0 = 0; k0 < K; k0 += 64) {
        // A: 128 rows x 8 uint4 (64 halves); 4 uint4/thread
        #pragma unroll
        for (int q = 0; q < 4; q++) {
            int j = tid * 4 + q;
            int r = j >> 3, c8 = j & 7;
            *(uint4*)(sA + r*GPAD + c8*8) =
                *(const uint4*)(A + (size_t)(bm + r) * K + k0 + c8*8);
        }
        // B: 64 rows x 8 uint4; 2 uint4/thread
        #pragma unroll
        for (int q = 0; q < 2; q++) {
            int j = tid * 2 + q;
            int r = j >> 3, c8 = j & 7;
            *(uint4*)(sB + r*GPAD + c8*8) =
                *(const uint4*)(B + (size_t)(bn + r) * K + k0 + c8*8);
        }
        __syncthreads();

        #pragma unroll
        for (int kk = 0; kk < 4; kk++) {
            wmma::fragment<wmma::matrix_a, 16, 16, 16, __half, wmma::row_major> a[2];
            wmma::fragment<wmma::matrix_b, 16, 16, 16, __half, wmma::col_major> b[2];
            #pragma unroll
            for (int mi = 0; mi < 2; mi++)
                wmma::load_matrix_sync(a[mi], sA + (wm*32 + mi*16)*GPAD + kk*16, GPAD);
            #pragma unroll
            for (int ni = 0; ni < 2; ni++)
                wmma::load_matrix_sync(b[ni], sB + (wn*32 + ni*16)*GPAD + kk*16, GPAD);
            #pragma unroll
            for (int mi = 0; mi < 2; mi++)
                #pragma unroll
                for (int ni = 0; ni < 2; ni++)
                    wmma::mma_sync(acc[mi][ni], a[mi], b[ni], acc[mi][ni]);
        }
        __syncthreads();
    }

    #pragma unroll
    for (int mi = 0; mi < 2; mi++)
        #pragma unroll
        for (int ni = 0; ni < 2; ni++)
            wmma::store_matrix_sync(sC + (wm*32 + mi*16)*68 + wn*32 + ni*16,
                                    acc[mi][ni], 68, wmma::mem_row_major);
    __syncthreads();
    #pragma unroll
    for (int q = 0; q < 8; q++) {
        int j = q * 256 + tid;
        int r = j >> 4, c4 = (j & 15) * 4;
        float4 v = *(float4*)(sC + r*68 + c4);
        float4 b = *(const float4*)(bias + bn + c4);
        v.x += b.x; v.y += b.y; v.z += b.z; v.w += b.w;
        *(float4*)(C + (size_t)(bm + r) * N + bn + c4) = v;
    }
}

// ---------------- kernel CR: char GRU recurrent (WMMA fp16 Wh, split-fp16 h) -
#define CR_M   64
#define CR_HS  136
#define CR_SC  52
#define CR_OFF_HHI  (G3C*WHS*2)
#define CR_OFF_HLO  (CR_OFF_HHI + CR_M*CR_HS*2)
#define CR_OFF_SCR  (CR_OFF_HLO + CR_M*CR_HS*2)
#define CR_OFF_BH   (CR_OFF_SCR + 16*16*CR_SC*4)
#define CR_SMEM     (CR_OFF_BH + G3C*4)

__global__ __launch_bounds__(512, 1)
void k_charrec(const float* __restrict__ cbh) {
    extern __shared__ char smraw[];
    __half* sWh = (__half*)smraw;
    __half* hHi = (__half*)(smraw + CR_OFF_HHI);
    __half* hLo = (__half*)(smraw + CR_OFF_HLO);
    float*  scr = (float*)(smraw + CR_OFF_SCR);
    float*  sbh = (float*)(smraw + CR_OFF_BH);
    const int tid = threadIdx.x;
    const int warp = tid >> 5, lane = tid & 31;
    const int wm = warp & 1, wj = warp >> 1;
    const int w0 = blockIdx.x * CR_M;
    float* myscr = scr + warp * 16 * CR_SC;

    {
        const uint4* s = (const uint4*)g_Wh16;
        uint4* d = (uint4*)sWh;
        for (int i = tid; i < G3C*WHS*2/16; i += 512) d[i] = s[i];
        uint32_t* hz = (uint32_t*)hHi;
        for (int i = tid; i < 2*CR_M*CR_HS/2; i += 512) hz[i] = 0u;
        if (tid < G3C) sbh[tid] = cbh[tid];
    }
    __syncthreads();

    for (int t = 0; t < LLC; t++) {
        wmma::fragment<wmma::accumulator, 16, 16, 16, float> acc[2][3];
        #pragma unroll
        for (int mi = 0; mi < 2; mi++)
            #pragma unroll
            for (int g = 0; g < 3; g++) wmma::fill_fragment(acc[mi][g], 0.f);

        #pragma unroll
        for (int kk = 0; kk < 8; kk++) {
            wmma::fragment<wmma::matrix_a, 16, 16, 16, __half, wmma::row_major> aH[2], aL[2];
            #pragma unroll
            for (int mi = 0; mi < 2; mi++) {
                wmma::load_matrix_sync(aH[mi], hHi + (wm*32 + mi*16)*CR_HS + kk*16, CR_HS);
                wmma::load_matrix_sync(aL[mi], hLo + (wm*32 + mi*16)*CR_HS + kk*16, CR_HS);
            }
            #pragma unroll
            for (int g = 0; g < 3; g++) {
                wmma::fragment<wmma::matrix_b, 16, 16, 16, __half, wmma::col_major> b;
                wmma::load_matrix_sync(b, sWh + (g*CHID + wj*16)*WHS + kk*16, WHS);
                #pragma unroll
                for (int mi = 0; mi < 2; mi++) {
                    wmma::mma_sync(acc[mi][g], aH[mi], b, acc[mi][g]);
                    wmma::mma_sync(acc[mi][g], aL[mi], b, acc[mi][g]);
                }
            }
        }
        __syncthreads();

        #pragma unroll
        for (int mi = 0; mi < 2; mi++) {
            #pragma unroll
            for (int g = 0; g < 3; g++)
                wmma::store_matrix_sync(myscr + g*16, acc[mi][g], CR_SC, wmma::mem_row_major);
            __syncwarp();
            #pragma unroll
            for (int q = 0; q < 8; q++) {
                int e = lane + 32*q;
                int row = e >> 4, jj = e & 15;
                int m = wm*32 + mi*16 + row;
                int j = wj*16 + jj;
                float pR = myscr[row*CR_SC + jj]      + sbh[j];
                float pZ = myscr[row*CR_SC + 16 + jj] + sbh[CHID + j];
                float pN = myscr[row*CR_SC + 32 + jj] + sbh[2*CHID + j];
                size_t rr = ((size_t)(w0 + m)*LLC + t)*G3C;
                float xr = g_cxw[rr + j];
                float xz = g_cxw[rr + CHID + j];
                float xn = g_cxw[rr + 2*CHID + j];
                float r  = fsig(xr + pR);
                float z  = fsig(xz + pZ);
                float nn = tanhf(xn + r*pN);
                float hp = __half2float(hHi[m*CR_HS + j]) + __half2float(hLo[m*CR_HS + j]);
                float hn = nn + z*(hp - nn);
                __half hh = __float2half(hn);
                hHi[m*CR_HS + j] = hh;
                hLo[m*CR_HS + j] = __float2half(hn - __half2float(hh));
            }
            __syncwarp();
        }
        __syncthreads();
    }

    #pragma unroll
    for (int mi = 0; mi < 2; mi++)
        #pragma unroll
        for (int q = 0; q < 8; q++) {
            int e = lane + 32*q;
            int row = e >> 4, jj = e & 15;
            int m = wm*32 + mi*16 + row;
            int j = wj*16 + jj;
            g_charh[(size_t)(w0 + m)*CHID + j] =
                __half2float(hHi[m*CR_HS + j]) + __half2float(hLo[m*CR_HS + j]);
        }
}

// ---------------- group barrier ----------------
__device__ __forceinline__ void group_barrier(int g) {
    __threadfence();
    __syncthreads();
    if (threadIdx.x == 0) {
        volatile unsigned int* vph = &g_barPh[g];
        unsigned int ph = *vph;
        unsigned int a = atomicAdd(&g_barA[g], 1u);
        if (a == 31u) {
            g_barA[g] = 0u;
            __threadfence();
            *vph = ph + 1u;
        } else {
            while (*vph == ph) { __nanosleep(20); }
        }
        __threadfence();
    }
    __syncthreads();
}

// ---------------- persistent word GRU (WMMA split-fp16, 4-way K-split) -------
#define WG_LDW 520
#define WG_LDH 520
#define WG_SC  52
#define WG_OFF_WHL  (48*WG_LDW*2)
#define WG_OFF_HH   (2*48*WG_LDW*2)
#define WG_OFF_HL   (WG_OFF_HH + 32*WG_LDH*2)
#define WG_OFF_PRE  (WG_OFF_HL + 32*WG_LDH*2)
#define WG_OFF_BH   (WG_OFF_PRE + 32*WG_SC*4)
#define WG_SMEM     (WG_OFF_BH + 48*4)

__global__ __launch_bounds__(256, 1)
void k_wordgru(const float* __restrict__ gbh) {
    extern __shared__ char smraw[];
    __half* sWhH = (__half*)smraw;
    __half* sWhL = (__half*)(smraw + WG_OFF_WHL);
    __half* sHh  = (__half*)(smraw + WG_OFF_HH);
    __half* sHl  = (__half*)(smraw + WG_OFF_HL);
    float*  pre  = (float*)(smraw + WG_OFF_PRE);
    float*  sbh  = (float*)(smraw + WG_OFF_BH);
    const int tid = threadIdx.x;
    const int warp = tid >> 5;
    const int bid = blockIdx.x;
    const int mb = bid >> 5, jb = bid & 31;
    const int b0 = mb * 32, j0 = jb * 16;

    for (int i = tid; i < 48*64; i += 256) {
        int r = i >> 6, c8 = (i & 63) * 8;
        int gate = r >> 4, jj = r & 15;
        size_t src = (size_t)(gate*HID + j0 + jj) * HID + c8;
        *(uint4*)(sWhH + r*WG_LDW + c8) = *(const uint4*)(g_gWhH16 + src);
        *(uint4*)(sWhL + r*WG_LDW + c8) = *(const uint4*)(g_gWhL16 + src);
    }
    if (tid < 48) {
        int gate = tid >> 4, jj = tid & 15;
        sbh[tid] = gbh[gate*HID + j0 + jj];
    }
    for (int e = tid; e < 32*16; e += 256) {
        int m = e >> 4, jj = e & 15;
        int idx = (b0 + m)*HID + j0 + jj;
        g_h16H[idx] = __float2half(0.f);
        g_h16L[idx] = __float2half(0.f);
    }
    __syncthreads();
    group_barrier(mb);

    const int wmi = warp & 1, wni = warp >> 1;

    for (int s = 0; s < SSQ; s++) {
        {
            const __half* srcH = g_h16H + (s & 1) * (BB*HID);
            const __half* srcL = g_h16L + (s & 1) * (BB*HID);
            for (int i = tid; i < 32*64; i += 256) {
                int r = i >> 6, c8 = (i & 63) * 8;
                size_t src = (size_t)(b0 + r) * HID + c8;
                *(uint4*)(sHh + r*WG_LDH + c8) = *(const uint4*)(srcH + src);
                *(uint4*)(sHl + r*WG_LDH + c8) = *(const uint4*)(srcL + src);
            }
        }
        __syncthreads();

        float xr[2], xz[2], xn[2];
        #pragma unroll
        for (int q = 0; q < 2; q++) {
            int e = tid + 256*q;
            int m = e >> 4, jj = e & 15;
            size_t base = ((size_t)(b0 + m)*SSQ + s) * G3H;
            xr[q] = g_xw[base + j0 + jj];
            xz[q] = g_xw[base + HID + j0 + jj];
            xn[q] = g_xw[base + 2*HID + j0 + jj];
        }

        if (warp < 6) {
            wmma::fragment<wmma::accumulator, 16, 16, 16, float> acc[4];
            #pragma unroll
            for (int q = 0; q < 4; q++) wmma::fill_fragment(acc[q], 0.f);
            #pragma unroll
            for (int kk = 0; kk < 8; kk++) {
                #pragma unroll
                for (int kq = 0; kq < 4; kq++) {
                    int k = kq*8 + kk;
                    wmma::fragment<wmma::matrix_a, 16, 16, 16, __half, wmma::row_major> aH, aL;
                    wmma::fragment<wmma::matrix_b, 16, 16, 16, __half, wmma::col_major> bH, bL;
                    wmma::load_matrix_sync(aH, sHh + (wmi*16)*WG_LDH + k*16, WG_LDH);
                    wmma::load_matrix_sync(aL, sHl + (wmi*16)*WG_LDH + k*16, WG_LDH);
                    wmma::load_matrix_sync(bH, sWhH + (wni*16)*WG_LDW + k*16, WG_LDW);
                    wmma::load_matrix_sync(bL, sWhL + (wni*16)*WG_LDW + k*16, WG_LDW);
                    wmma::mma_sync(acc[kq], aH, bH, acc[kq]);
                    wmma::mma_sync(acc[kq], aL, bH, acc[kq]);
                    wmma::mma_sync(acc[kq], aH, bL, acc[kq]);
                }
            }
            #pragma unroll
            for (int i = 0; i < acc[0].num_elements; i++)
                acc[0].x[i] += acc[1].x[i] + acc[2].x[i] + acc[3].x[i];
            wmma::store_matrix_sync(pre + (wmi*16)*WG_SC + wni*16, acc[0], WG_SC,
                                    wmma::mem_row_major);
        }
        __syncthreads();

        const int ob = (s + 1) & 1;
        #pragma unroll
        for (int q = 0; q < 2; q++) {
            int e = tid + 256*q;
            int m = e >> 4, jj = e & 15;
            int b = b0 + m, j = j0 + jj;
            float pR = pre[m*WG_SC + jj]      + sbh[jj];
            float pZ = pre[m*WG_SC + 16 + jj] + sbh[16 + jj];
            float pN = pre[m*WG_SC + 32 + jj] + sbh[32 + jj];
            float r  = fsig(xr[q] + pR);
            float z  = fsig(xz[q] + pZ);
            float nn = tanhf(xn[q] + r*pN);
            float hp = __half2float(sHh[m*WG_LDH + j]) + __half2float(sHl[m*WG_LDH + j]);
            float hn = nn + z*(hp - nn);
            g_gruout[((size_t)b*SSQ + s)*HID + j] = hn;
            __half hh = __float2half(hn);
            int idx = ob*(BB*HID) + b*HID + j;
            g_h16H[idx] = hh;
            g_h16L[idx] = __float2half(hn - __half2float(hh));
        }
        if (s == SSQ - 1) break;
        group_barrier(mb);
    }
}

// ---------------- classifier ----------------
__global__ __launch_bounds__(256)
void k_cls(const float* __restrict__ clsW, const float* __restrict__ clsb,
           float* __restrict__ out) {
    const int warp = threadIdx.x >> 5, lane = threadIdx.x & 31;
    const int gw = blockIdx.x * 8 + warp;
    for (int row = gw; row < NW; row += gridDim.x * 8) {
        const float* hrow = g_gruout + (size_t)row * HID;
        float acc[NCLS];
        #pragma unroll
        for (int c = 0; c < NCLS; c++) acc[c] = 0.f;
        for (int k = lane; k < HID; k += 32) {
            float hv = hrow[k];
            #pragma unroll
            for (int c = 0; c < NCLS; c++)
                acc[c] = fmaf(hv, clsW[c*HID + k], acc[c]);
        }
        #pragma unroll
        for (int off = 16; off > 0; off >>= 1) {
            #pragma unroll
            for (int c = 0; c < NCLS; c++)
                acc[c] += __shfl_down_sync(0xffffffffu, acc[c], off);
        }
        if (lane == 0) {
            #pragma unroll
            for (int c = 0; c < NCLS; c++)
                out[(size_t)row*NCLS + c] = acc[c] + clsb[c];
        }
    }
}

// ---------------- launch ----------------
extern "C" void kernel_launch(void* const* d_in, const int* in_sizes, int n_in,
                              void* d_out, int out_size) {
    const int*   x     = (const int*)  d_in[0];
    const int*   xch   = (const int*)  d_in[1];
    const float* embw  = (const float*)d_in[2];
    const float* cembw = (const float*)d_in[3];
    const float* cWi   = (const float*)d_in[4];
    const float* cWh   = (const float*)d_in[5];
    const float* cbi   = (const float*)d_in[6];
    const float* cbh   = (const float*)d_in[7];
    const float* gWi   = (const float*)d_in[8];
    const float* gWh   = (const float*)d_in[9];
    const float* gbi   = (const float*)d_in[10];
    const float* gbh   = (const float*)d_in[11];
    const float* clsW  = (const float*)d_in[12];
    const float* clsb  = (const float*)d_in[13];
    float* out = (float*)d_out;

    void *aC16, *aX16, *bC16, *bX16, *pcxw, *pxw;
    cudaGetSymbolAddress(&aC16, g_Ac16);
    cudaGetSymbolAddress(&aX16, g_Ax16);
    cudaGetSymbolAddress(&bC16, g_Bcx16);
    cudaGetSymbolAddress(&bX16, g_Bxw16);
    cudaGetSymbolAddress(&pcxw, g_cxw);
    cudaGetSymbolAddress(&pxw, g_xw);

    cudaFuncSetAttribute(k_charrec, cudaFuncAttributeMaxDynamicSharedMemorySize, CR_SMEM);
    cudaFuncSetAttribute(k_wordgru, cudaFuncAttributeMaxDynamicSharedMemorySize, WG_SMEM);
    cudaFuncSetAttribute(k_gemm,    cudaFuncAttributeMaxDynamicSharedMemorySize, GEMM_SMEM);

    k_prep<<<512, 256>>>(cWh, gWi, cWi, gWh);
    k_gatherA_c<<<NW*LLC/256, 256>>>(xch, cembw);
    dim3 gc(G3C/64, NW*LLC/128);   // (6, 4096)
    k_gemm<<<gc, 256, GEMM_SMEM>>>((const __half*)aC16, (const __half*)bC16,
                                   cbi, (float*)pcxw, G3C, CEMB);
    k_charrec<<<NW/CR_M, 512, CR_SMEM>>>(cbh);
    k_gatherA_x<<<NW/8, 256>>>(x, embw);
    dim3 gx(G3H/64, NW/128);       // (24, 256)
    k_gemm<<<gx, 256, GEMM_SMEM>>>((const __half*)aX16, (const __half*)bX16,
                                   gbi, (float*)pxw, G3H, DIM);
    k_wordgru<<<NBLK_W, 256, WG_SMEM>>>(gbh);
    k_cls<<<512, 256>>>(clsW, clsb, out);
}

// round 15
// speedup vs baseline: 3.2000x; 1.0689x over previous
#include <cuda_runtime.h>
#include <cuda_bf16.h>
#include <cuda_fp16.h>
#include <mma.h>
#include <cstdint>
#include <math.h>

using namespace nvcuda;

#define BB    128
#define SSQ   256
#define LLC   16
#define EMB   256
#define HID   512
#define NCLS  20
#define CEMB  64
#define CHID  128
#define NW    (BB*SSQ)        // 32768 words
#define DIM   384             // EMB + CHID
#define G3C   384             // 3*CHID
#define G3H   1536            // 3*HID
#define NBLK_W 128

// ---------------- scratch (__device__ globals, no allocation) ----------------
__device__ __half g_cxw16[(size_t)NW*LLC*G3C];    // char input projections (fp16)
__device__ float g_charh[NW*CHID];                // char GRU final hidden (n = s*B+b)
__device__ __half g_xw16[(size_t)NW*G3H];         // word input projections (fp16)
__device__ float g_gruout[(size_t)NW*HID];
__device__ unsigned int g_barA[4];
__device__ unsigned int g_barPh[4];
// fp16 feed-forward weights (row-major [N][K])
__device__ __half g_Bxw16[G3H*DIM];
__device__ __half g_Bcx16[G3C*CEMB];
// char Wh in fp16, padded [384][136]
#define WHS 136
__device__ __half g_Wh16[G3C*WHS];
// word Wh fp16 image [1536][512]
__device__ __half g_gWh16[G3H*HID];
// word GRU hidden state, split-fp16, double buffered
__device__ __half g_h16H[2*BB*HID], g_h16L[2*BB*HID];
// fp16 gathered A matrices
__device__ __half g_Ac16[(size_t)NW*LLC*CEMB];
__device__ __half g_Ax16[(size_t)NW*DIM];

// ---------------- helpers ----------------
__device__ __forceinline__ uint2 cvt4h(float4 v) {
    union { __half2 h; uint32_t u; } a, b;
    a.h = __floats2half2_rn(v.x, v.y);
    b.h = __floats2half2_rn(v.z, v.w);
    return make_uint2(a.u, b.u);
}
__device__ __forceinline__ float fsig(float x) {
    return __fdividef(1.f, 1.f + __expf(-x));
}

// ---------------- kernel P: weight prep ----------------
__global__ void k_prep(const float* __restrict__ cWh, const float* __restrict__ gWi,
                       const float* __restrict__ cWi, const float* __restrict__ gWh) {
    int stride = gridDim.x * blockDim.x;
    int i0 = blockIdx.x * blockDim.x + threadIdx.x;
    for (int i = i0; i < G3C*WHS; i += stride) {
        int n = i / WHS, k = i % WHS;
        g_Wh16[i] = (k < CHID) ? __float2half(cWh[n*CHID + k]) : __float2half(0.f);
    }
    for (int i = i0; i < G3H*HID; i += stride)
        g_gWh16[i] = __float2half(gWh[i]);
    for (int i = i0; i < G3H*DIM; i += stride)
        g_Bxw16[i] = __float2half(gWi[i]);
    for (int i = i0; i < G3C*CEMB; i += stride)
        g_Bcx16[i] = __float2half(cWi[i]);
}

// ---------------- gather A for char GEMM (fp16) ----------------
__global__ __launch_bounds__(256)
void k_gatherA_c(const int* __restrict__ xc, const float* __restrict__ cembw) {
    const int r = blockIdx.x * 256 + threadIdx.x;
    const int c = xc[r];
    const float4* src = (const float4*)(cembw + (size_t)c * CEMB);
    uint2* dst = (uint2*)(g_Ac16 + (size_t)r * CEMB);
    #pragma unroll
    for (int i = 0; i < 16; i++) dst[i] = cvt4h(src[i]);
}

// ---------------- gather A for word GEMM (fp16) ----------------
__global__ __launch_bounds__(256)
void k_gatherA_x(const int* __restrict__ xtok, const float* __restrict__ embw) {
    const int warp = threadIdx.x >> 5, lane = threadIdx.x & 31;
    const int row = blockIdx.x * 8 + warp;
    const int tok = xtok[row];
    const int nidx = (row & 255) * 128 + (row >> 8);
    uint2* dst = (uint2*)(g_Ax16 + (size_t)row * DIM);
    #pragma unroll
    for (int q = 0; q < 3; q++) {
        int k4 = q * 32 + lane;
        int k = k4 * 4;
        float4 v = (k < EMB)
            ? *(const float4*)(embw + (size_t)tok * EMB + k)
            : *(const float4*)(g_charh + (size_t)nidx * CHID + (k - EMB));
        dst[k4] = cvt4h(v);
    }
}

// ---------------- wmma fp16 GEMM: C16 = A·B^T + bias -------------------------
#define GPAD 72
#define GSM_A  (128*GPAD)                 // halves
#define GSM_B  (64*GPAD)
#define GEMM_SMEM (128*68*4)              // epilogue fp32 dominates: 34816 B

__global__ __launch_bounds__(256)
void k_gemm(const __half* __restrict__ A, const __half* __restrict__ B,
            const float* __restrict__ bias, __half* __restrict__ C,
            int N, int K) {
    extern __shared__ char smraw[];
    __half* sA = (__half*)smraw;
    __half* sB = sA + GSM_A;
    float* sC = (float*)smraw;            // reused in epilogue

    const int tid = threadIdx.x;
    const int warp = tid >> 5;
    const int wm = warp & 3, wn = warp >> 2;
    const int bm = blockIdx.y * 128, bn = blockIdx.x * 64;

    wmma::fragment<wmma::accumulator, 16, 16, 16, float> acc[2][2];
    #pragma unroll
    for (int i = 0; i < 2; i++)
        #pragma unroll
        for (int j = 0; j < 2; j++) wmma::fill_fragment(acc[i][j], 0.f);

    for (int k0 = 0; k0 < K; k0 += 64) {
        #pragma unroll
        for (int q = 0; q < 4; q++) {
            int j = tid * 4 + q;
            int r = j >> 3, c8 = j & 7;
            *(uint4*)(sA + r*GPAD + c8*8) =
                *(const uint4*)(A + (size_t)(bm + r) * K + k0 + c8*8);
        }
        #pragma unroll
        for (int q = 0; q < 2; q++) {
            int j = tid * 2 + q;
            int r = j >> 3, c8 = j & 7;
            *(uint4*)(sB + r*GPAD + c8*8) =
                *(const uint4*)(B + (size_t)(bn + r) * K + k0 + c8*8);
        }
        __syncthreads();

        #pragma unroll
        for (int kk = 0; kk < 4; kk++) {
            wmma::fragment<wmma::matrix_a, 16, 16, 16, __half, wmma::row_major> a[2];
            wmma::fragment<wmma::matrix_b, 16, 16, 16, __half, wmma::col_major> b[2];
            #pragma unroll
            for (int mi = 0; mi < 2; mi++)
                wmma::load_matrix_sync(a[mi], sA + (wm*32 + mi*16)*GPAD + kk*16, GPAD);
            #pragma unroll
            for (int ni = 0; ni < 2; ni++)
                wmma::load_matrix_sync(b[ni], sB + (wn*32 + ni*16)*GPAD + kk*16, GPAD);
            #pragma unroll
            for (int mi = 0; mi < 2; mi++)
                #pragma unroll
                for (int ni = 0; ni < 2; ni++)
                    wmma::mma_sync(acc[mi][ni], a[mi], b[ni], acc[mi][ni]);
        }
        __syncthreads();
    }

    #pragma unroll
    for (int mi = 0; mi < 2; mi++)
        #pragma unroll
        for (int ni = 0; ni < 2; ni++)
            wmma::store_matrix_sync(sC + (wm*32 + mi*16)*68 + wn*32 + ni*16,
                                    acc[mi][ni], 68, wmma::mem_row_major);
    __syncthreads();
    #pragma unroll
    for (int q = 0; q < 8; q++) {
        int j = q * 256 + tid;
        int r = j >> 4, c4 = (j & 15) * 4;
        float4 v = *(float4*)(sC + r*68 + c4);
        float4 b = *(const float4*)(bias + bn + c4);
        v.x += b.x; v.y += b.y; v.z += b.z; v.w += b.w;
        *(uint2*)(C + (size_t)(bm + r) * N + bn + c4) = cvt4h(v);
    }
}

// ---------------- kernel CR: char GRU recurrent (WMMA fp16 Wh, split-fp16 h) -
#define CR_M   64
#define CR_HS  136
#define CR_SC  52
#define CR_OFF_HHI  (G3C*WHS*2)
#define CR_OFF_HLO  (CR_OFF_HHI + CR_M*CR_HS*2)
#define CR_OFF_SCR  (CR_OFF_HLO + CR_M*CR_HS*2)
#define CR_OFF_BH   (CR_OFF_SCR + 16*16*CR_SC*4)
#define CR_SMEM     (CR_OFF_BH + G3C*4)

__global__ __launch_bounds__(512, 1)
void k_charrec(const float* __restrict__ cbh) {
    extern __shared__ char smraw[];
    __half* sWh = (__half*)smraw;
    __half* hHi = (__half*)(smraw + CR_OFF_HHI);
    __half* hLo = (__half*)(smraw + CR_OFF_HLO);
    float*  scr = (float*)(smraw + CR_OFF_SCR);
    float*  sbh = (float*)(smraw + CR_OFF_BH);
    const int tid = threadIdx.x;
    const int warp = tid >> 5, lane = tid & 31;
    const int wm = warp & 1, wj = warp >> 1;
    const int w0 = blockIdx.x * CR_M;
    float* myscr = scr + warp * 16 * CR_SC;

    {
        const uint4* s = (const uint4*)g_Wh16;
        uint4* d = (uint4*)sWh;
        for (int i = tid; i < G3C*WHS*2/16; i += 512) d[i] = s[i];
        uint32_t* hz = (uint32_t*)hHi;
        for (int i = tid; i < 2*CR_M*CR_HS/2; i += 512) hz[i] = 0u;
        if (tid < G3C) sbh[tid] = cbh[tid];
    }
    __syncthreads();

    for (int t = 0; t < LLC; t++) {
        wmma::fragment<wmma::accumulator, 16, 16, 16, float> acc[2][3];
        #pragma unroll
        for (int mi = 0; mi < 2; mi++)
            #pragma unroll
            for (int g = 0; g < 3; g++) wmma::fill_fragment(acc[mi][g], 0.f);

        #pragma unroll
        for (int kk = 0; kk < 8; kk++) {
            wmma::fragment<wmma::matrix_a, 16, 16, 16, __half, wmma::row_major> aH[2], aL[2];
            #pragma unroll
            for (int mi = 0; mi < 2; mi++) {
                wmma::load_matrix_sync(aH[mi], hHi + (wm*32 + mi*16)*CR_HS + kk*16, CR_HS);
                wmma::load_matrix_sync(aL[mi], hLo + (wm*32 + mi*16)*CR_HS + kk*16, CR_HS);
            }
            #pragma unroll
            for (int g = 0; g < 3; g++) {
                wmma::fragment<wmma::matrix_b, 16, 16, 16, __half, wmma::col_major> b;
                wmma::load_matrix_sync(b, sWh + (g*CHID + wj*16)*WHS + kk*16, WHS);
                #pragma unroll
                for (int mi = 0; mi < 2; mi++) {
                    wmma::mma_sync(acc[mi][g], aH[mi], b, acc[mi][g]);
                    wmma::mma_sync(acc[mi][g], aL[mi], b, acc[mi][g]);
                }
            }
        }
        __syncthreads();

        #pragma unroll
        for (int mi = 0; mi < 2; mi++) {
            #pragma unroll
            for (int g = 0; g < 3; g++)
                wmma::store_matrix_sync(myscr + g*16, acc[mi][g], CR_SC, wmma::mem_row_major);
            __syncwarp();
            #pragma unroll
            for (int q = 0; q < 8; q++) {
                int e = lane + 32*q;
                int row = e >> 4, jj = e & 15;
                int m = wm*32 + mi*16 + row;
                int j = wj*16 + jj;
                float pR = myscr[row*CR_SC + jj]      + sbh[j];
                float pZ = myscr[row*CR_SC + 16 + jj] + sbh[CHID + j];
                float pN = myscr[row*CR_SC + 32 + jj] + sbh[2*CHID + j];
                size_t rr = ((size_t)(w0 + m)*LLC + t)*G3C;
                float xr = __half2float(g_cxw16[rr + j]);
                float xz = __half2float(g_cxw16[rr + CHID + j]);
                float xn = __half2float(g_cxw16[rr + 2*CHID + j]);
                float r  = fsig(xr + pR);
                float z  = fsig(xz + pZ);
                float nn = tanhf(xn + r*pN);
                float hp = __half2float(hHi[m*CR_HS + j]) + __half2float(hLo[m*CR_HS + j]);
                float hn = nn + z*(hp - nn);
                __half hh = __float2half(hn);
                hHi[m*CR_HS + j] = hh;
                hLo[m*CR_HS + j] = __float2half(hn - __half2float(hh));
            }
            __syncwarp();
        }
        __syncthreads();
    }

    #pragma unroll
    for (int mi = 0; mi < 2; mi++)
        #pragma unroll
        for (int q = 0; q < 8; q++) {
            int e = lane + 32*q;
            int row = e >> 4, jj = e & 15;
            int m = wm*32 + mi*16 + row;
            int j = wj*16 + jj;
            g_charh[(size_t)(w0 + m)*CHID + j] =
                __half2float(hHi[m*CR_HS + j]) + __half2float(hLo[m*CR_HS + j]);
        }
}

// ---------------- group barrier ----------------
__device__ __forceinline__ void group_barrier(int g) {
    __threadfence();
    __syncthreads();
    if (threadIdx.x == 0) {
        volatile unsigned int* vph = &g_barPh[g];
        unsigned int ph = *vph;
        unsigned int a = atomicAdd(&g_barA[g], 1u);
        if (a == 31u) {
            g_barA[g] = 0u;
            __threadfence();
            *vph = ph + 1u;
        } else {
            while (*vph == ph) { __nanosleep(20); }
        }
        __threadfence();
    }
    __syncthreads();
}

// ---------------- persistent word GRU (WMMA fp16 Wh, split-fp16 h) -----------
#define WG_LDW 520
#define WG_LDH 520
#define WG_SC  52
#define WG_OFF_HH   (48*WG_LDW*2)                  // 49920
#define WG_OFF_HL   (WG_OFF_HH + 32*WG_LDH*2)      // +33280
#define WG_OFF_PRE  (WG_OFF_HL + 32*WG_LDH*2)      // +33280
#define WG_OFF_BH   (WG_OFF_PRE + 32*WG_SC*4)      // +6656
#define WG_SMEM     (WG_OFF_BH + 48*4)             // 123328

__global__ __launch_bounds__(256, 1)
void k_wordgru(const float* __restrict__ gbh) {
    extern __shared__ char smraw[];
    __half* sWh  = (__half*)smraw;                     // [48][520]
    __half* sHh  = (__half*)(smraw + WG_OFF_HH);       // [32][520]
    __half* sHl  = (__half*)(smraw + WG_OFF_HL);
    float*  pre  = (float*)(smraw + WG_OFF_PRE);       // [32][52]
    float*  sbh  = (float*)(smraw + WG_OFF_BH);        // [48]
    const int tid = threadIdx.x;
    const int warp = tid >> 5;
    const int bid = blockIdx.x;
    const int mb = bid >> 5, jb = bid & 31;
    const int b0 = mb * 32, j0 = jb * 16;

    for (int i = tid; i < 48*64; i += 256) {
        int r = i >> 6, c8 = (i & 63) * 8;
        int gate = r >> 4, jj = r & 15;
        size_t src = (size_t)(gate*HID + j0 + jj) * HID + c8;
        *(uint4*)(sWh + r*WG_LDW + c8) = *(const uint4*)(g_gWh16 + src);
    }
    if (tid < 48) {
        int gate = tid >> 4, jj = tid & 15;
        sbh[tid] = gbh[gate*HID + j0 + jj];
    }
    for (int e = tid; e < 32*16; e += 256) {
        int m = e >> 4, jj = e & 15;
        int idx = (b0 + m)*HID + j0 + jj;
        g_h16H[idx] = __float2half(0.f);
        g_h16L[idx] = __float2half(0.f);
    }
    __syncthreads();
    group_barrier(mb);

    const int wmi = warp & 1, wni = warp >> 1;

    for (int s = 0; s < SSQ; s++) {
        {
            const __half* srcH = g_h16H + (s & 1) * (BB*HID);
            const __half* srcL = g_h16L + (s & 1) * (BB*HID);
            for (int i = tid; i < 32*64; i += 256) {
                int r = i >> 6, c8 = (i & 63) * 8;
                size_t src = (size_t)(b0 + r) * HID + c8;
                *(uint4*)(sHh + r*WG_LDH + c8) = *(const uint4*)(srcH + src);
                *(uint4*)(sHl + r*WG_LDH + c8) = *(const uint4*)(srcL + src);
            }
        }
        __syncthreads();

        // prefetch xw (fp16) into registers
        float xr[2], xz[2], xn[2];
        #pragma unroll
        for (int q = 0; q < 2; q++) {
            int e = tid + 256*q;
            int m = e >> 4, jj = e & 15;
            size_t base = ((size_t)(b0 + m)*SSQ + s) * G3H;
            xr[q] = __half2float(g_xw16[base + j0 + jj]);
            xz[q] = __half2float(g_xw16[base + HID + j0 + jj]);
            xn[q] = __half2float(g_xw16[base + 2*HID + j0 + jj]);
        }

        if (warp < 6) {
            wmma::fragment<wmma::accumulator, 16, 16, 16, float> acc[4];
            #pragma unroll
            for (int q = 0; q < 4; q++) wmma::fill_fragment(acc[q], 0.f);
            #pragma unroll
            for (int kk = 0; kk < 8; kk++) {
                #pragma unroll
                for (int kq = 0; kq < 4; kq++) {
                    int k = kq*8 + kk;
                    wmma::fragment<wmma::matrix_a, 16, 16, 16, __half, wmma::row_major> aH, aL;
                    wmma::fragment<wmma::matrix_b, 16, 16, 16, __half, wmma::col_major> bW;
                    wmma::load_matrix_sync(aH, sHh + (wmi*16)*WG_LDH + k*16, WG_LDH);
                    wmma::load_matrix_sync(aL, sHl + (wmi*16)*WG_LDH + k*16, WG_LDH);
                    wmma::load_matrix_sync(bW, sWh + (wni*16)*WG_LDW + k*16, WG_LDW);
                    wmma::mma_sync(acc[kq], aH, bW, acc[kq]);
                    wmma::mma_sync(acc[kq], aL, bW, acc[kq]);
                }
            }
            #pragma unroll
            for (int i = 0; i < acc[0].num_elements; i++)
                acc[0].x[i] += acc[1].x[i] + acc[2].x[i] + acc[3].x[i];
            wmma::store_matrix_sync(pre + (wmi*16)*WG_SC + wni*16, acc[0], WG_SC,
                                    wmma::mem_row_major);
        }
        __syncthreads();

        const int ob = (s + 1) & 1;
        #pragma unroll
        for (int q = 0; q < 2; q++) {
            int e = tid + 256*q;
            int m = e >> 4, jj = e & 15;
            int b = b0 + m, j = j0 + jj;
            float pR = pre[m*WG_SC + jj]      + sbh[jj];
            float pZ = pre[m*WG_SC + 16 + jj] + sbh[16 + jj];
            float pN = pre[m*WG_SC + 32 + jj] + sbh[32 + jj];
            float r  = fsig(xr[q] + pR);
            float z  = fsig(xz[q] + pZ);
            float nn = tanhf(xn[q] + r*pN);
            float hp = __half2float(sHh[m*WG_LDH + j]) + __half2float(sHl[m*WG_LDH + j]);
            float hn = nn + z*(hp - nn);
            g_gruout[((size_t)b*SSQ + s)*HID + j] = hn;
            __half hh = __float2half(hn);
            int idx = ob*(BB*HID) + b*HID + j;
            g_h16H[idx] = hh;
            g_h16L[idx] = __float2half(hn - __half2float(hh));
        }
        if (s == SSQ - 1) break;
        group_barrier(mb);
    }
}

// ---------------- classifier ----------------
__global__ __launch_bounds__(256)
void k_cls(const float* __restrict__ clsW, const float* __restrict__ clsb,
           float* __restrict__ out) {
    const int warp = threadIdx.x >> 5, lane = threadIdx.x & 31;
    const int gw = blockIdx.x * 8 + warp;
    for (int row = gw; row < NW; row += gridDim.x * 8) {
        const float* hrow = g_gruout + (size_t)row * HID;
        float acc[NCLS];
        #pragma unroll
        for (int c = 0; c < NCLS; c++) acc[c] = 0.f;
        for (int k = lane; k < HID; k += 32) {
            float hv = hrow[k];
            #pragma unroll
            for (int c = 0; c < NCLS; c++)
                acc[c] = fmaf(hv, clsW[c*HID + k], acc[c]);
        }
        #pragma unroll
        for (int off = 16; off > 0; off >>= 1) {
            #pragma unroll
            for (int c = 0; c < NCLS; c++)
                acc[c] += __shfl_down_sync(0xffffffffu, acc[c], off);
        }
        if (lane == 0) {
            #pragma unroll
            for (int c = 0; c < NCLS; c++)
                out[(size_t)row*NCLS + c] = acc[c] + clsb[c];
        }
    }
}

// ---------------- launch ----------------
extern "C" void kernel_launch(void* const* d_in, const int* in_sizes, int n_in,
                              void* d_out, int out_size) {
    const int*   x     = (const int*)  d_in[0];
    const int*   xch   = (const int*)  d_in[1];
    const float* embw  = (const float*)d_in[2];
    const float* cembw = (const float*)d_in[3];
    const float* cWi   = (const float*)d_in[4];
    const float* cWh   = (const float*)d_in[5];
    const float* cbi   = (const float*)d_in[6];
    const float* cbh   = (const float*)d_in[7];
    const float* gWi   = (const float*)d_in[8];
    const float* gWh   = (const float*)d_in[9];
    const float* gbi   = (const float*)d_in[10];
    const float* gbh   = (const float*)d_in[11];
    const float* clsW  = (const float*)d_in[12];
    const float* clsb  = (const float*)d_in[13];
    float* out = (float*)d_out;

    void *aC16, *aX16, *bC16, *bX16, *pcxw, *pxw;
    cudaGetSymbolAddress(&aC16, g_Ac16);
    cudaGetSymbolAddress(&aX16, g_Ax16);
    cudaGetSymbolAddress(&bC16, g_Bcx16);
    cudaGetSymbolAddress(&bX16, g_Bxw16);
    cudaGetSymbolAddress(&pcxw, g_cxw16);
    cudaGetSymbolAddress(&pxw, g_xw16);

    cudaFuncSetAttribute(k_charrec, cudaFuncAttributeMaxDynamicSharedMemorySize, CR_SMEM);
    cudaFuncSetAttribute(k_wordgru, cudaFuncAttributeMaxDynamicSharedMemorySize, WG_SMEM);
    cudaFuncSetAttribute(k_gemm,    cudaFuncAttributeMaxDynamicSharedMemorySize, GEMM_SMEM);

    k_prep<<<512, 256>>>(cWh, gWi, cWi, gWh);
    k_gatherA_c<<<NW*LLC/256, 256>>>(xch, cembw);
    dim3 gc(G3C/64, NW*LLC/128);   // (6, 4096)
    k_gemm<<<gc, 256, GEMM_SMEM>>>((const __half*)aC16, (const __half*)bC16,
                                   cbi, (__half*)pcxw, G3C, CEMB);
    k_charrec<<<NW/CR_M, 512, CR_SMEM>>>(cbh);
    k_gatherA_x<<<NW/8, 256>>>(x, embw);
    dim3 gx(G3H/64, NW/128);       // (24, 256)
    k_gemm<<<gx, 256, GEMM_SMEM>>>((const __half*)aX16, (const __half*)bX16,
                                   gbi, (__half*)pxw, G3H, DIM);
    k_wordgru<<<NBLK_W, 256, WG_SMEM>>>(gbh);
    k_cls<<<512, 256>>>(clsW, clsb, out);
}

// round 16
// speedup vs baseline: 3.3039x; 1.0325x over previous
#include <cuda_runtime.h>
#include <cuda_bf16.h>
#include <cuda_fp16.h>
#include <mma.h>
#include <cstdint>
#include <math.h>

using namespace nvcuda;

#define BB    128
#define SSQ   256
#define LLC   16
#define EMB   256
#define HID   512
#define NCLS  20
#define CEMB  64
#define CHID  128
#define NW    (BB*SSQ)        // 32768 words
#define DIM   384             // EMB + CHID
#define G3C   384             // 3*CHID
#define G3H   1536            // 3*HID
#define NBLK_W 128

// ---------------- scratch (__device__ globals, no allocation) ----------------
__device__ __half g_cxw16[(size_t)NW*LLC*G3C];    // char input projections (fp16)
__device__ float g_charh[NW*CHID];                // char GRU final hidden (n = s*B+b)
__device__ __half g_xw16[(size_t)NW*G3H];         // word input projections (fp16)
__device__ float g_gruout[(size_t)NW*HID];
__device__ unsigned int g_barA[4];
__device__ unsigned int g_barPh[4];
// fp16 feed-forward weights (row-major [N][K])
__device__ __half g_Bxw16[G3H*DIM];
__device__ __half g_Bcx16[G3C*CEMB];
// char Wh in fp16, padded [384][136]
#define WHS 136
__device__ __half g_Wh16[G3C*WHS];
// word Wh fp16 image [1536][512]
__device__ __half g_gWh16[G3H*HID];
// word GRU hidden state, split-fp16, double buffered
__device__ __half g_h16H[2*BB*HID], g_h16L[2*BB*HID];
// fp16 gathered A matrices
__device__ __half g_Ac16[(size_t)NW*LLC*CEMB];
__device__ __half g_Ax16[(size_t)NW*DIM];

// ---------------- helpers ----------------
__device__ __forceinline__ uint2 cvt4h(float4 v) {
    union { __half2 h; uint32_t u; } a, b;
    a.h = __floats2half2_rn(v.x, v.y);
    b.h = __floats2half2_rn(v.z, v.w);
    return make_uint2(a.u, b.u);
}
__device__ __forceinline__ float fsig(float x) {
    return __fdividef(1.f, 1.f + __expf(-x));
}
__device__ __forceinline__ float ftanh(float x) {
    return fmaf(2.f, fsig(2.f * x), -1.f);
}

// ---------------- kernel P: weight prep ----------------
__global__ void k_prep(const float* __restrict__ cWh, const float* __restrict__ gWi,
                       const float* __restrict__ cWi, const float* __restrict__ gWh) {
    int stride = gridDim.x * blockDim.x;
    int i0 = blockIdx.x * blockDim.x + threadIdx.x;
    for (int i = i0; i < G3C*WHS; i += stride) {
        int n = i / WHS, k = i % WHS;
        g_Wh16[i] = (k < CHID) ? __float2half(cWh[n*CHID + k]) : __float2half(0.f);
    }
    for (int i = i0; i < G3H*HID; i += stride)
        g_gWh16[i] = __float2half(gWh[i]);
    for (int i = i0; i < G3H*DIM; i += stride)
        g_Bxw16[i] = __float2half(gWi[i]);
    for (int i = i0; i < G3C*CEMB; i += stride)
        g_Bcx16[i] = __float2half(cWi[i]);
}

// ---------------- gather A for char GEMM (fp16) ----------------
__global__ __launch_bounds__(256)
void k_gatherA_c(const int* __restrict__ xc, const float* __restrict__ cembw) {
    const int r = blockIdx.x * 256 + threadIdx.x;
    const int c = xc[r];
    const float4* src = (const float4*)(cembw + (size_t)c * CEMB);
    uint2* dst = (uint2*)(g_Ac16 + (size_t)r * CEMB);
    #pragma unroll
    for (int i = 0; i < 16; i++) dst[i] = cvt4h(src[i]);
}

// ---------------- gather A for word GEMM (fp16) ----------------
__global__ __launch_bounds__(256)
void k_gatherA_x(const int* __restrict__ xtok, const float* __restrict__ embw) {
    const int warp = threadIdx.x >> 5, lane = threadIdx.x & 31;
    const int row = blockIdx.x * 8 + warp;
    const int tok = xtok[row];
    const int nidx = (row & 255) * 128 + (row >> 8);
    uint2* dst = (uint2*)(g_Ax16 + (size_t)row * DIM);
    #pragma unroll
    for (int q = 0; q < 3; q++) {
        int k4 = q * 32 + lane;
        int k = k4 * 4;
        float4 v = (k < EMB)
            ? *(const float4*)(embw + (size_t)tok * EMB + k)
            : *(const float4*)(g_charh + (size_t)nidx * CHID + (k - EMB));
        dst[k4] = cvt4h(v);
    }
}

// ---------------- wmma fp16 GEMM: C16 = A·B^T + bias -------------------------
#define GPAD 72
#define GSM_A  (128*GPAD)                 // halves
#define GSM_B  (64*GPAD)
#define GEMM_SMEM (128*68*4)              // epilogue fp32 dominates: 34816 B

__global__ __launch_bounds__(256)
void k_gemm(const __half* __restrict__ A, const __half* __restrict__ B,
            const float* __restrict__ bias, __half* __restrict__ C,
            int N, int K) {
    extern __shared__ char smraw[];
    __half* sA = (__half*)smraw;
    __half* sB = sA + GSM_A;
    float* sC = (float*)smraw;            // reused in epilogue

    const int tid = threadIdx.x;
    const int warp = tid >> 5;
    const int wm = warp & 3, wn = warp >> 2;
    const int bm = blockIdx.y * 128, bn = blockIdx.x * 64;

    wmma::fragment<wmma::accumulator, 16, 16, 16, float> acc[2][2];
    #pragma unroll
    for (int i = 0; i < 2; i++)
        #pragma unroll
        for (int j = 0; j < 2; j++) wmma::fill_fragment(acc[i][j], 0.f);

    for (int k0 = 0; k0 < K; k0 += 64) {
        #pragma unroll
        for (int q = 0; q < 4; q++) {
            int j = tid * 4 + q;
            int r = j >> 3, c8 = j & 7;
            *(uint4*)(sA + r*GPAD + c8*8) =
                *(const uint4*)(A + (size_t)(bm + r) * K + k0 + c8*8);
        }
        #pragma unroll
        for (int q = 0; q < 2; q++) {
            int j = tid * 2 + q;
            int r = j >> 3, c8 = j & 7;
            *(uint4*)(sB + r*GPAD + c8*8) =
                *(const uint4*)(B + (size_t)(bn + r) * K + k0 + c8*8);
        }
        __syncthreads();

        #pragma unroll
        for (int kk = 0; kk < 4; kk++) {
            wmma::fragment<wmma::matrix_a, 16, 16, 16, __half, wmma::row_major> a[2];
            wmma::fragment<wmma::matrix_b, 16, 16, 16, __half, wmma::col_major> b[2];
            #pragma unroll
            for (int mi = 0; mi < 2; mi++)
                wmma::load_matrix_sync(a[mi], sA + (wm*32 + mi*16)*GPAD + kk*16, GPAD);
            #pragma unroll
            for (int ni = 0; ni < 2; ni++)
                wmma::load_matrix_sync(b[ni], sB + (wn*32 + ni*16)*GPAD + kk*16, GPAD);
            #pragma unroll
            for (int mi = 0; mi < 2; mi++)
                #pragma unroll
                for (int ni = 0; ni < 2; ni++)
                    wmma::mma_sync(acc[mi][ni], a[mi], b[ni], acc[mi][ni]);
        }
        __syncthreads();
    }

    #pragma unroll
    for (int mi = 0; mi < 2; mi++)
        #pragma unroll
        for (int ni = 0; ni < 2; ni++)
            wmma::store_matrix_sync(sC + (wm*32 + mi*16)*68 + wn*32 + ni*16,
                                    acc[mi][ni], 68, wmma::mem_row_major);
    __syncthreads();
    #pragma unroll
    for (int q = 0; q < 8; q++) {
        int j = q * 256 + tid;
        int r = j >> 4, c4 = (j & 15) * 4;
        float4 v = *(float4*)(sC + r*68 + c4);
        float4 b = *(const float4*)(bias + bn + c4);
        v.x += b.x; v.y += b.y; v.z += b.z; v.w += b.w;
        *(uint2*)(C + (size_t)(bm + r) * N + bn + c4) = cvt4h(v);
    }
}

// ---------------- kernel CR: char GRU recurrent (WMMA fp16 Wh, fp16 h) -------
// Single fp16 h image (no lo term): MMA per warp-step halves to 24 ops.
#define CR_M   64
#define CR_HS  136
#define CR_SC  52
#define CR_OFF_HHI  (G3C*WHS*2)                     // 104448
#define CR_OFF_SCR  (CR_OFF_HHI + CR_M*CR_HS*2)     // +17408 = 121856
#define CR_OFF_BH   (CR_OFF_SCR + 16*16*CR_SC*4)    // +53248 = 175104
#define CR_SMEM     (CR_OFF_BH + G3C*4)             // 176640

__global__ __launch_bounds__(512, 1)
void k_charrec(const float* __restrict__ cbh) {
    extern __shared__ char smraw[];
    __half* sWh = (__half*)smraw;
    __half* hHi = (__half*)(smraw + CR_OFF_HHI);
    float*  scr = (float*)(smraw + CR_OFF_SCR);
    float*  sbh = (float*)(smraw + CR_OFF_BH);
    const int tid = threadIdx.x;
    const int warp = tid >> 5, lane = tid & 31;
    const int wm = warp & 1, wj = warp >> 1;
    const int w0 = blockIdx.x * CR_M;
    float* myscr = scr + warp * 16 * CR_SC;

    {
        const uint4* s = (const uint4*)g_Wh16;
        uint4* d = (uint4*)sWh;
        for (int i = tid; i < G3C*WHS*2/16; i += 512) d[i] = s[i];
        uint32_t* hz = (uint32_t*)hHi;
        for (int i = tid; i < CR_M*CR_HS/2; i += 512) hz[i] = 0u;
        if (tid < G3C) sbh[tid] = cbh[tid];
    }
    __syncthreads();

    for (int t = 0; t < LLC; t++) {
        wmma::fragment<wmma::accumulator, 16, 16, 16, float> acc[2][3];
        #pragma unroll
        for (int mi = 0; mi < 2; mi++)
            #pragma unroll
            for (int g = 0; g < 3; g++) wmma::fill_fragment(acc[mi][g], 0.f);

        #pragma unroll
        for (int kk = 0; kk < 8; kk++) {
            wmma::fragment<wmma::matrix_a, 16, 16, 16, __half, wmma::row_major> aH[2];
            #pragma unroll
            for (int mi = 0; mi < 2; mi++)
                wmma::load_matrix_sync(aH[mi], hHi + (wm*32 + mi*16)*CR_HS + kk*16, CR_HS);
            #pragma unroll
            for (int g = 0; g < 3; g++) {
                wmma::fragment<wmma::matrix_b, 16, 16, 16, __half, wmma::col_major> b;
                wmma::load_matrix_sync(b, sWh + (g*CHID + wj*16)*WHS + kk*16, WHS);
                #pragma unroll
                for (int mi = 0; mi < 2; mi++)
                    wmma::mma_sync(acc[mi][g], aH[mi], b, acc[mi][g]);
            }
        }
        __syncthreads();

        #pragma unroll
        for (int mi = 0; mi < 2; mi++) {
            #pragma unroll
            for (int g = 0; g < 3; g++)
                wmma::store_matrix_sync(myscr + g*16, acc[mi][g], CR_SC, wmma::mem_row_major);
            __syncwarp();
            #pragma unroll
            for (int q = 0; q < 8; q++) {
                int e = lane + 32*q;
                int row = e >> 4, jj = e & 15;
                int m = wm*32 + mi*16 + row;
                int j = wj*16 + jj;
                float pR = myscr[row*CR_SC + jj]      + sbh[j];
                float pZ = myscr[row*CR_SC + 16 + jj] + sbh[CHID + j];
                float pN = myscr[row*CR_SC + 32 + jj] + sbh[2*CHID + j];
                size_t rr = ((size_t)(w0 + m)*LLC + t)*G3C;
                float xr = __half2float(g_cxw16[rr + j]);
                float xz = __half2float(g_cxw16[rr + CHID + j]);
                float xn = __half2float(g_cxw16[rr + 2*CHID + j]);
                float r  = fsig(xr + pR);
                float z  = fsig(xz + pZ);
                float nn = ftanh(xn + r*pN);
                float hp = __half2float(hHi[m*CR_HS + j]);
                float hn = nn + z*(hp - nn);
                hHi[m*CR_HS + j] = __float2half(hn);
            }
            __syncwarp();
        }
        __syncthreads();
    }

    #pragma unroll
    for (int mi = 0; mi < 2; mi++)
        #pragma unroll
        for (int q = 0; q < 8; q++) {
            int e = lane + 32*q;
            int row = e >> 4, jj = e & 15;
            int m = wm*32 + mi*16 + row;
            int j = wj*16 + jj;
            g_charh[(size_t)(w0 + m)*CHID + j] = __half2float(hHi[m*CR_HS + j]);
        }
}

// ---------------- group barrier ----------------
__device__ __forceinline__ void group_barrier(int g) {
    __threadfence();
    __syncthreads();
    if (threadIdx.x == 0) {
        volatile unsigned int* vph = &g_barPh[g];
        unsigned int ph = *vph;
        unsigned int a = atomicAdd(&g_barA[g], 1u);
        if (a == 31u) {
            g_barA[g] = 0u;
            __threadfence();
            *vph = ph + 1u;
        } else {
            while (*vph == ph) { __nanosleep(20); }
        }
        __threadfence();
    }
    __syncthreads();
}

// ---------------- persistent word GRU (WMMA fp16 Wh, split-fp16 h) -----------
#define WG_LDW 520
#define WG_LDH 520
#define WG_SC  52
#define WG_OFF_HH   (48*WG_LDW*2)
#define WG_OFF_HL   (WG_OFF_HH + 32*WG_LDH*2)
#define WG_OFF_PRE  (WG_OFF_HL + 32*WG_LDH*2)
#define WG_OFF_BH   (WG_OFF_PRE + 32*WG_SC*4)
#define WG_SMEM     (WG_OFF_BH + 48*4)

__global__ __launch_bounds__(256, 1)
void k_wordgru(const float* __restrict__ gbh) {
    extern __shared__ char smraw[];
    __half* sWh  = (__half*)smraw;
    __half* sHh  = (__half*)(smraw + WG_OFF_HH);
    __half* sHl  = (__half*)(smraw + WG_OFF_HL);
    float*  pre  = (float*)(smraw + WG_OFF_PRE);
    float*  sbh  = (float*)(smraw + WG_OFF_BH);
    const int tid = threadIdx.x;
    const int warp = tid >> 5;
    const int bid = blockIdx.x;
    const int mb = bid >> 5, jb = bid & 31;
    const int b0 = mb * 32, j0 = jb * 16;

    for (int i = tid; i < 48*64; i += 256) {
        int r = i >> 6, c8 = (i & 63) * 8;
        int gate = r >> 4, jj = r & 15;
        size_t src = (size_t)(gate*HID + j0 + jj) * HID + c8;
        *(uint4*)(sWh + r*WG_LDW + c8) = *(const uint4*)(g_gWh16 + src);
    }
    if (tid < 48) {
        int gate = tid >> 4, jj = tid & 15;
        sbh[tid] = gbh[gate*HID + j0 + jj];
    }
    for (int e = tid; e < 32*16; e += 256) {
        int m = e >> 4, jj = e & 15;
        int idx = (b0 + m)*HID + j0 + jj;
        g_h16H[idx] = __float2half(0.f);
        g_h16L[idx] = __float2half(0.f);
    }
    __syncthreads();
    group_barrier(mb);

    const int wmi = warp & 1, wni = warp >> 1;

    for (int s = 0; s < SSQ; s++) {
        {
            const __half* srcH = g_h16H + (s & 1) * (BB*HID);
            const __half* srcL = g_h16L + (s & 1) * (BB*HID);
            for (int i = tid; i < 32*64; i += 256) {
                int r = i >> 6, c8 = (i & 63) * 8;
                size_t src = (size_t)(b0 + r) * HID + c8;
                *(uint4*)(sHh + r*WG_LDH + c8) = *(const uint4*)(srcH + src);
                *(uint4*)(sHl + r*WG_LDH + c8) = *(const uint4*)(srcL + src);
            }
        }
        __syncthreads();

        float xr[2], xz[2], xn[2];
        #pragma unroll
        for (int q = 0; q < 2; q++) {
            int e = tid + 256*q;
            int m = e >> 4, jj = e & 15;
            size_t base = ((size_t)(b0 + m)*SSQ + s) * G3H;
            xr[q] = __half2float(g_xw16[base + j0 + jj]);
            xz[q] = __half2float(g_xw16[base + HID + j0 + jj]);
            xn[q] = __half2float(g_xw16[base + 2*HID + j0 + jj]);
        }

        if (warp < 6) {
            wmma::fragment<wmma::accumulator, 16, 16, 16, float> acc[4];
            #pragma unroll
            for (int q = 0; q < 4; q++) wmma::fill_fragment(acc[q], 0.f);
            #pragma unroll
            for (int kk = 0; kk < 8; kk++) {
                #pragma unroll
                for (int kq = 0; kq < 4; kq++) {
                    int k = kq*8 + kk;
                    wmma::fragment<wmma::matrix_a, 16, 16, 16, __half, wmma::row_major> aH, aL;
                    wmma::fragment<wmma::matrix_b, 16, 16, 16, __half, wmma::col_major> bW;
                    wmma::load_matrix_sync(aH, sHh + (wmi*16)*WG_LDH + k*16, WG_LDH);
                    wmma::load_matrix_sync(aL, sHl + (wmi*16)*WG_LDH + k*16, WG_LDH);
                    wmma::load_matrix_sync(bW, sWh + (wni*16)*WG_LDW + k*16, WG_LDW);
                    wmma::mma_sync(acc[kq], aH, bW, acc[kq]);
                    wmma::mma_sync(acc[kq], aL, bW, acc[kq]);
                }
            }
            #pragma unroll
            for (int i = 0; i < acc[0].num_elements; i++)
                acc[0].x[i] += acc[1].x[i] + acc[2].x[i] + acc[3].x[i];
            wmma::store_matrix_sync(pre + (wmi*16)*WG_SC + wni*16, acc[0], WG_SC,
                                    wmma::mem_row_major);
        }
        __syncthreads();

        const int ob = (s + 1) & 1;
        #pragma unroll
        for (int q = 0; q < 2; q++) {
            int e = tid + 256*q;
            int m = e >> 4, jj = e & 15;
            int b = b0 + m, j = j0 + jj;
            float pR = pre[m*WG_SC + jj]      + sbh[jj];
            float pZ = pre[m*WG_SC + 16 + jj] + sbh[16 + jj];
            float pN = pre[m*WG_SC + 32 + jj] + sbh[32 + jj];
            float r  = fsig(xr[q] + pR);
            float z  = fsig(xz[q] + pZ);
            float nn = ftanh(xn[q] + r*pN);
            float hp = __half2float(sHh[m*WG_LDH + j]) + __half2float(sHl[m*WG_LDH + j]);
            float hn = nn + z*(hp - nn);
            g_gruout[((size_t)b*SSQ + s)*HID + j] = hn;
            __half hh = __float2half(hn);
            int idx = ob*(BB*HID) + b*HID + j;
            g_h16H[idx] = hh;
            g_h16L[idx] = __float2half(hn - __half2float(hh));
        }
        if (s == SSQ - 1) break;
        group_barrier(mb);
    }
}

// ---------------- classifier ----------------
__global__ __launch_bounds__(256)
void k_cls(const float* __restrict__ clsW, const float* __restrict__ clsb,
           float* __restrict__ out) {
    const int warp = threadIdx.x >> 5, lane = threadIdx.x & 31;
    const int gw = blockIdx.x * 8 + warp;
    for (int row = gw; row < NW; row += gridDim.x * 8) {
        const float* hrow = g_gruout + (size_t)row * HID;
        float acc[NCLS];
        #pragma unroll
        for (int c = 0; c < NCLS; c++) acc[c] = 0.f;
        for (int k = lane; k < HID; k += 32) {
            float hv = hrow[k];
            #pragma unroll
            for (int c = 0; c < NCLS; c++)
                acc[c] = fmaf(hv, clsW[c*HID + k], acc[c]);
        }
        #pragma unroll
        for (int off = 16; off > 0; off >>= 1) {
            #pragma unroll
            for (int c = 0; c < NCLS; c++)
                acc[c] += __shfl_down_sync(0xffffffffu, acc[c], off);
        }
        if (lane == 0) {
            #pragma unroll
            for (int c = 0; c < NCLS; c++)
                out[(size_t)row*NCLS + c] = acc[c] + clsb[c];
        }
    }
}

// ---------------- launch ----------------
extern "C" void kernel_launch(void* const* d_in, const int* in_sizes, int n_in,
                              void* d_out, int out_size) {
    const int*   x     = (const int*)  d_in[0];
    const int*   xch   = (const int*)  d_in[1];
    const float* embw  = (const float*)d_in[2];
    const float* cembw = (const float*)d_in[3];
    const float* cWi   = (const float*)d_in[4];
    const float* cWh   = (const float*)d_in[5];
    const float* cbi   = (const float*)d_in[6];
    const float* cbh   = (const float*)d_in[7];
    const float* gWi   = (const float*)d_in[8];
    const float* gWh   = (const float*)d_in[9];
    const float* gbi   = (const float*)d_in[10];
    const float* gbh   = (const float*)d_in[11];
    const float* clsW  = (const float*)d_in[12];
    const float* clsb  = (const float*)d_in[13];
    float* out = (float*)d_out;

    void *aC16, *aX16, *bC16, *bX16, *pcxw, *pxw;
    cudaGetSymbolAddress(&aC16, g_Ac16);
    cudaGetSymbolAddress(&aX16, g_Ax16);
    cudaGetSymbolAddress(&bC16, g_Bcx16);
    cudaGetSymbolAddress(&bX16, g_Bxw16);
    cudaGetSymbolAddress(&pcxw, g_cxw16);
    cudaGetSymbolAddress(&pxw, g_xw16);

    cudaFuncSetAttribute(k_charrec, cudaFuncAttributeMaxDynamicSharedMemorySize, CR_SMEM);
    cudaFuncSetAttribute(k_wordgru, cudaFuncAttributeMaxDynamicSharedMemorySize, WG_SMEM);
    cudaFuncSetAttribute(k_gemm,    cudaFuncAttributeMaxDynamicSharedMemorySize, GEMM_SMEM);

    k_prep<<<512, 256>>>(cWh, gWi, cWi, gWh);
    k_gatherA_c<<<NW*LLC/256, 256>>>(xch, cembw);
    dim3 gc(G3C/64, NW*LLC/128);   // (6, 4096)
    k_gemm<<<gc, 256, GEMM_SMEM>>>((const __half*)aC16, (const __half*)bC16,
                                   cbi, (__half*)pcxw, G3C, CEMB);
    k_charrec<<<NW/CR_M, 512, CR_SMEM>>>(cbh);
    k_gatherA_x<<<NW/8, 256>>>(x, embw);
    dim3 gx(G3H/64, NW/128);       // (24, 256)
    k_gemm<<<gx, 256, GEMM_SMEM>>>((const __half*)aX16, (const __half*)bX16,
                                   gbi, (__half*)pxw, G3H, DIM);
    k_wordgru<<<NBLK_W, 256, WG_SMEM>>>(gbh);
    k_cls<<<512, 256>>>(clsW, clsb, out);
}

// round 17
// speedup vs baseline: 3.6203x; 1.0958x over previous
#include <cuda_runtime.h>
#include <cuda_bf16.h>
#include <cuda_fp16.h>
#include <mma.h>
#include <cstdint>
#include <math.h>

using namespace nvcuda;

#define BB    128
#define SSQ   256
#define LLC   16
#define EMB   256
#define HID   512
#define NCLS  20
#define CEMB  64
#define CHID  128
#define NW    (BB*SSQ)        // 32768 words
#define DIM   384             // EMB + CHID
#define G3C   384             // 3*CHID
#define G3H   1536            // 3*HID
#define NBLK_W 128

// ---------------- scratch (__device__ globals, no allocation) ----------------
__device__ __half g_cxw16[(size_t)NW*LLC*G3C];    // char input projections (fp16)
__device__ float g_charh[NW*CHID];                // char GRU final hidden (n = s*B+b)
__device__ __half g_xw16[(size_t)NW*G3H];         // word input projections (fp16)
__device__ __half g_gruout16[(size_t)NW*HID];     // word GRU outputs (fp16)
__device__ unsigned int g_barA[4];
__device__ unsigned int g_barPh[4];
// fp16 feed-forward weights (row-major [N][K])
__device__ __half g_Bxw16[G3H*DIM];
__device__ __half g_Bcx16[G3C*CEMB];
// char Wh in fp16, padded [384][136]
#define WHS 136
__device__ __half g_Wh16[G3C*WHS];
// word Wh fp16 image [1536][512]
__device__ __half g_gWh16[G3H*HID];
// word GRU hidden state, fp16, double buffered
__device__ __half g_h16H[2*BB*HID];
// fp16 gathered A matrices
__device__ __half g_Ac16[(size_t)NW*LLC*CEMB];
__device__ __half g_Ax16[(size_t)NW*DIM];

// ---------------- helpers ----------------
__device__ __forceinline__ uint2 cvt4h(float4 v) {
    union { __half2 h; uint32_t u; } a, b;
    a.h = __floats2half2_rn(v.x, v.y);
    b.h = __floats2half2_rn(v.z, v.w);
    return make_uint2(a.u, b.u);
}
__device__ __forceinline__ float fsig(float x) {
    return __fdividef(1.f, 1.f + __expf(-x));
}
__device__ __forceinline__ float ftanh(float x) {
    return fmaf(2.f, fsig(2.f * x), -1.f);
}

// ---------------- kernel P: weight prep ----------------
__global__ void k_prep(const float* __restrict__ cWh, const float* __restrict__ gWi,
                       const float* __restrict__ cWi, const float* __restrict__ gWh) {
    int stride = gridDim.x * blockDim.x;
    int i0 = blockIdx.x * blockDim.x + threadIdx.x;
    for (int i = i0; i < G3C*WHS; i += stride) {
        int n = i / WHS, k = i % WHS;
        g_Wh16[i] = (k < CHID) ? __float2half(cWh[n*CHID + k]) : __float2half(0.f);
    }
    for (int i = i0; i < G3H*HID; i += stride)
        g_gWh16[i] = __float2half(gWh[i]);
    for (int i = i0; i < G3H*DIM; i += stride)
        g_Bxw16[i] = __float2half(gWi[i]);
    for (int i = i0; i < G3C*CEMB; i += stride)
        g_Bcx16[i] = __float2half(cWi[i]);
}

// ---------------- gather A for char GEMM (fp16) ----------------
__global__ __launch_bounds__(256)
void k_gatherA_c(const int* __restrict__ xc, const float* __restrict__ cembw) {
    const int r = blockIdx.x * 256 + threadIdx.x;
    const int c = xc[r];
    const float4* src = (const float4*)(cembw + (size_t)c * CEMB);
    uint2* dst = (uint2*)(g_Ac16 + (size_t)r * CEMB);
    #pragma unroll
    for (int i = 0; i < 16; i++) dst[i] = cvt4h(src[i]);
}

// ---------------- gather A for word GEMM (fp16) ----------------
__global__ __launch_bounds__(256)
void k_gatherA_x(const int* __restrict__ xtok, const float* __restrict__ embw) {
    const int warp = threadIdx.x >> 5, lane = threadIdx.x & 31;
    const int row = blockIdx.x * 8 + warp;
    const int tok = xtok[row];
    const int nidx = (row & 255) * 128 + (row >> 8);
    uint2* dst = (uint2*)(g_Ax16 + (size_t)row * DIM);
    #pragma unroll
    for (int q = 0; q < 3; q++) {
        int k4 = q * 32 + lane;
        int k = k4 * 4;
        float4 v = (k < EMB)
            ? *(const float4*)(embw + (size_t)tok * EMB + k)
            : *(const float4*)(g_charh + (size_t)nidx * CHID + (k - EMB));
        dst[k4] = cvt4h(v);
    }
}

// ---------------- wmma fp16 GEMM: C16 = A·B^T + bias -------------------------
#define GPAD 72
#define GSM_A  (128*GPAD)
#define GSM_B  (64*GPAD)
#define GEMM_SMEM (128*68*4)

__global__ __launch_bounds__(256)
void k_gemm(const __half* __restrict__ A, const __half* __restrict__ B,
            const float* __restrict__ bias, __half* __restrict__ C,
            int N, int K) {
    extern __shared__ char smraw[];
    __half* sA = (__half*)smraw;
    __half* sB = sA + GSM_A;
    float* sC = (float*)smraw;

    const int tid = threadIdx.x;
    const int warp = tid >> 5;
    const int wm = warp & 3, wn = warp >> 2;
    const int bm = blockIdx.y * 128, bn = blockIdx.x * 64;

    wmma::fragment<wmma::accumulator, 16, 16, 16, float> acc[2][2];
    #pragma unroll
    for (int i = 0; i < 2; i++)
        #pragma unroll
        for (int j = 0; j < 2; j++) wmma::fill_fragment(acc[i][j], 0.f);

    for (int k0 = 0; k0 < K; k0 += 64) {
        #pragma unroll
        for (int q = 0; q < 4; q++) {
            int j = tid * 4 + q;
            int r = j >> 3, c8 = j & 7;
            *(uint4*)(sA + r*GPAD + c8*8) =
                *(const uint4*)(A + (size_t)(bm + r) * K + k0 + c8*8);
        }
        #pragma unroll
        for (int q = 0; q < 2; q++) {
            int j = tid * 2 + q;
            int r = j >> 3, c8 = j & 7;
            *(uint4*)(sB + r*GPAD + c8*8) =
                *(const uint4*)(B + (size_t)(bn + r) * K + k0 + c8*8);
        }
        __syncthreads();

        #pragma unroll
        for (int kk = 0; kk < 4; kk++) {
            wmma::fragment<wmma::matrix_a, 16, 16, 16, __half, wmma::row_major> a[2];
            wmma::fragment<wmma::matrix_b, 16, 16, 16, __half, wmma::col_major> b[2];
            #pragma unroll
            for (int mi = 0; mi < 2; mi++)
                wmma::load_matrix_sync(a[mi], sA + (wm*32 + mi*16)*GPAD + kk*16, GPAD);
            #pragma unroll
            for (int ni = 0; ni < 2; ni++)
                wmma::load_matrix_sync(b[ni], sB + (wn*32 + ni*16)*GPAD + kk*16, GPAD);
            #pragma unroll
            for (int mi = 0; mi < 2; mi++)
                #pragma unroll
                for (int ni = 0; ni < 2; ni++)
                    wmma::mma_sync(acc[mi][ni], a[mi], b[ni], acc[mi][ni]);
        }
        __syncthreads();
    }

    #pragma unroll
    for (int mi = 0; mi < 2; mi++)
        #pragma unroll
        for (int ni = 0; ni < 2; ni++)
            wmma::store_matrix_sync(sC + (wm*32 + mi*16)*68 + wn*32 + ni*16,
                                    acc[mi][ni], 68, wmma::mem_row_major);
    __syncthreads();
    #pragma unroll
    for (int q = 0; q < 8; q++) {
        int j = q * 256 + tid;
        int r = j >> 4, c4 = (j & 15) * 4;
        float4 v = *(float4*)(sC + r*68 + c4);
        float4 b = *(const float4*)(bias + bn + c4);
        v.x += b.x; v.y += b.y; v.z += b.z; v.w += b.w;
        *(uint2*)(C + (size_t)(bm + r) * N + bn + c4) = cvt4h(v);
    }
}

// ---------------- kernel CR: char GRU recurrent (WMMA fp16 Wh, fp16 h) -------
#define CR_M   64
#define CR_HS  136
#define CR_SC  52
#define CR_OFF_HHI  (G3C*WHS*2)
#define CR_OFF_SCR  (CR_OFF_HHI + CR_M*CR_HS*2)
#define CR_OFF_BH   (CR_OFF_SCR + 16*16*CR_SC*4)
#define CR_SMEM     (CR_OFF_BH + G3C*4)

__global__ __launch_bounds__(512, 1)
void k_charrec(const float* __restrict__ cbh) {
    extern __shared__ char smraw[];
    __half* sWh = (__half*)smraw;
    __half* hHi = (__half*)(smraw + CR_OFF_HHI);
    float*  scr = (float*)(smraw + CR_OFF_SCR);
    float*  sbh = (float*)(smraw + CR_OFF_BH);
    const int tid = threadIdx.x;
    const int warp = tid >> 5, lane = tid & 31;
    const int wm = warp & 1, wj = warp >> 1;
    const int w0 = blockIdx.x * CR_M;
    float* myscr = scr + warp * 16 * CR_SC;

    {
        const uint4* s = (const uint4*)g_Wh16;
        uint4* d = (uint4*)sWh;
        for (int i = tid; i < G3C*WHS*2/16; i += 512) d[i] = s[i];
        uint32_t* hz = (uint32_t*)hHi;
        for (int i = tid; i < CR_M*CR_HS/2; i += 512) hz[i] = 0u;
        if (tid < G3C) sbh[tid] = cbh[tid];
    }
    __syncthreads();

    for (int t = 0; t < LLC; t++) {
        wmma::fragment<wmma::accumulator, 16, 16, 16, float> acc[2][3];
        #pragma unroll
        for (int mi = 0; mi < 2; mi++)
            #pragma unroll
            for (int g = 0; g < 3; g++) wmma::fill_fragment(acc[mi][g], 0.f);

        #pragma unroll
        for (int kk = 0; kk < 8; kk++) {
            wmma::fragment<wmma::matrix_a, 16, 16, 16, __half, wmma::row_major> aH[2];
            #pragma unroll
            for (int mi = 0; mi < 2; mi++)
                wmma::load_matrix_sync(aH[mi], hHi + (wm*32 + mi*16)*CR_HS + kk*16, CR_HS);
            #pragma unroll
            for (int g = 0; g < 3; g++) {
                wmma::fragment<wmma::matrix_b, 16, 16, 16, __half, wmma::col_major> b;
                wmma::load_matrix_sync(b, sWh + (g*CHID + wj*16)*WHS + kk*16, WHS);
                #pragma unroll
                for (int mi = 0; mi < 2; mi++)
                    wmma::mma_sync(acc[mi][g], aH[mi], b, acc[mi][g]);
            }
        }
        __syncthreads();

        #pragma unroll
        for (int mi = 0; mi < 2; mi++) {
            #pragma unroll
            for (int g = 0; g < 3; g++)
                wmma::store_matrix_sync(myscr + g*16, acc[mi][g], CR_SC, wmma::mem_row_major);
            __syncwarp();
            #pragma unroll
            for (int q = 0; q < 8; q++) {
                int e = lane + 32*q;
                int row = e >> 4, jj = e & 15;
                int m = wm*32 + mi*16 + row;
                int j = wj*16 + jj;
                float pR = myscr[row*CR_SC + jj]      + sbh[j];
                float pZ = myscr[row*CR_SC + 16 + jj] + sbh[CHID + j];
                float pN = myscr[row*CR_SC + 32 + jj] + sbh[2*CHID + j];
                size_t rr = ((size_t)(w0 + m)*LLC + t)*G3C;
                float xr = __half2float(g_cxw16[rr + j]);
                float xz = __half2float(g_cxw16[rr + CHID + j]);
                float xn = __half2float(g_cxw16[rr + 2*CHID + j]);
                float r  = fsig(xr + pR);
                float z  = fsig(xz + pZ);
                float nn = ftanh(xn + r*pN);
                float hp = __half2float(hHi[m*CR_HS + j]);
                float hn = nn + z*(hp - nn);
                hHi[m*CR_HS + j] = __float2half(hn);
            }
            __syncwarp();
        }
        __syncthreads();
    }

    #pragma unroll
    for (int mi = 0; mi < 2; mi++)
        #pragma unroll
        for (int q = 0; q < 8; q++) {
            int e = lane + 32*q;
            int row = e >> 4, jj = e & 15;
            int m = wm*32 + mi*16 + row;
            int j = wj*16 + jj;
            g_charh[(size_t)(w0 + m)*CHID + j] = __half2float(hHi[m*CR_HS + j]);
        }
}

// ---------------- group barrier ----------------
__device__ __forceinline__ void group_barrier(int g) {
    __threadfence();
    __syncthreads();
    if (threadIdx.x == 0) {
        volatile unsigned int* vph = &g_barPh[g];
        unsigned int ph = *vph;
        unsigned int a = atomicAdd(&g_barA[g], 1u);
        if (a == 31u) {
            g_barA[g] = 0u;
            __threadfence();
            *vph = ph + 1u;
        } else {
            while (*vph == ph) { __nanosleep(20); }
        }
        __threadfence();
    }
    __syncthreads();
}

// ---------------- persistent word GRU (WMMA fp16 Wh, fp16 h) -----------------
#define WG_LDW 520
#define WG_LDH 520
#define WG_SC  52
#define WG_OFF_HH   (48*WG_LDW*2)                  // 49920
#define WG_OFF_PRE  (WG_OFF_HH + 32*WG_LDH*2)      // +33280
#define WG_OFF_BH   (WG_OFF_PRE + 32*WG_SC*4)      // +6656
#define WG_SMEM     (WG_OFF_BH + 48*4)             // 90048

__global__ __launch_bounds__(256, 1)
void k_wordgru(const float* __restrict__ gbh) {
    extern __shared__ char smraw[];
    __half* sWh  = (__half*)smraw;                     // [48][520]
    __half* sHh  = (__half*)(smraw + WG_OFF_HH);       // [32][520]
    float*  pre  = (float*)(smraw + WG_OFF_PRE);       // [32][52]
    float*  sbh  = (float*)(smraw + WG_OFF_BH);        // [48]
    const int tid = threadIdx.x;
    const int warp = tid >> 5;
    const int bid = blockIdx.x;
    const int mb = bid >> 5, jb = bid & 31;
    const int b0 = mb * 32, j0 = jb * 16;

    for (int i = tid; i < 48*64; i += 256) {
        int r = i >> 6, c8 = (i & 63) * 8;
        int gate = r >> 4, jj = r & 15;
        size_t src = (size_t)(gate*HID + j0 + jj) * HID + c8;
        *(uint4*)(sWh + r*WG_LDW + c8) = *(const uint4*)(g_gWh16 + src);
    }
    if (tid < 48) {
        int gate = tid >> 4, jj = tid & 15;
        sbh[tid] = gbh[gate*HID + j0 + jj];
    }
    for (int e = tid; e < 32*16; e += 256) {
        int m = e >> 4, jj = e & 15;
        g_h16H[(b0 + m)*HID + j0 + jj] = __float2half(0.f);
    }
    __syncthreads();
    group_barrier(mb);

    const int wmi = warp & 1, wni = warp >> 1;

    for (int s = 0; s < SSQ; s++) {
        // stage h (fp16) for this m-group from buffer s&1
        {
            const __half* srcH = g_h16H + (s & 1) * (BB*HID);
            for (int i = tid; i < 32*64; i += 256) {
                int r = i >> 6, c8 = (i & 63) * 8;
                *(uint4*)(sHh + r*WG_LDH + c8) =
                    *(const uint4*)(srcH + (size_t)(b0 + r) * HID + c8);
            }
        }
        __syncthreads();

        // prefetch xw (fp16) into registers
        float xr[2], xz[2], xn[2];
        #pragma unroll
        for (int q = 0; q < 2; q++) {
            int e = tid + 256*q;
            int m = e >> 4, jj = e & 15;
            size_t base = ((size_t)(b0 + m)*SSQ + s) * G3H;
            xr[q] = __half2float(g_xw16[base + j0 + jj]);
            xz[q] = __half2float(g_xw16[base + HID + j0 + jj]);
            xn[q] = __half2float(g_xw16[base + 2*HID + j0 + jj]);
        }

        if (warp < 6) {
            wmma::fragment<wmma::accumulator, 16, 16, 16, float> acc[4];
            #pragma unroll
            for (int q = 0; q < 4; q++) wmma::fill_fragment(acc[q], 0.f);
            #pragma unroll
            for (int kk = 0; kk < 8; kk++) {
                #pragma unroll
                for (int kq = 0; kq < 4; kq++) {
                    int k = kq*8 + kk;
                    wmma::fragment<wmma::matrix_a, 16, 16, 16, __half, wmma::row_major> aH;
                    wmma::fragment<wmma::matrix_b, 16, 16, 16, __half, wmma::col_major> bW;
                    wmma::load_matrix_sync(aH, sHh + (wmi*16)*WG_LDH + k*16, WG_LDH);
                    wmma::load_matrix_sync(bW, sWh + (wni*16)*WG_LDW + k*16, WG_LDW);
                    wmma::mma_sync(acc[kq], aH, bW, acc[kq]);
                }
            }
            #pragma unroll
            for (int i = 0; i < acc[0].num_elements; i++)
                acc[0].x[i] += acc[1].x[i] + acc[2].x[i] + acc[3].x[i];
            wmma::store_matrix_sync(pre + (wmi*16)*WG_SC + wni*16, acc[0], WG_SC,
                                    wmma::mem_row_major);
        }
        __syncthreads();

        const int ob = (s + 1) & 1;
        #pragma unroll
        for (int q = 0; q < 2; q++) {
            int e = tid + 256*q;
            int m = e >> 4, jj = e & 15;
            int b = b0 + m, j = j0 + jj;
            float pR = pre[m*WG_SC + jj]      + sbh[jj];
            float pZ = pre[m*WG_SC + 16 + jj] + sbh[16 + jj];
            float pN = pre[m*WG_SC + 32 + jj] + sbh[32 + jj];
            float r  = fsig(xr[q] + pR);
            float z  = fsig(xz[q] + pZ);
            float nn = ftanh(xn[q] + r*pN);
            float hp = __half2float(sHh[m*WG_LDH + j]);
            float hn = nn + z*(hp - nn);
            __half hh = __float2half(hn);
            g_gruout16[((size_t)b*SSQ + s)*HID + j] = hh;
            g_h16H[ob*(BB*HID) + b*HID + j] = hh;
        }
        if (s == SSQ - 1) break;
        group_barrier(mb);
    }
}

// ---------------- classifier (fp16 input, half2 loads) -----------------------
__global__ __launch_bounds__(256)
void k_cls(const float* __restrict__ clsW, const float* __restrict__ clsb,
           float* __restrict__ out) {
    const int warp = threadIdx.x >> 5, lane = threadIdx.x & 31;
    const int gw = blockIdx.x * 8 + warp;
    for (int row = gw; row < NW; row += gridDim.x * 8) {
        const __half2* hrow = (const __half2*)(g_gruout16 + (size_t)row * HID);
        float acc[NCLS];
        #pragma unroll
        for (int c = 0; c < NCLS; c++) acc[c] = 0.f;
        for (int k2 = lane; k2 < HID/2; k2 += 32) {
            float2 hv = __half22float2(hrow[k2]);
            int k = k2 * 2;
            #pragma unroll
            for (int c = 0; c < NCLS; c++) {
                acc[c] = fmaf(hv.x, clsW[c*HID + k],     acc[c]);
                acc[c] = fmaf(hv.y, clsW[c*HID + k + 1], acc[c]);
            }
        }
        #pragma unroll
        for (int off = 16; off > 0; off >>= 1) {
            #pragma unroll
            for (int c = 0; c < NCLS; c++)
                acc[c] += __shfl_down_sync(0xffffffffu, acc[c], off);
        }
        if (lane == 0) {
            #pragma unroll
            for (int c = 0; c < NCLS; c++)
                out[(size_t)row*NCLS + c] = acc[c] + clsb[c];
        }
    }
}

// ---------------- launch ----------------
extern "C" void kernel_launch(void* const* d_in, const int* in_sizes, int n_in,
                              void* d_out, int out_size) {
    const int*   x     = (const int*)  d_in[0];
    const int*   xch   = (const int*)  d_in[1];
    const float* embw  = (const float*)d_in[2];
    const float* cembw = (const float*)d_in[3];
    const float* cWi   = (const float*)d_in[4];
    const float* cWh   = (const float*)d_in[5];
    const float* cbi   = (const float*)d_in[6];
    const float* cbh   = (const float*)d_in[7];
    const float* gWi   = (const float*)d_in[8];
    const float* gWh   = (const float*)d_in[9];
    const float* gbi   = (const float*)d_in[10];
    const float* gbh   = (const float*)d_in[11];
    const float* clsW  = (const float*)d_in[12];
    const float* clsb  = (const float*)d_in[13];
    float* out = (float*)d_out;

    void *aC16, *aX16, *bC16, *bX16, *pcxw, *pxw;
    cudaGetSymbolAddress(&aC16, g_Ac16);
    cudaGetSymbolAddress(&aX16, g_Ax16);
    cudaGetSymbolAddress(&bC16, g_Bcx16);
    cudaGetSymbolAddress(&bX16, g_Bxw16);
    cudaGetSymbolAddress(&pcxw, g_cxw16);
    cudaGetSymbolAddress(&pxw, g_xw16);

    cudaFuncSetAttribute(k_charrec, cudaFuncAttributeMaxDynamicSharedMemorySize, CR_SMEM);
    cudaFuncSetAttribute(k_wordgru, cudaFuncAttributeMaxDynamicSharedMemorySize, WG_SMEM);
    cudaFuncSetAttribute(k_gemm,    cudaFuncAttributeMaxDynamicSharedMemorySize, GEMM_SMEM);

    k_prep<<<512, 256>>>(cWh, gWi, cWi, gWh);
    k_gatherA_c<<<NW*LLC/256, 256>>>(xch, cembw);
    dim3 gc(G3C/64, NW*LLC/128);   // (6, 4096)
    k_gemm<<<gc, 256, GEMM_SMEM>>>((const __half*)aC16, (const __half*)bC16,
                                   cbi, (__half*)pcxw, G3C, CEMB);
    k_charrec<<<NW/CR_M, 512, CR_SMEM>>>(cbh);
    k_gatherA_x<<<NW/8, 256>>>(x, embw);
    dim3 gx(G3H/64, NW/128);       // (24, 256)
    k_gemm<<<gx, 256, GEMM_SMEM>>>((const __half*)aX16, (const __half*)bX16,
                                   gbi, (__half*)pxw, G3H, DIM);
    k_wordgru<<<NBLK_W, 256, WG_SMEM>>>(gbh);
    k_cls<<<512, 256>>>(clsW, clsb, out);
}